// round 5
// baseline (speedup 1.0000x reference)
#include <cuda_runtime.h>
#include <math.h>

// Problem constants (fixed shapes)
#define NN    299593      // total nodes, complete 8-ary tree, 7 levels
#define HH    128         // D_ENC
#define EMBD  128         // D_EMB
#define NIOU  384         // 3*H
#define DDEC  256
#define NPAR  37449       // nodes at levels 0..5 (all parents) = off[6]

// Scratch (device globals: allocation-free per harness rules)
__device__ float g_h [(size_t)NN  * HH];
__device__ float g_c [(size_t)NN  * HH];
__device__ float g_xf[(size_t)NPAR * HH];
__device__ float g_uh[(size_t)NPAR * NIOU];
__device__ float g_fc[(size_t)NPAR * HH];

#define TS 68   // padded SMEM row stride (floats): conflict-free LDS.128, 16B-aligned

__device__ __forceinline__ float sigf(float v) { return 1.0f / (1.0f + __expf(-v)); }

// acc[i][j] += sum_k As[k][m0+i] * Ws[k][c0+j]   (As, Ws are [128][TS] transposed tiles)
__device__ __forceinline__ void mma64(const float* __restrict__ As,
                                      const float* __restrict__ Ws,
                                      float acc[4][4], int m0, int c0) {
#pragma unroll 8
    for (int k = 0; k < 128; k++) {
        float4 a = *(const float4*)(As + k * TS + m0);
        float4 b = *(const float4*)(Ws + k * TS + c0);
        acc[0][0] += a.x * b.x; acc[0][1] += a.x * b.y; acc[0][2] += a.x * b.z; acc[0][3] += a.x * b.w;
        acc[1][0] += a.y * b.x; acc[1][1] += a.y * b.y; acc[1][2] += a.y * b.z; acc[1][3] += a.y * b.w;
        acc[2][0] += a.z * b.x; acc[2][1] += a.z * b.y; acc[2][2] += a.z * b.z; acc[2][3] += a.z * b.w;
        acc[3][0] += a.w * b.x; acc[3][1] += a.w * b.y; acc[3][2] += a.w * b.z; acc[3][3] += a.w * b.w;
    }
}

// Stage a 128 x 64 weight chunk (row-major source, leading dim ld) into Ws[k][c]
__device__ __forceinline__ void loadW(float* __restrict__ Ws, const float* __restrict__ src,
                                      int ld, int colbase) {
    int t = threadIdx.x;
#pragma unroll
    for (int i = 0; i < 32; i++) {
        int idx = t + 256 * i;
        int k = idx >> 6, c = idx & 63;
        Ws[k * TS + c] = src[k * ld + colbase + c];
    }
}

// ---------------------------------------------------------------------------
// x_f precompute: g_xf[r] = x[r] @ W_f + b_f  for r < NPAR (parents only)
// ---------------------------------------------------------------------------
__global__ void xf_kernel(const float* __restrict__ x, const float* __restrict__ W_f,
                          const float* __restrict__ b_f) {
    extern __shared__ float sm[];
    float* As = sm;
    float* Ws = sm + 128 * TS;
    int t = threadIdx.x;
    int base = blockIdx.x << 6;
    int n_rows = NPAR - base; if (n_rows > 64) n_rows = 64;
    int m0 = (t & 15) * 4, c0 = (t >> 4) * 4;

#pragma unroll
    for (int i = 0; i < 32; i++) {
        int idx = t + 256 * i;
        int m = idx >> 7, k = idx & 127;
        float v = 0.f;
        if (m < n_rows) v = x[(size_t)(base + m) * EMBD + k];
        As[k * TS + m] = v;
    }
    for (int ch = 0; ch < 2; ch++) {
        __syncthreads();
        loadW(Ws, W_f, HH, ch * 64);
        __syncthreads();
        float acc[4][4] = {};
        mma64(As, Ws, acc, m0, c0);
#pragma unroll
        for (int i = 0; i < 4; i++)
#pragma unroll
            for (int j = 0; j < 4; j++) {
                int m = m0 + i, cc = ch * 64 + c0 + j;
                if (m < n_rows)
                    g_xf[(size_t)(base + m) * HH + cc] = acc[i][j] + b_f[cc];
            }
    }
}

// ---------------------------------------------------------------------------
// Fused per-level kernel:
//   iou = x@W_iou + b_iou (+ Uh_sum) -> c,h -> g = h@[U_iou|U_f]
//   f = sigmoid(x_f[parent] + g_f); segmented 8-row sums -> Uh_sum/fc_sum[parent]
// ---------------------------------------------------------------------------
__global__ void level_kernel(const float* __restrict__ x, const float* __restrict__ W_iou,
                             const float* __restrict__ b_iou, const float* __restrict__ U_iou,
                             const float* __restrict__ U_f,
                             int base0, int n_total, int read_sums, int has_parent) {
    extern __shared__ float sm[];
    float* As  = sm;                 // [128][TS] x^T, later h^T
    float* Ws  = sm + 128 * TS;      // [128][TS] weight chunk, reused as g_s[64][TS]
    float* iob = sm + 2 * 128 * TS;  // [64][384] iou buffer; [:,0:128] reused for c

    int t = threadIdx.x;
    int base = base0 + (blockIdx.x << 6);
    int n_rows = n_total - (blockIdx.x << 6); if (n_rows > 64) n_rows = 64;
    int m0 = (t & 15) * 4, c0 = (t >> 4) * 4;

    // load x tile (transposed, zero-padded)
#pragma unroll
    for (int i = 0; i < 32; i++) {
        int idx = t + 256 * i;
        int m = idx >> 7, k = idx & 127;
        float v = 0.f;
        if (m < n_rows) v = x[(size_t)(base + m) * EMBD + k];
        As[k * TS + m] = v;
    }

    // GEMM1: iou = x @ W_iou + b_iou (+ Uh_sum), 6 chunks of 64 cols
    for (int ch = 0; ch < 6; ch++) {
        __syncthreads();
        loadW(Ws, W_iou, NIOU, ch * 64);
        __syncthreads();
        float acc[4][4] = {};
        mma64(As, Ws, acc, m0, c0);
        int n0 = ch * 64;
#pragma unroll
        for (int i = 0; i < 4; i++)
#pragma unroll
            for (int j = 0; j < 4; j++) {
                int m = m0 + i, cc = n0 + c0 + j;
                float v = acc[i][j] + b_iou[cc];
                if (read_sums && m < n_rows) v += g_uh[(size_t)(base + m) * NIOU + cc];
                iob[m * NIOU + cc] = v;
            }
    }
    __syncthreads();

    // Activations: c = sig(i)*tanh(u)+fc_sum, h = sig(o)*tanh(c)
    // write h -> As (transposed), c -> iob[:,0:128]
#pragma unroll
    for (int i = 0; i < 32; i++) {
        int idx = t + 256 * i;
        int m = idx >> 7, j = idx & 127;
        float hn = 0.f, cn = 0.f;
        if (m < n_rows) {
            int r = base + m;
            float iv = iob[m * NIOU + j];
            float ov = iob[m * NIOU + 128 + j];
            float uv = iob[m * NIOU + 256 + j];
            float fcs = read_sums ? g_fc[(size_t)r * HH + j] : 0.f;
            cn = sigf(iv) * tanhf(uv) + fcs;
            hn = sigf(ov) * tanhf(cn);
            g_c[(size_t)r * HH + j] = cn;
            g_h[(size_t)r * HH + j] = hn;
        }
        As[j * TS + m] = hn;       // h^T for GEMM2 (zeros for padded rows)
        iob[m * NIOU + j] = cn;    // c (same (m,j) owner already consumed its i-value)
    }

    if (!has_parent) return;

    // GEMM2: g = h @ [U_iou(384) | U_f(128)], 8 chunks; reduce 8-row sibling groups
    int pbase = (base - 1) >> 3;
    for (int ch = 0; ch < 8; ch++) {
        __syncthreads();   // activation writes / previous g_s reads complete
        if (ch < 6) loadW(Ws, U_iou, NIOU, ch * 64);
        else        loadW(Ws, U_f, HH, (ch - 6) * 64);
        __syncthreads();
        float acc[4][4] = {};
        mma64(As, Ws, acc, m0, c0);
        __syncthreads();   // all Ws reads done -> reuse Ws as g_s
        if (ch < 6) {
#pragma unroll
            for (int i = 0; i < 4; i++)
#pragma unroll
                for (int j = 0; j < 4; j++)
                    Ws[(m0 + i) * TS + c0 + j] = acc[i][j];
        } else {
            int cb = (ch - 6) * 64;
#pragma unroll
            for (int i = 0; i < 4; i++)
#pragma unroll
                for (int j = 0; j < 4; j++) {
                    int m = m0 + i, cc = cb + c0 + j;
                    float v = 0.f;
                    if (m < n_rows) {
                        int r = base + m;
                        int par = (r - 1) >> 3;
                        float f = sigf(acc[i][j] + g_xf[(size_t)par * HH + cc]);
                        v = f * iob[m * NIOU + cc];   // f * c
                    }
                    Ws[(m0 + i) * TS + c0 + j] = v;
                }
        }
        __syncthreads();
        // segmented sum: 8 sibling rows -> 1 parent row, 8 parents x 64 cols
        for (int e = t; e < 512; e += 256) {
            int p = e >> 6, cc = e & 63;
            if (p * 8 < n_rows) {
                float s = 0.f;
#pragma unroll
                for (int q = 0; q < 8; q++) s += Ws[(p * 8 + q) * TS + cc];
                int prow = pbase + p;
                if (ch < 6) g_uh[(size_t)prow * NIOU + ch * 64 + cc] = s;
                else        g_fc[(size_t)prow * HH + (ch - 6) * 64 + cc] = s;
            }
        }
    }
}

// ---------------------------------------------------------------------------
// Output: out = tanh(LayerNorm(h @ W_out + b_out) * gamma + beta)
// ---------------------------------------------------------------------------
__global__ void out_kernel(const float* __restrict__ W_out, const float* __restrict__ b_out,
                           const float* __restrict__ gamma, const float* __restrict__ beta,
                           float* __restrict__ out) {
    extern __shared__ float sm[];
    float* As = sm;
    float* Ws = sm + 128 * TS;
    float* ys = sm + 2 * 128 * TS;   // [64][256]
    int t = threadIdx.x;
    int base = blockIdx.x << 6;
    int n_rows = NN - base; if (n_rows > 64) n_rows = 64;
    int m0 = (t & 15) * 4, c0 = (t >> 4) * 4;

#pragma unroll
    for (int i = 0; i < 32; i++) {
        int idx = t + 256 * i;
        int m = idx >> 7, k = idx & 127;
        float v = 0.f;
        if (m < n_rows) v = g_h[(size_t)(base + m) * HH + k];
        As[k * TS + m] = v;
    }
    for (int ch = 0; ch < 4; ch++) {
        __syncthreads();
        loadW(Ws, W_out, DDEC, ch * 64);
        __syncthreads();
        float acc[4][4] = {};
        mma64(As, Ws, acc, m0, c0);
#pragma unroll
        for (int i = 0; i < 4; i++)
#pragma unroll
            for (int j = 0; j < 4; j++) {
                int cc = ch * 64 + c0 + j;
                ys[(m0 + i) * DDEC + cc] = acc[i][j] + b_out[cc];
            }
    }
    __syncthreads();

    // LayerNorm + tanh: 4 lanes per row
    int m = t >> 2, q = t & 3;
    float s = 0.f, sq = 0.f;
    for (int j = q * 64; j < q * 64 + 64; j++) {
        float v = ys[m * DDEC + j];
        s += v; sq += v * v;
    }
    s  += __shfl_xor_sync(0xffffffffu, s, 1);  s  += __shfl_xor_sync(0xffffffffu, s, 2);
    sq += __shfl_xor_sync(0xffffffffu, sq, 1); sq += __shfl_xor_sync(0xffffffffu, sq, 2);
    float mu  = s * (1.f / 256.f);
    float var = sq * (1.f / 256.f) - mu * mu;
    float rs  = rsqrtf(var + 1e-5f);
    if (m < n_rows) {
        int r = base + m;
        for (int j = q * 64; j < q * 64 + 64; j++) {
            float v = (ys[m * DDEC + j] - mu) * rs * gamma[j] + beta[j];
            out[(size_t)r * DDEC + j] = tanhf(v);
        }
    }
}

// ---------------------------------------------------------------------------
extern "C" void kernel_launch(void* const* d_in, const int* in_sizes, int n_in,
                              void* d_out, int out_size) {
    const float* x = (const float*)d_in[0];
    // d_in[1]=parent, d_in[2]=levels (heap layout makes them redundant)
    // num_levels may appear as a size-1 scalar at index 3
    int wi = 3;
    if (n_in > 3 && in_sizes[3] <= 1) wi = 4;
    const float* W_iou = (const float*)d_in[wi + 0];
    const float* b_iou = (const float*)d_in[wi + 1];
    const float* U_iou = (const float*)d_in[wi + 2];
    const float* W_f   = (const float*)d_in[wi + 3];
    const float* b_f   = (const float*)d_in[wi + 4];
    const float* U_f   = (const float*)d_in[wi + 5];
    const float* W_out = (const float*)d_in[wi + 6];
    const float* b_out = (const float*)d_in[wi + 7];
    const float* gamma = (const float*)d_in[wi + 8];
    const float* beta  = (const float*)d_in[wi + 9];
    float* out = (float*)d_out;

    const int LEVEL_SMEM = (2 * 128 * TS + 64 * NIOU) * (int)sizeof(float);  // 167,936 B
    const int OUT_SMEM   = (2 * 128 * TS + 64 * DDEC) * (int)sizeof(float);  // 135,168 B
    const int XF_SMEM    = (2 * 128 * TS) * (int)sizeof(float);              //  69,632 B
    cudaFuncSetAttribute(level_kernel, cudaFuncAttributeMaxDynamicSharedMemorySize, LEVEL_SMEM);
    cudaFuncSetAttribute(out_kernel,   cudaFuncAttributeMaxDynamicSharedMemorySize, OUT_SMEM);
    cudaFuncSetAttribute(xf_kernel,    cudaFuncAttributeMaxDynamicSharedMemorySize, XF_SMEM);

    xf_kernel<<<(NPAR + 63) / 64, 256, XF_SMEM>>>(x, W_f, b_f);

    const int off[8] = {0, 1, 9, 73, 585, 4681, 37449, 299593};
    for (int l = 6; l >= 0; l--) {
        int base = off[l], n = off[l + 1] - off[l];
        int blocks = (n + 63) / 64;
        level_kernel<<<blocks, 256, LEVEL_SMEM>>>(x, W_iou, b_iou, U_iou, U_f,
                                                  base, n, (l < 6) ? 1 : 0, (l > 0) ? 1 : 0);
    }
    out_kernel<<<(NN + 63) / 64, 256, OUT_SMEM>>>(W_out, b_out, gamma, beta, out);
}

// round 7
// speedup vs baseline: 2.4360x; 2.4360x over previous
#include <cuda_runtime.h>
#include <cuda_bf16.h>
#include <math.h>
#include <stdint.h>

// ---------------------------------------------------------------------------
// Problem constants
// ---------------------------------------------------------------------------
#define NN    299593      // total nodes, complete 8-ary tree, 7 levels
#define HH    128         // D_ENC == D_EMB
#define NIOU  384         // 3*H
#define DDEC  256
#define NPAR  37449       // nodes at levels 0..5 (all parents)

#define CHUNK_BYTES 32768 // one pre-swizzled B chunk: 64 N-rows x 256 Kcat x bf16

// Scratch (device globals: allocation-free per harness rules)
__device__ float g_h [(size_t)NN  * HH];
__device__ float g_xf[(size_t)NPAR * HH];
__device__ float g_uh[(size_t)NPAR * NIOU];
__device__ float g_fc[(size_t)NPAR * HH];

// Pre-swizzled bf16-split weight blobs ([hi | lo] over Kcat=256)
__device__ uint4 g_Wiou_sw[6 * CHUNK_BYTES / 16];
__device__ uint4 g_U_sw   [8 * CHUNK_BYTES / 16];   // [U_iou(384) | U_f(128)] cols
__device__ uint4 g_Wout_sw[4 * CHUNK_BYTES / 16];

// ---------------------------------------------------------------------------
// Helpers
// ---------------------------------------------------------------------------
__device__ __forceinline__ uint32_t smem_to_u32(const void* p) {
    uint32_t a;
    asm("{ .reg .u64 t; cvta.to.shared.u64 t, %1; cvt.u32.u64 %0, t; }" : "=r"(a) : "l"(p));
    return a;
}
__device__ __forceinline__ uint32_t swz(uint32_t o) { return o ^ ((o >> 3) & 0x70); }
// byte offsets in blocked-atom SW128 tiles (atom = 8 rows x 64 bf16 = 1024B)
__device__ __forceinline__ uint32_t offA(int row, int k) {  // 128-row tile: 16 atom-rows
    return swz((uint32_t)(((row >> 3) + (k >> 6) * 16) * 1024 + (row & 7) * 128 + (k & 63) * 2));
}
__device__ __forceinline__ uint32_t offB(int row, int k) {  // 64-row tile: 8 atom-rows
    return swz((uint32_t)(((row >> 3) + (k >> 6) * 8) * 1024 + (row & 7) * 128 + (k & 63) * 2));
}
__device__ __forceinline__ unsigned short f2bfu(float v) {
    __nv_bfloat16 b = __float2bfloat16(v);
    return *reinterpret_cast<unsigned short*>(&b);
}
__device__ __forceinline__ float bfu2f(unsigned short u) {
    __nv_bfloat16 b = *reinterpret_cast<__nv_bfloat16*>(&u);
    return __bfloat162float(b);
}
__device__ __forceinline__ void split2(float a, float b, uint32_t& hi, uint32_t& lo) {
    unsigned short ha = f2bfu(a), hb = f2bfu(b);
    unsigned short la = f2bfu(a - bfu2f(ha)), lb = f2bfu(b - bfu2f(hb));
    hi = (uint32_t)ha | ((uint32_t)hb << 16);
    lo = (uint32_t)la | ((uint32_t)lb << 16);
}
__device__ __forceinline__ float sigf(float v) { return 1.0f / (1.0f + __expf(-v)); }

#define LDSM4(R0, R1, R2, R3, ADDR) \
    asm volatile("ldmatrix.sync.aligned.m8n8.x4.shared.b16 {%0,%1,%2,%3}, [%4];" \
                 : "=r"(R0), "=r"(R1), "=r"(R2), "=r"(R3) : "r"(ADDR))

__device__ __forceinline__ void mma_bf16(float (&d)[4], const uint32_t (&a)[4],
                                         uint32_t b0, uint32_t b1) {
    asm volatile("mma.sync.aligned.m16n8k16.row.col.f32.bf16.bf16.f32 "
                 "{%0,%1,%2,%3}, {%4,%5,%6,%7}, {%8,%9}, {%0,%1,%2,%3};"
                 : "+f"(d[0]), "+f"(d[1]), "+f"(d[2]), "+f"(d[3])
                 : "r"(a[0]), "r"(a[1]), "r"(a[2]), "r"(a[3]), "r"(b0), "r"(b1));
}

__device__ __forceinline__ void zacc(float (&a)[2][4][4]) {
#pragma unroll
    for (int i = 0; i < 2; i++)
#pragma unroll
        for (int j = 0; j < 4; j++)
#pragma unroll
            for (int k = 0; k < 4; k++) a[i][j][k] = 0.f;
}

// One 64-col chunk: C[m32 x n32 per warp] += A_cat[128 x 256] * B_cat[64 x 256]^T
// 3-term bf16 split via kcat offsets: (Ah,Bh),(Al,Bh),(Ah,Bl)
__device__ __forceinline__ void mma_chunk(uint32_t Abase, uint32_t Bbase,
                                          float (&acc)[2][4][4],
                                          int wm, int wn, int lane) {
    int rA = wm * 32 + (lane & 15);
    uint32_t PA = Abase + ((rA >> 3) << 10) + ((rA & 7) << 7);
    uint32_t CA = (rA & 7) << 4;
    int aK = (lane >> 4) << 3;
    int nB = wn * 32 + (((lane >> 4) & 1) << 3) + (lane & 7);
    uint32_t PB = Bbase + ((nB >> 3) << 10) + ((nB & 7) << 7);
    uint32_t CB = (nB & 7) << 4;
    int bK = ((lane >> 3) & 1) << 3;
#pragma unroll 2
    for (int s = 0; s < 24; s++) {
        int t3 = s >> 3;
        int kc = (s & 7) << 4;
        int kA = kc + aK + ((t3 == 1) ? 128 : 0);
        int kB = kc + bK + ((t3 == 2) ? 128 : 0);
        uint32_t aA = PA + ((uint32_t)(kA >> 6) << 14) + ((uint32_t)((kA & 63) << 1) ^ CA);
        uint32_t aB = PB + ((uint32_t)(kB >> 6) << 13) + ((uint32_t)((kB & 63) << 1) ^ CB);
        uint32_t a0[4], a1[4], b[8];
        LDSM4(a0[0], a0[1], a0[2], a0[3], aA);
        LDSM4(a1[0], a1[1], a1[2], a1[3], aA + 2048);
        LDSM4(b[0], b[1], b[2], b[3], aB);
        LDSM4(b[4], b[5], b[6], b[7], aB + 2048);
#pragma unroll
        for (int n = 0; n < 4; n++) {
            mma_bf16(acc[0][n], a0, b[n * 2], b[n * 2 + 1]);
            mma_bf16(acc[1][n], a1, b[n * 2], b[n * 2 + 1]);
        }
    }
}

__device__ __forceinline__ void ld_chunk(uint4 (&P)[8], const uint4* blob, int ch, int t) {
    const uint4* s = blob + (size_t)ch * (CHUNK_BYTES / 16);
#pragma unroll
    for (int i = 0; i < 8; i++) P[i] = s[t + 256 * i];
}
__device__ __forceinline__ void st_chunk(char* dst, const uint4 (&P)[8], int t) {
    uint4* d = (uint4*)dst;
#pragma unroll
    for (int i = 0; i < 8; i++) d[t + 256 * i] = P[i];
}

// ---------------------------------------------------------------------------
// Weight prep: split fp32 src[128][ncols] into bf16 hi/lo, swizzle into blobs
// ---------------------------------------------------------------------------
__global__ void prep_kernel(const float* __restrict__ src, int ncols, int dst_id, int chunkoff) {
    int idx = blockIdx.x * blockDim.x + threadIdx.x;
    if (idx >= 128 * ncols) return;
    int k = idx / ncols, n = idx - k * ncols;
    float v = src[k * ncols + n];
    unsigned short hu = f2bfu(v);
    unsigned short lu = f2bfu(v - bfu2f(hu));
    unsigned char* bb = (dst_id == 0) ? (unsigned char*)g_Wiou_sw
                      : (dst_id == 1) ? (unsigned char*)g_U_sw
                                      : (unsigned char*)g_Wout_sw;
    unsigned char* blob = bb + (size_t)(chunkoff + (n >> 6)) * CHUNK_BYTES;
    int row = n & 63;
    *(unsigned short*)(blob + offB(row, k))       = hu;
    *(unsigned short*)(blob + offB(row, 128 + k)) = lu;
}

// ---------------------------------------------------------------------------
// SMEM layout (dynamic, 1024-aligned):
//   A tile  [0, 65536)      128 x 256 kcat bf16, SW128 blocked
//   B buf0  [65536, 98304)
//   B buf1  [98304, 131072)
//   H tile  [131072, 196608)  (level kernel only)
//   LN part [131072, 133120)  (out kernel only)
// ---------------------------------------------------------------------------
#define SM_B0   65536
#define SM_B1   98304
#define SM_H    131072
#define SM_LVL  196608
#define SM_OUT  133120

// build a 128x[hi|lo] split tile from fp32 rows (src row-major, HH cols)
__device__ __forceinline__ void build_tile(char* Ac, const float* src, size_t base,
                                           int n_rows, int t) {
    int row = t >> 1, kh = (t & 1) << 6;
    bool val = row < n_rows;
    const float4* xr = (const float4*)(src + (base + row) * HH + kh);
#pragma unroll
    for (int gg = 0; gg < 8; gg++) {
        float v[8];
        if (val) {
            float4 a = xr[gg * 2], b = xr[gg * 2 + 1];
            v[0]=a.x; v[1]=a.y; v[2]=a.z; v[3]=a.w; v[4]=b.x; v[5]=b.y; v[6]=b.z; v[7]=b.w;
        } else {
#pragma unroll
            for (int q = 0; q < 8; q++) v[q] = 0.f;
        }
        uint32_t hi[4], lo[4];
#pragma unroll
        for (int q = 0; q < 4; q++) split2(v[2*q], v[2*q+1], hi[q], lo[q]);
        int kc = kh + gg * 8;
        *(uint4*)(Ac + offA(row, kc))       = make_uint4(hi[0], hi[1], hi[2], hi[3]);
        *(uint4*)(Ac + offA(row, 128 + kc)) = make_uint4(lo[0], lo[1], lo[2], lo[3]);
    }
}

// ---------------------------------------------------------------------------
// Fused per-level kernel: one CTA per 128-row tile, 256 threads (8 warps 4x2)
// ---------------------------------------------------------------------------
__global__ __launch_bounds__(256, 1)
void level_mm(const float* __restrict__ x, const float* __restrict__ b_iou,
              int base0, int n_total, int read_sums, int has_parent) {
    extern __shared__ __align__(1024) char smem[];
    uint32_t sb = smem_to_u32(smem);
    int t = threadIdx.x, lane = t & 31, w = t >> 5;
    int wm = w & 3, wn = w >> 2;
    int q = lane & 3, g = lane >> 2;
    int base = base0 + ((int)blockIdx.x << 7);
    int n_rows = n_total - ((int)blockIdx.x << 7); if (n_rows > 128) n_rows = 128;

    build_tile(smem, x, (size_t)base, n_rows, t);

    float accI[2][4][4], accO[2][4][4], accU[2][4][4];
    float creg[2][2][2][4][2];   // [pass][mi][rh][nn][pair] : c values for f-gate
    uint4 P[8];
    ld_chunk(P, g_Wiou_sw, 0, t);
    int pb = 0;

    // ---- GEMM1 + epilogue1, two passes of 64 H-cols ----
#pragma unroll
    for (int p = 0; p < 2; p++) {
        zacc(accI); zacc(accO); zacc(accU);
#pragma unroll
        for (int sub = 0; sub < 3; sub++) {
            st_chunk(smem + (pb ? SM_B1 : SM_B0), P, t);
            int idx = p * 3 + sub;
            if (idx < 5) ld_chunk(P, g_Wiou_sw, ((idx + 1) % 3) * 2 + (idx + 1) / 3, t);
            else         ld_chunk(P, g_U_sw, 0, t);
            __syncthreads();
            uint32_t Bb = sb + (pb ? SM_B1 : SM_B0);
            if (sub == 0)      mma_chunk(sb, Bb, accI, wm, wn, lane);
            else if (sub == 1) mma_chunk(sb, Bb, accO, wm, wn, lane);
            else               mma_chunk(sb, Bb, accU, wm, wn, lane);
            pb ^= 1;
        }
        // epilogue1: gates -> c (regs), h (global + H smem tile)
#pragma unroll
        for (int mi = 0; mi < 2; mi++)
#pragma unroll
        for (int nn = 0; nn < 4; nn++) {
            int cp = p * 64 + wn * 32 + nn * 8 + 2 * q;
            float bi0 = __ldg(b_iou + cp),       bi1 = __ldg(b_iou + cp + 1);
            float bo0 = __ldg(b_iou + 128 + cp), bo1 = __ldg(b_iou + 129 + cp);
            float bu0 = __ldg(b_iou + 256 + cp), bu1 = __ldg(b_iou + 257 + cp);
#pragma unroll
            for (int rh = 0; rh < 2; rh++) {
                int lr = wm * 32 + mi * 16 + g + rh * 8;
                int rg = base + lr;
                bool val = lr < n_rows;
                float2 ui = make_float2(0.f, 0.f), uo = ui, uu = ui, fc = ui;
                if (val && read_sums) {
                    const float* uh = g_uh + (size_t)rg * NIOU + cp;
                    ui = *(const float2*)(uh);
                    uo = *(const float2*)(uh + 128);
                    uu = *(const float2*)(uh + 256);
                    fc = *(const float2*)(g_fc + (size_t)rg * HH + cp);
                }
                float iv0 = accI[mi][nn][rh*2]   + bi0 + ui.x;
                float iv1 = accI[mi][nn][rh*2+1] + bi1 + ui.y;
                float ov0 = accO[mi][nn][rh*2]   + bo0 + uo.x;
                float ov1 = accO[mi][nn][rh*2+1] + bo1 + uo.y;
                float uv0 = accU[mi][nn][rh*2]   + bu0 + uu.x;
                float uv1 = accU[mi][nn][rh*2+1] + bu1 + uu.y;
                float c0 = sigf(iv0) * tanhf(uv0) + fc.x;
                float c1 = sigf(iv1) * tanhf(uv1) + fc.y;
                float h0 = val ? sigf(ov0) * tanhf(c0) : 0.f;
                float h1 = val ? sigf(ov1) * tanhf(c1) : 0.f;
                creg[p][mi][rh][nn][0] = c0;
                creg[p][mi][rh][nn][1] = c1;
                if (val) *(float2*)(g_h + (size_t)rg * HH + cp) = make_float2(h0, h1);
                uint32_t hi, lo; split2(h0, h1, hi, lo);
                *(uint32_t*)(smem + SM_H + offA(lr, cp))       = hi;
                *(uint32_t*)(smem + SM_H + offA(lr, cp + 128)) = lo;
            }
        }
    }

    if (!has_parent) return;

    // ---- GEMM2: g = h @ [U_iou | U_f], chunks 0..5 (Uh) runtime loop ----
    float accG[2][4][4];
    for (int ch = 0; ch < 6; ch++) {
        st_chunk(smem + (pb ? SM_B1 : SM_B0), P, t);
        ld_chunk(P, g_U_sw, ch + 1, t);
        __syncthreads();
        zacc(accG);
        mma_chunk(sb + SM_H, sb + (pb ? SM_B1 : SM_B0), accG, wm, wn, lane);
        pb ^= 1;
#pragma unroll
        for (int mi = 0; mi < 2; mi++)
#pragma unroll
        for (int nn = 0; nn < 4; nn++) {
            int cb = ch * 64 + wn * 32 + nn * 8 + 2 * q;
            float v[4];
#pragma unroll
            for (int r = 0; r < 4; r++) {
                float s = accG[mi][nn][r];
                s += __shfl_xor_sync(0xffffffffu, s, 4);
                s += __shfl_xor_sync(0xffffffffu, s, 8);
                s += __shfl_xor_sync(0xffffffffu, s, 16);
                v[r] = s;
            }
            if (lane < 4) {
#pragma unroll
                for (int rh = 0; rh < 2; rh++) {
                    int lr0 = wm * 32 + mi * 16 + rh * 8;
                    if (lr0 < n_rows) {
                        int pr = (base + lr0 - 1) >> 3;
                        *(float2*)(g_uh + (size_t)pr * NIOU + cb) =
                            make_float2(v[rh*2], v[rh*2+1]);
                    }
                }
            }
        }
    }
    // ---- chunks 6,7: f = sigmoid(g + xf[par]); fc = f*c; reduce -> parents ----
#pragma unroll
    for (int cf = 0; cf < 2; cf++) {
        st_chunk(smem + (pb ? SM_B1 : SM_B0), P, t);
        if (cf == 0) ld_chunk(P, g_U_sw, 7, t);
        __syncthreads();
        zacc(accG);
        mma_chunk(sb + SM_H, sb + (pb ? SM_B1 : SM_B0), accG, wm, wn, lane);
        pb ^= 1;
#pragma unroll
        for (int mi = 0; mi < 2; mi++)
#pragma unroll
        for (int nn = 0; nn < 4; nn++) {
            int cfl = cf * 64 + wn * 32 + nn * 8 + 2 * q;
            float v[4];
#pragma unroll
            for (int rh = 0; rh < 2; rh++) {
                int lr = wm * 32 + mi * 16 + g + rh * 8;
                int rg = base + lr;
                if (lr < n_rows) {
                    int pr = (rg - 1) >> 3;
                    float2 xf2 = *(const float2*)(g_xf + (size_t)pr * HH + cfl);
                    v[rh*2]   = sigf(accG[mi][nn][rh*2]   + xf2.x) * creg[cf][mi][rh][nn][0];
                    v[rh*2+1] = sigf(accG[mi][nn][rh*2+1] + xf2.y) * creg[cf][mi][rh][nn][1];
                } else { v[rh*2] = 0.f; v[rh*2+1] = 0.f; }
            }
#pragma unroll
            for (int r = 0; r < 4; r++) {
                float s = v[r];
                s += __shfl_xor_sync(0xffffffffu, s, 4);
                s += __shfl_xor_sync(0xffffffffu, s, 8);
                s += __shfl_xor_sync(0xffffffffu, s, 16);
                v[r] = s;
            }
            if (lane < 4) {
#pragma unroll
                for (int rh = 0; rh < 2; rh++) {
                    int lr0 = wm * 32 + mi * 16 + rh * 8;
                    if (lr0 < n_rows) {
                        int pr = (base + lr0 - 1) >> 3;
                        *(float2*)(g_fc + (size_t)pr * HH + cfl) =
                            make_float2(v[rh*2], v[rh*2+1]);
                    }
                }
            }
        }
    }
}

// ---------------------------------------------------------------------------
// Output kernel: out = tanh(LN(h @ W_out + b_out) * gamma + beta)
// ---------------------------------------------------------------------------
__global__ __launch_bounds__(256, 1)
void out_mm(const float* __restrict__ b_out, const float* __restrict__ gamma,
            const float* __restrict__ beta, float* __restrict__ out) {
    extern __shared__ __align__(1024) char smem[];
    uint32_t sb = smem_to_u32(smem);
    int t = threadIdx.x, lane = t & 31, w = t >> 5;
    int wm = w & 3, wn = w >> 2;
    int q = lane & 3, g = lane >> 2;
    int base = (int)blockIdx.x << 7;
    int n_rows = NN - base; if (n_rows > 128) n_rows = 128;

    build_tile(smem, g_h, (size_t)base, n_rows, t);

    float acc4[4][2][4][4];
#pragma unroll
    for (int ch = 0; ch < 4; ch++) zacc(acc4[ch]);
    uint4 P[8];
    ld_chunk(P, g_Wout_sw, 0, t);
    int pb = 0;
#pragma unroll
    for (int ch = 0; ch < 4; ch++) {
        st_chunk(smem + (pb ? SM_B1 : SM_B0), P, t);
        if (ch < 3) ld_chunk(P, g_Wout_sw, ch + 1, t);
        __syncthreads();
        mma_chunk(sb, sb + (pb ? SM_B1 : SM_B0), acc4[ch], wm, wn, lane);
        pb ^= 1;
    }

    // bias in place + per-row partial sums
    float s[2][2] = {{0.f,0.f},{0.f,0.f}}, sq[2][2] = {{0.f,0.f},{0.f,0.f}};
#pragma unroll
    for (int ch = 0; ch < 4; ch++)
#pragma unroll
    for (int nn = 0; nn < 4; nn++) {
        int cb = ch * 64 + wn * 32 + nn * 8 + 2 * q;
        float b0 = __ldg(b_out + cb), b1 = __ldg(b_out + cb + 1);
#pragma unroll
        for (int mi = 0; mi < 2; mi++)
#pragma unroll
        for (int rh = 0; rh < 2; rh++) {
            float y0 = (acc4[ch][mi][nn][rh*2]   += b0);
            float y1 = (acc4[ch][mi][nn][rh*2+1] += b1);
            s[mi][rh]  += y0 + y1;
            sq[mi][rh] += y0 * y0 + y1 * y1;
        }
    }
#pragma unroll
    for (int mi = 0; mi < 2; mi++)
#pragma unroll
    for (int rh = 0; rh < 2; rh++) {
        s[mi][rh]  += __shfl_xor_sync(0xffffffffu, s[mi][rh], 1);
        s[mi][rh]  += __shfl_xor_sync(0xffffffffu, s[mi][rh], 2);
        sq[mi][rh] += __shfl_xor_sync(0xffffffffu, sq[mi][rh], 1);
        sq[mi][rh] += __shfl_xor_sync(0xffffffffu, sq[mi][rh], 2);
    }
    float2* part = (float2*)(smem + SM_H);   // [128][2]
    if (q == 0) {
#pragma unroll
        for (int mi = 0; mi < 2; mi++)
#pragma unroll
        for (int rh = 0; rh < 2; rh++) {
            int lr = wm * 32 + mi * 16 + g + rh * 8;
            part[lr * 2 + wn] = make_float2(s[mi][rh], sq[mi][rh]);
        }
    }
    __syncthreads();
    float mu[2][2], rs[2][2];
#pragma unroll
    for (int mi = 0; mi < 2; mi++)
#pragma unroll
    for (int rh = 0; rh < 2; rh++) {
        int lr = wm * 32 + mi * 16 + g + rh * 8;
        float2 a = part[lr * 2], b = part[lr * 2 + 1];
        float m = (a.x + b.x) * (1.f / 256.f);
        float var = (a.y + b.y) * (1.f / 256.f) - m * m;
        mu[mi][rh] = m;
        rs[mi][rh] = rsqrtf(var + 1e-5f);
    }
#pragma unroll
    for (int ch = 0; ch < 4; ch++)
#pragma unroll
    for (int nn = 0; nn < 4; nn++) {
        int cb = ch * 64 + wn * 32 + nn * 8 + 2 * q;
        float g0 = __ldg(gamma + cb), g1 = __ldg(gamma + cb + 1);
        float e0 = __ldg(beta + cb),  e1 = __ldg(beta + cb + 1);
#pragma unroll
        for (int mi = 0; mi < 2; mi++)
#pragma unroll
        for (int rh = 0; rh < 2; rh++) {
            int lr = wm * 32 + mi * 16 + g + rh * 8;
            if (lr < n_rows) {
                float y0 = (acc4[ch][mi][nn][rh*2]   - mu[mi][rh]) * rs[mi][rh] * g0 + e0;
                float y1 = (acc4[ch][mi][nn][rh*2+1] - mu[mi][rh]) * rs[mi][rh] * g1 + e1;
                *(float2*)(out + (size_t)(base + lr) * DDEC + cb) =
                    make_float2(tanhf(y0), tanhf(y1));
            }
        }
    }
}

// ---------------------------------------------------------------------------
// x_f precompute (FFMA, small): g_xf[r] = x[r] @ W_f + b_f  for r < NPAR
// ---------------------------------------------------------------------------
#define TS 68
__global__ void xf_kernel(const float* __restrict__ x, const float* __restrict__ W_f,
                          const float* __restrict__ b_f) {
    extern __shared__ float sm[];
    float* As = sm;
    float* Ws = sm + 128 * TS;
    int t = threadIdx.x;
    int base = blockIdx.x << 6;
    int n_rows = NPAR - base; if (n_rows > 64) n_rows = 64;
    int m0 = (t & 15) * 4, c0 = (t >> 4) * 4;

#pragma unroll
    for (int i = 0; i < 32; i++) {
        int idx = t + 256 * i;
        int m = idx >> 7, k = idx & 127;
        float v = 0.f;
        if (m < n_rows) v = x[(size_t)(base + m) * HH + k];
        As[k * TS + m] = v;
    }
    for (int ch = 0; ch < 2; ch++) {
        __syncthreads();
#pragma unroll
        for (int i = 0; i < 32; i++) {
            int idx = t + 256 * i;
            int k = idx >> 6, c = idx & 63;
            Ws[k * TS + c] = W_f[k * HH + ch * 64 + c];
        }
        __syncthreads();
        float acc[4][4] = {};
#pragma unroll 8
        for (int k = 0; k < 128; k++) {
            float4 a = *(const float4*)(As + k * TS + m0);
            float4 b = *(const float4*)(Ws + k * TS + c0);
            acc[0][0] += a.x*b.x; acc[0][1] += a.x*b.y; acc[0][2] += a.x*b.z; acc[0][3] += a.x*b.w;
            acc[1][0] += a.y*b.x; acc[1][1] += a.y*b.y; acc[1][2] += a.y*b.z; acc[1][3] += a.y*b.w;
            acc[2][0] += a.z*b.x; acc[2][1] += a.z*b.y; acc[2][2] += a.z*b.z; acc[2][3] += a.z*b.w;
            acc[3][0] += a.w*b.x; acc[3][1] += a.w*b.y; acc[3][2] += a.w*b.z; acc[3][3] += a.w*b.w;
        }
#pragma unroll
        for (int i = 0; i < 4; i++)
#pragma unroll
            for (int j = 0; j < 4; j++) {
                int m = m0 + i, cc = ch * 64 + c0 + j;
                if (m < n_rows)
                    g_xf[(size_t)(base + m) * HH + cc] = acc[i][j] + b_f[cc];
            }
    }
}

// ---------------------------------------------------------------------------
extern "C" void kernel_launch(void* const* d_in, const int* in_sizes, int n_in,
                              void* d_out, int out_size) {
    const float* x = (const float*)d_in[0];
    int wi = 3;
    if (n_in > 3 && in_sizes[3] <= 1) wi = 4;
    const float* W_iou = (const float*)d_in[wi + 0];
    const float* b_iou = (const float*)d_in[wi + 1];
    const float* U_iou = (const float*)d_in[wi + 2];
    const float* W_f   = (const float*)d_in[wi + 3];
    const float* b_f   = (const float*)d_in[wi + 4];
    const float* U_f   = (const float*)d_in[wi + 5];
    const float* W_out = (const float*)d_in[wi + 6];
    const float* b_out = (const float*)d_in[wi + 7];
    const float* gamma = (const float*)d_in[wi + 8];
    const float* beta  = (const float*)d_in[wi + 9];
    float* out = (float*)d_out;

    cudaFuncSetAttribute(level_mm, cudaFuncAttributeMaxDynamicSharedMemorySize, SM_LVL);
    cudaFuncSetAttribute(out_mm,   cudaFuncAttributeMaxDynamicSharedMemorySize, SM_OUT);
    cudaFuncSetAttribute(xf_kernel, cudaFuncAttributeMaxDynamicSharedMemorySize,
                         (2 * 128 * TS) * (int)sizeof(float));

    // weight prep (split + swizzle)
    prep_kernel<<<192, 256>>>(W_iou, 384, 0, 0);
    prep_kernel<<<192, 256>>>(U_iou, 384, 1, 0);
    prep_kernel<<< 64, 256>>>(U_f,   128, 1, 6);
    prep_kernel<<<128, 256>>>(W_out, 256, 2, 0);

    xf_kernel<<<(NPAR + 63) / 64, 256, (2 * 128 * TS) * sizeof(float)>>>(x, W_f, b_f);

    const int off[8] = {0, 1, 9, 73, 585, 4681, 37449, 299593};
    for (int l = 6; l >= 0; l--) {
        int base = off[l], n = off[l + 1] - off[l];
        int blocks = (n + 127) / 128;
        level_mm<<<blocks, 256, SM_LVL>>>(x, b_iou, base, n,
                                          (l < 6) ? 1 : 0, (l > 0) ? 1 : 0);
    }
    out_mm<<<(NN + 127) / 128, 256, SM_OUT>>>(b_out, gamma, beta, out);
}

// round 8
// speedup vs baseline: 2.5519x; 1.0476x over previous
#include <cuda_runtime.h>
#include <cuda_bf16.h>
#include <math.h>
#include <stdint.h>

// ---------------------------------------------------------------------------
// Problem constants
// ---------------------------------------------------------------------------
#define NN    299593      // total nodes, complete 8-ary tree, 7 levels
#define HH    128         // D_ENC == D_EMB
#define NIOU  384         // 3*H
#define DDEC  256
#define NPAR  37449       // nodes at levels 0..5 (all parents)

#define CHUNK_BYTES 16384 // one pre-swizzled B chunk: 32 N-rows x 256 Kcat x bf16

// Scratch (device globals: allocation-free per harness rules)
__device__ float g_h [(size_t)NN  * HH];
__device__ float g_c [(size_t)NN  * HH];
__device__ float g_xf[(size_t)NPAR * HH];
__device__ float g_uh[(size_t)NPAR * NIOU];
__device__ float g_fc[(size_t)NPAR * HH];

// Pre-swizzled bf16-split weight blobs ([hi | lo] over Kcat=256), 32-row chunks
__device__ uint4 g_Wiou_sw[12 * CHUNK_BYTES / 16];
__device__ uint4 g_U_sw   [16 * CHUNK_BYTES / 16];  // [U_iou(384) | U_f(128)] cols
__device__ uint4 g_Wout_sw[ 8 * CHUNK_BYTES / 16];

// ---------------------------------------------------------------------------
// Helpers
// ---------------------------------------------------------------------------
__device__ __forceinline__ uint32_t smem_to_u32(const void* p) {
    uint32_t a;
    asm("{ .reg .u64 t; cvta.to.shared.u64 t, %1; cvt.u32.u64 %0, t; }" : "=r"(a) : "l"(p));
    return a;
}
__device__ __forceinline__ uint32_t swz(uint32_t o) { return o ^ ((o >> 3) & 0x70); }
// byte offsets in blocked-atom SW128 tiles (atom = 8 rows x 64 bf16 = 1024B)
__device__ __forceinline__ uint32_t offA(int row, int k) {  // 128-row tile: 16 atoms/kblk
    return swz((uint32_t)(((row >> 3) + (k >> 6) * 16) * 1024 + (row & 7) * 128 + (k & 63) * 2));
}
__device__ __forceinline__ uint32_t offB32(int row, int k) { // 32-row tile: 4 atoms/kblk
    return swz((uint32_t)(((row >> 3) + (k >> 6) * 4) * 1024 + (row & 7) * 128 + (k & 63) * 2));
}
__device__ __forceinline__ unsigned short f2bfu(float v) {
    __nv_bfloat16 b = __float2bfloat16(v);
    return *reinterpret_cast<unsigned short*>(&b);
}
__device__ __forceinline__ float bfu2f(unsigned short u) {
    __nv_bfloat16 b = *reinterpret_cast<__nv_bfloat16*>(&u);
    return __bfloat162float(b);
}
__device__ __forceinline__ void split2(float a, float b, uint32_t& hi, uint32_t& lo) {
    unsigned short ha = f2bfu(a), hb = f2bfu(b);
    unsigned short la = f2bfu(a - bfu2f(ha)), lb = f2bfu(b - bfu2f(hb));
    hi = (uint32_t)ha | ((uint32_t)hb << 16);
    lo = (uint32_t)la | ((uint32_t)lb << 16);
}
__device__ __forceinline__ float sigf(float v) {
    return __fdividef(1.0f, 1.0f + __expf(-v));
}
__device__ __forceinline__ float tanh_fast(float x) {
    float t = __expf(2.0f * x);          // saturates: inf/0 handled correctly
    return 1.0f - __fdividef(2.0f, t + 1.0f);
}

#define LDSM4(R0, R1, R2, R3, ADDR) \
    asm volatile("ldmatrix.sync.aligned.m8n8.x4.shared.b16 {%0,%1,%2,%3}, [%4];" \
                 : "=r"(R0), "=r"(R1), "=r"(R2), "=r"(R3) : "r"(ADDR))

__device__ __forceinline__ void mma_bf16(float (&d)[4], const uint32_t (&a)[4],
                                         uint32_t b0, uint32_t b1) {
    asm volatile("mma.sync.aligned.m16n8k16.row.col.f32.bf16.bf16.f32 "
                 "{%0,%1,%2,%3}, {%4,%5,%6,%7}, {%8,%9}, {%0,%1,%2,%3};"
                 : "+f"(d[0]), "+f"(d[1]), "+f"(d[2]), "+f"(d[3])
                 : "r"(a[0]), "r"(a[1]), "r"(a[2]), "r"(a[3]), "r"(b0), "r"(b1));
}

__device__ __forceinline__ void zacc(float (&a)[2][2][4]) {
#pragma unroll
    for (int i = 0; i < 2; i++)
#pragma unroll
        for (int j = 0; j < 2; j++)
#pragma unroll
            for (int k = 0; k < 4; k++) a[i][j][k] = 0.f;
}

// One 32-col chunk: per-warp C[m32 x n16] += A_cat[128x256] * B_cat[32x256]^T
// 3-term bf16 split via kcat offsets: (Ah,Bh),(Al,Bh),(Ah,Bl)
__device__ __forceinline__ void mma_chunk32(uint32_t Abase, uint32_t Bbase,
                                            float (&acc)[2][2][4],
                                            int wm, int wn, int lane) {
    int rA = wm * 32 + (lane & 15);
    uint32_t PA = Abase + ((rA >> 3) << 10) + ((rA & 7) << 7);
    uint32_t CA = (rA & 7) << 4;
    int aK = (lane >> 4) << 3;
    int nB = wn * 16 + (((lane >> 4) & 1) << 3) + (lane & 7);
    uint32_t PB = Bbase + ((nB >> 3) << 10) + ((nB & 7) << 7);
    uint32_t CB = (nB & 7) << 4;
    int bK = ((lane >> 3) & 1) << 3;
#pragma unroll 4
    for (int s = 0; s < 24; s++) {
        int t3 = s >> 3;
        int kc = (s & 7) << 4;
        int kA = kc + aK + ((t3 == 1) ? 128 : 0);
        int kB = kc + bK + ((t3 == 2) ? 128 : 0);
        uint32_t aA = PA + ((uint32_t)(kA >> 6) << 14) + ((uint32_t)((kA & 63) << 1) ^ CA);
        uint32_t aB = PB + ((uint32_t)(kB >> 6) << 12) + ((uint32_t)((kB & 63) << 1) ^ CB);
        uint32_t a0[4], a1[4], b[4];
        LDSM4(a0[0], a0[1], a0[2], a0[3], aA);
        LDSM4(a1[0], a1[1], a1[2], a1[3], aA + 2048);
        LDSM4(b[0], b[1], b[2], b[3], aB);
        mma_bf16(acc[0][0], a0, b[0], b[1]);
        mma_bf16(acc[1][0], a1, b[0], b[1]);
        mma_bf16(acc[0][1], a0, b[2], b[3]);
        mma_bf16(acc[1][1], a1, b[2], b[3]);
    }
}

__device__ __forceinline__ void ld_chunk(uint4 (&P)[4], const uint4* blob, int ch, int t) {
    const uint4* s = blob + (size_t)ch * (CHUNK_BYTES / 16);
#pragma unroll
    for (int i = 0; i < 4; i++) P[i] = s[t + 256 * i];
}
__device__ __forceinline__ void st_chunk(char* dst, const uint4 (&P)[4], int t) {
    uint4* d = (uint4*)dst;
#pragma unroll
    for (int i = 0; i < 4; i++) d[t + 256 * i] = P[i];
}

// ---------------------------------------------------------------------------
// Weight prep: split fp32 src[128][ncols] into bf16 hi/lo, swizzle into blobs
// ---------------------------------------------------------------------------
__global__ void prep_kernel(const float* __restrict__ src, int ncols, int dst_id, int chunkoff) {
    int idx = blockIdx.x * blockDim.x + threadIdx.x;
    if (idx >= 128 * ncols) return;
    int k = idx / ncols, n = idx - k * ncols;
    float v = src[k * ncols + n];
    unsigned short hu = f2bfu(v);
    unsigned short lu = f2bfu(v - bfu2f(hu));
    unsigned char* bb = (dst_id == 0) ? (unsigned char*)g_Wiou_sw
                      : (dst_id == 1) ? (unsigned char*)g_U_sw
                                      : (unsigned char*)g_Wout_sw;
    unsigned char* blob = bb + (size_t)(chunkoff + (n >> 5)) * CHUNK_BYTES;
    int row = n & 31;
    *(unsigned short*)(blob + offB32(row, k))       = hu;
    *(unsigned short*)(blob + offB32(row, 128 + k)) = lu;
}

// ---------------------------------------------------------------------------
// SMEM layout (dynamic, 1024-aligned):
//   A tile [0, 65536)   128 x 256 kcat bf16, SW128 blocked (x, later h)
//   B buf  [65536, 81920)  single-buffered 32-col weight chunk
//   LN part[81920, 83968)  out kernel only
// ---------------------------------------------------------------------------
#define SM_B    65536
#define SM_LVL  81920
#define SM_OUT  83968

// build a 128x[hi|lo] split tile from fp32 rows (src row-major, HH cols)
__device__ __forceinline__ void build_tile(char* Ac, const float* src, size_t base,
                                           int n_rows, int t) {
    int row = t >> 1, kh = (t & 1) << 6;
    bool val = row < n_rows;
    const float4* xr = (const float4*)(src + (base + row) * HH + kh);
#pragma unroll
    for (int gg = 0; gg < 8; gg++) {
        float v[8];
        if (val) {
            float4 a = xr[gg * 2], b = xr[gg * 2 + 1];
            v[0]=a.x; v[1]=a.y; v[2]=a.z; v[3]=a.w; v[4]=b.x; v[5]=b.y; v[6]=b.z; v[7]=b.w;
        } else {
#pragma unroll
            for (int q = 0; q < 8; q++) v[q] = 0.f;
        }
        uint32_t hi[4], lo[4];
#pragma unroll
        for (int q = 0; q < 4; q++) split2(v[2*q], v[2*q+1], hi[q], lo[q]);
        int kc = kh + gg * 8;
        *(uint4*)(Ac + offA(row, kc))       = make_uint4(hi[0], hi[1], hi[2], hi[3]);
        *(uint4*)(Ac + offA(row, 128 + kc)) = make_uint4(lo[0], lo[1], lo[2], lo[3]);
    }
}

// ---------------------------------------------------------------------------
// Fused per-level kernel: one CTA per 128-row tile, 256 threads, 2 CTAs/SM
// ---------------------------------------------------------------------------
__global__ __launch_bounds__(256, 2)
void level_mm(const float* __restrict__ x, const float* __restrict__ b_iou,
              int base0, int n_total, int read_sums, int has_parent) {
    extern __shared__ __align__(1024) char smem[];
    uint32_t sb = smem_to_u32(smem);
    uint32_t sbB = sb + SM_B;
    int t = threadIdx.x, lane = t & 31, w = t >> 5;
    int wm = w & 3, wn = w >> 2;
    int q = lane & 3, g = lane >> 2;
    int base = base0 + ((int)blockIdx.x << 7);
    int n_rows = n_total - ((int)blockIdx.x << 7); if (n_rows > 128) n_rows = 128;

    build_tile(smem, x, (size_t)base, n_rows, t);

    uint4 P[4];
    ld_chunk(P, g_Wiou_sw, 0, t);   // id(q=0): sub0,pass0 -> chunk 0

    // ---- GEMM1 + epilogue1: 4 passes of 32 H-cols (chunk ids: sub*4 + pass) ----
    float accI[2][2][4], accO[2][2][4], accU[2][2][4];
#pragma unroll 1
    for (int p = 0; p < 4; p++) {
        zacc(accI); zacc(accO); zacc(accU);
#pragma unroll
        for (int sub = 0; sub < 3; sub++) {
            __syncthreads();                     // prior MMA done reading B
            st_chunk(smem + SM_B, P, t);
            int nq = p * 3 + sub + 1;
            if (nq < 12) ld_chunk(P, g_Wiou_sw, (nq % 3) * 4 + nq / 3, t);
            else         ld_chunk(P, g_U_sw, 0, t);
            __syncthreads();                     // B stores visible
            if (sub == 0)      mma_chunk32(sb, sbB, accI, wm, wn, lane);
            else if (sub == 1) mma_chunk32(sb, sbB, accO, wm, wn, lane);
            else               mma_chunk32(sb, sbB, accU, wm, wn, lane);
        }
        // epilogue: gates -> c,h (global)
#pragma unroll
        for (int mi = 0; mi < 2; mi++)
#pragma unroll
        for (int nn = 0; nn < 2; nn++) {
            int cp = p * 32 + wn * 16 + nn * 8 + 2 * q;
            float bi0 = __ldg(b_iou + cp),       bi1 = __ldg(b_iou + cp + 1);
            float bo0 = __ldg(b_iou + 128 + cp), bo1 = __ldg(b_iou + 129 + cp);
            float bu0 = __ldg(b_iou + 256 + cp), bu1 = __ldg(b_iou + 257 + cp);
#pragma unroll
            for (int rh = 0; rh < 2; rh++) {
                int lr = wm * 32 + mi * 16 + g + rh * 8;
                int rg = base + lr;
                bool val = lr < n_rows;
                float2 ui = make_float2(0.f, 0.f), uo = ui, uu = ui, fc = ui;
                if (val && read_sums) {
                    const float* uh = g_uh + (size_t)rg * NIOU + cp;
                    ui = *(const float2*)(uh);
                    uo = *(const float2*)(uh + 128);
                    uu = *(const float2*)(uh + 256);
                    fc = *(const float2*)(g_fc + (size_t)rg * HH + cp);
                }
                float c0 = sigf(accI[mi][nn][rh*2]   + bi0 + ui.x) *
                           tanh_fast(accU[mi][nn][rh*2]   + bu0 + uu.x) + fc.x;
                float c1 = sigf(accI[mi][nn][rh*2+1] + bi1 + ui.y) *
                           tanh_fast(accU[mi][nn][rh*2+1] + bu1 + uu.y) + fc.y;
                float h0 = sigf(accO[mi][nn][rh*2]   + bo0 + uo.x) * tanh_fast(c0);
                float h1 = sigf(accO[mi][nn][rh*2+1] + bo1 + uo.y) * tanh_fast(c1);
                if (val) {
                    *(float2*)(g_c + (size_t)rg * HH + cp) = make_float2(c0, c1);
                    *(float2*)(g_h + (size_t)rg * HH + cp) = make_float2(h0, h1);
                }
            }
        }
    }

    if (!has_parent) return;

    // ---- rebuild A tile in place as h split (g_h visible CTA-wide after sync) ----
    __syncthreads();                             // all GEMM1 A-reads + g_h writes done
    build_tile(smem, g_h, (size_t)base, n_rows, t);

    // ---- GEMM2: g = h @ [U_iou | U_f], 16 chunks of 32 cols ----
    float accG[2][2][4];
#pragma unroll 1
    for (int ch = 0; ch < 16; ch++) {
        __syncthreads();                         // prev MMA done reading B / A built
        st_chunk(smem + SM_B, P, t);
        if (ch < 15) ld_chunk(P, g_U_sw, ch + 1, t);
        __syncthreads();
        zacc(accG);
        mma_chunk32(sb, sbB, accG, wm, wn, lane);
#pragma unroll
        for (int mi = 0; mi < 2; mi++)
#pragma unroll
        for (int nn = 0; nn < 2; nn++) {
            int cb = ch * 32 + wn * 16 + nn * 8 + 2 * q;
            float v[4];
            if (ch < 12) {
#pragma unroll
                for (int r = 0; r < 4; r++) v[r] = accG[mi][nn][r];
            } else {
                int cfl = cb - 384;
#pragma unroll
                for (int rh = 0; rh < 2; rh++) {
                    int lr = wm * 32 + mi * 16 + g + rh * 8;
                    int rg = base + lr;
                    if (lr < n_rows) {
                        int pr = (rg - 1) >> 3;
                        float2 xf2 = *(const float2*)(g_xf + (size_t)pr * HH + cfl);
                        float2 c2  = *(const float2*)(g_c  + (size_t)rg * HH + cfl);
                        v[rh*2]   = sigf(accG[mi][nn][rh*2]   + xf2.x) * c2.x;
                        v[rh*2+1] = sigf(accG[mi][nn][rh*2+1] + xf2.y) * c2.y;
                    } else { v[rh*2] = 0.f; v[rh*2+1] = 0.f; }
                }
            }
#pragma unroll
            for (int r = 0; r < 4; r++) {
                float s = v[r];
                s += __shfl_xor_sync(0xffffffffu, s, 4);
                s += __shfl_xor_sync(0xffffffffu, s, 8);
                s += __shfl_xor_sync(0xffffffffu, s, 16);
                v[r] = s;
            }
            if (lane < 4) {
#pragma unroll
                for (int rh = 0; rh < 2; rh++) {
                    int lr0 = wm * 32 + mi * 16 + rh * 8;
                    if (lr0 < n_rows) {
                        int pr = (base + lr0 - 1) >> 3;
                        if (ch < 12)
                            *(float2*)(g_uh + (size_t)pr * NIOU + cb) =
                                make_float2(v[rh*2], v[rh*2+1]);
                        else
                            *(float2*)(g_fc + (size_t)pr * HH + (cb - 384)) =
                                make_float2(v[rh*2], v[rh*2+1]);
                    }
                }
            }
        }
    }
}

// ---------------------------------------------------------------------------
// Output kernel: out = tanh(LN(h @ W_out + b_out) * gamma + beta)
// ---------------------------------------------------------------------------
__global__ __launch_bounds__(256, 1)
void out_mm(const float* __restrict__ b_out, const float* __restrict__ gamma,
            const float* __restrict__ beta, float* __restrict__ out) {
    extern __shared__ __align__(1024) char smem[];
    uint32_t sb = smem_to_u32(smem);
    uint32_t sbB = sb + SM_B;
    int t = threadIdx.x, lane = t & 31, w = t >> 5;
    int wm = w & 3, wn = w >> 2;
    int q = lane & 3, g = lane >> 2;
    int base = (int)blockIdx.x << 7;
    int n_rows = NN - base; if (n_rows > 128) n_rows = 128;

    build_tile(smem, g_h, (size_t)base, n_rows, t);

    float acc8[8][2][2][4];
    uint4 P[4];
    ld_chunk(P, g_Wout_sw, 0, t);
#pragma unroll 1
    for (int ch = 0; ch < 8; ch++) {
        __syncthreads();
        st_chunk(smem + SM_B, P, t);
        if (ch < 7) ld_chunk(P, g_Wout_sw, ch + 1, t);
        __syncthreads();
        zacc(acc8[ch]);
        mma_chunk32(sb, sbB, acc8[ch], wm, wn, lane);
    }

    // bias + per-row partial sums
    float s[2][2] = {{0.f,0.f},{0.f,0.f}}, sq[2][2] = {{0.f,0.f},{0.f,0.f}};
#pragma unroll
    for (int ch = 0; ch < 8; ch++)
#pragma unroll
    for (int nn = 0; nn < 2; nn++) {
        int cb = ch * 32 + wn * 16 + nn * 8 + 2 * q;
        float b0 = __ldg(b_out + cb), b1 = __ldg(b_out + cb + 1);
#pragma unroll
        for (int mi = 0; mi < 2; mi++)
#pragma unroll
        for (int rh = 0; rh < 2; rh++) {
            float y0 = (acc8[ch][mi][nn][rh*2]   += b0);
            float y1 = (acc8[ch][mi][nn][rh*2+1] += b1);
            s[mi][rh]  += y0 + y1;
            sq[mi][rh] += y0 * y0 + y1 * y1;
        }
    }
#pragma unroll
    for (int mi = 0; mi < 2; mi++)
#pragma unroll
    for (int rh = 0; rh < 2; rh++) {
        s[mi][rh]  += __shfl_xor_sync(0xffffffffu, s[mi][rh], 1);
        s[mi][rh]  += __shfl_xor_sync(0xffffffffu, s[mi][rh], 2);
        sq[mi][rh] += __shfl_xor_sync(0xffffffffu, sq[mi][rh], 1);
        sq[mi][rh] += __shfl_xor_sync(0xffffffffu, sq[mi][rh], 2);
    }
    float2* part = (float2*)(smem + SM_LVL);   // [128][2]
    if (q == 0) {
#pragma unroll
        for (int mi = 0; mi < 2; mi++)
#pragma unroll
        for (int rh = 0; rh < 2; rh++) {
            int lr = wm * 32 + mi * 16 + g + rh * 8;
            part[lr * 2 + wn] = make_float2(s[mi][rh], sq[mi][rh]);
        }
    }
    __syncthreads();
    float mu[2][2], rs[2][2];
#pragma unroll
    for (int mi = 0; mi < 2; mi++)
#pragma unroll
    for (int rh = 0; rh < 2; rh++) {
        int lr = wm * 32 + mi * 16 + g + rh * 8;
        float2 a = part[lr * 2], b = part[lr * 2 + 1];
        float m = (a.x + b.x) * (1.f / 256.f);
        float var = (a.y + b.y) * (1.f / 256.f) - m * m;
        mu[mi][rh] = m;
        rs[mi][rh] = rsqrtf(var + 1e-5f);
    }
#pragma unroll
    for (int ch = 0; ch < 8; ch++)
#pragma unroll
    for (int nn = 0; nn < 2; nn++) {
        int cb = ch * 32 + wn * 16 + nn * 8 + 2 * q;
        float g0 = __ldg(gamma + cb), g1 = __ldg(gamma + cb + 1);
        float e0 = __ldg(beta + cb),  e1 = __ldg(beta + cb + 1);
#pragma unroll
        for (int mi = 0; mi < 2; mi++)
#pragma unroll
        for (int rh = 0; rh < 2; rh++) {
            int lr = wm * 32 + mi * 16 + g + rh * 8;
            if (lr < n_rows) {
                float y0 = (acc8[ch][mi][nn][rh*2]   - mu[mi][rh]) * rs[mi][rh] * g0 + e0;
                float y1 = (acc8[ch][mi][nn][rh*2+1] - mu[mi][rh]) * rs[mi][rh] * g1 + e1;
                *(float2*)(out + (size_t)(base + lr) * DDEC + cb) =
                    make_float2(tanh_fast(y0), tanh_fast(y1));
            }
        }
    }
}

// ---------------------------------------------------------------------------
// x_f precompute (FFMA, small): g_xf[r] = x[r] @ W_f + b_f  for r < NPAR
// ---------------------------------------------------------------------------
#define TS 68
__global__ void xf_kernel(const float* __restrict__ x, const float* __restrict__ W_f,
                          const float* __restrict__ b_f) {
    extern __shared__ float sm[];
    float* As = sm;
    float* Ws = sm + 128 * TS;
    int t = threadIdx.x;
    int base = blockIdx.x << 6;
    int n_rows = NPAR - base; if (n_rows > 64) n_rows = 64;
    int m0 = (t & 15) * 4, c0 = (t >> 4) * 4;

#pragma unroll
    for (int i = 0; i < 32; i++) {
        int idx = t + 256 * i;
        int m = idx >> 7, k = idx & 127;
        float v = 0.f;
        if (m < n_rows) v = x[(size_t)(base + m) * HH + k];
        As[k * TS + m] = v;
    }
    for (int ch = 0; ch < 2; ch++) {
        __syncthreads();
#pragma unroll
        for (int i = 0; i < 32; i++) {
            int idx = t + 256 * i;
            int k = idx >> 6, c = idx & 63;
            Ws[k * TS + c] = W_f[k * HH + ch * 64 + c];
        }
        __syncthreads();
        float acc[4][4] = {};
#pragma unroll 8
        for (int k = 0; k < 128; k++) {
            float4 a = *(const float4*)(As + k * TS + m0);
            float4 b = *(const float4*)(Ws + k * TS + c0);
            acc[0][0] += a.x*b.x; acc[0][1] += a.x*b.y; acc[0][2] += a.x*b.z; acc[0][3] += a.x*b.w;
            acc[1][0] += a.y*b.x; acc[1][1] += a.y*b.y; acc[1][2] += a.y*b.z; acc[1][3] += a.y*b.w;
            acc[2][0] += a.z*b.x; acc[2][1] += a.z*b.y; acc[2][2] += a.z*b.z; acc[2][3] += a.z*b.w;
            acc[3][0] += a.w*b.x; acc[3][1] += a.w*b.y; acc[3][2] += a.w*b.z; acc[3][3] += a.w*b.w;
        }
#pragma unroll
        for (int i = 0; i < 4; i++)
#pragma unroll
            for (int j = 0; j < 4; j++) {
                int m = m0 + i, cc = ch * 64 + c0 + j;
                if (m < n_rows)
                    g_xf[(size_t)(base + m) * HH + cc] = acc[i][j] + b_f[cc];
            }
    }
}

// ---------------------------------------------------------------------------
extern "C" void kernel_launch(void* const* d_in, const int* in_sizes, int n_in,
                              void* d_out, int out_size) {
    const float* x = (const float*)d_in[0];
    int wi = 3;
    if (n_in > 3 && in_sizes[3] <= 1) wi = 4;
    const float* W_iou = (const float*)d_in[wi + 0];
    const float* b_iou = (const float*)d_in[wi + 1];
    const float* U_iou = (const float*)d_in[wi + 2];
    const float* W_f   = (const float*)d_in[wi + 3];
    const float* b_f   = (const float*)d_in[wi + 4];
    const float* U_f   = (const float*)d_in[wi + 5];
    const float* W_out = (const float*)d_in[wi + 6];
    const float* b_out = (const float*)d_in[wi + 7];
    const float* gamma = (const float*)d_in[wi + 8];
    const float* beta  = (const float*)d_in[wi + 9];
    float* out = (float*)d_out;

    cudaFuncSetAttribute(level_mm, cudaFuncAttributeMaxDynamicSharedMemorySize, SM_LVL);
    cudaFuncSetAttribute(out_mm,   cudaFuncAttributeMaxDynamicSharedMemorySize, SM_OUT);
    cudaFuncSetAttribute(xf_kernel, cudaFuncAttributeMaxDynamicSharedMemorySize,
                         (2 * 128 * TS) * (int)sizeof(float));

    // weight prep (split + swizzle into 32-col chunks)
    prep_kernel<<<192, 256>>>(W_iou, 384, 0, 0);
    prep_kernel<<<192, 256>>>(U_iou, 384, 1, 0);
    prep_kernel<<< 64, 256>>>(U_f,   128, 1, 12);
    prep_kernel<<<128, 256>>>(W_out, 256, 2, 0);

    xf_kernel<<<(NPAR + 63) / 64, 256, (2 * 128 * TS) * sizeof(float)>>>(x, W_f, b_f);

    const int off[8] = {0, 1, 9, 73, 585, 4681, 37449, 299593};
    for (int l = 6; l >= 0; l--) {
        int base = off[l], n = off[l + 1] - off[l];
        int blocks = (n + 127) / 128;
        level_mm<<<blocks, 256, SM_LVL>>>(x, b_iou, base, n,
                                          (l < 6) ? 1 : 0, (l > 0) ? 1 : 0);
    }
    out_mm<<<(NN + 127) / 128, 256, SM_OUT>>>(b_out, gamma, beta, out);
}

// round 9
// speedup vs baseline: 2.7056x; 1.0602x over previous
#include <cuda_runtime.h>
#include <cuda_bf16.h>
#include <math.h>
#include <stdint.h>

// ---------------------------------------------------------------------------
// Problem constants
// ---------------------------------------------------------------------------
#define NN    299593      // total nodes, complete 8-ary tree, 7 levels
#define HH    128         // D_ENC == D_EMB
#define NIOU  384         // 3*H
#define DDEC  256
#define NPAR  37449       // nodes at levels 0..5 (all parents)

#define CHUNK_BYTES 16384 // one pre-swizzled B chunk: 32 N-rows x 256 Kcat x bf16
#define CHUNK_U4    (CHUNK_BYTES / 16)

// Scratch (device globals: allocation-free per harness rules)
__device__ float g_h [(size_t)NN  * HH];
__device__ float g_c [(size_t)NN  * HH];
__device__ float g_xf[(size_t)NPAR * HH];
__device__ float g_uh[(size_t)NPAR * NIOU];
__device__ float g_fc[(size_t)NPAR * HH];

// Pre-swizzled bf16-split weight blobs ([hi | lo] over Kcat=256), 32-row chunks
__device__ uint4 g_Wiou_sw[12 * CHUNK_U4];
__device__ uint4 g_U_sw   [16 * CHUNK_U4];  // [U_iou(384) | U_f(128)] cols
__device__ uint4 g_Wout_sw[ 8 * CHUNK_U4];

// ---------------------------------------------------------------------------
// Helpers
// ---------------------------------------------------------------------------
__device__ __forceinline__ uint32_t smem_to_u32(const void* p) {
    uint32_t a;
    asm("{ .reg .u64 t; cvta.to.shared.u64 t, %1; cvt.u32.u64 %0, t; }" : "=r"(a) : "l"(p));
    return a;
}
__device__ __forceinline__ uint32_t swz(uint32_t o) { return o ^ ((o >> 3) & 0x70); }
__device__ __forceinline__ uint32_t offA(int row, int k) {  // 128-row tile: 16 atoms/kblk
    return swz((uint32_t)(((row >> 3) + (k >> 6) * 16) * 1024 + (row & 7) * 128 + (k & 63) * 2));
}
__device__ __forceinline__ uint32_t offB32(int row, int k) { // 32-row tile: 4 atoms/kblk
    return swz((uint32_t)(((row >> 3) + (k >> 6) * 4) * 1024 + (row & 7) * 128 + (k & 63) * 2));
}
__device__ __forceinline__ unsigned short f2bfu(float v) {
    __nv_bfloat16 b = __float2bfloat16(v);
    return *reinterpret_cast<unsigned short*>(&b);
}
__device__ __forceinline__ float bfu2f(unsigned short u) {
    __nv_bfloat16 b = *reinterpret_cast<__nv_bfloat16*>(&u);
    return __bfloat162float(b);
}
__device__ __forceinline__ void split2(float a, float b, uint32_t& hi, uint32_t& lo) {
    unsigned short ha = f2bfu(a), hb = f2bfu(b);
    unsigned short la = f2bfu(a - bfu2f(ha)), lb = f2bfu(b - bfu2f(hb));
    hi = (uint32_t)ha | ((uint32_t)hb << 16);
    lo = (uint32_t)la | ((uint32_t)lb << 16);
}
__device__ __forceinline__ float sigf(float v) {
    return __fdividef(1.0f, 1.0f + __expf(-v));
}
__device__ __forceinline__ float tanh_fast(float x) {
    float t = __expf(2.0f * x);
    return 1.0f - __fdividef(2.0f, t + 1.0f);
}

#define LDSM4(R0, R1, R2, R3, ADDR) \
    asm volatile("ldmatrix.sync.aligned.m8n8.x4.shared.b16 {%0,%1,%2,%3}, [%4];" \
                 : "=r"(R0), "=r"(R1), "=r"(R2), "=r"(R3) : "r"(ADDR))

__device__ __forceinline__ void mma_bf16(float (&d)[4], const uint32_t (&a)[4],
                                         uint32_t b0, uint32_t b1) {
    asm volatile("mma.sync.aligned.m16n8k16.row.col.f32.bf16.bf16.f32 "
                 "{%0,%1,%2,%3}, {%4,%5,%6,%7}, {%8,%9}, {%0,%1,%2,%3};"
                 : "+f"(d[0]), "+f"(d[1]), "+f"(d[2]), "+f"(d[3])
                 : "r"(a[0]), "r"(a[1]), "r"(a[2]), "r"(a[3]), "r"(b0), "r"(b1));
}

__device__ __forceinline__ void zacc(float (&a)[2][2][4]) {
#pragma unroll
    for (int i = 0; i < 2; i++)
#pragma unroll
        for (int j = 0; j < 2; j++)
#pragma unroll
            for (int k = 0; k < 4; k++) a[i][j][k] = 0.f;
}

// One 32-col chunk: per-warp C[m32 x n16] += A_cat[128x256] * B_cat[32x256]^T
// 3-term bf16 split via kcat offsets: (Ah,Bh),(Al,Bh),(Ah,Bl)
__device__ __forceinline__ void mma_chunk32(uint32_t Abase, uint32_t Bbase,
                                            float (&acc)[2][2][4],
                                            int wm, int wn, int lane) {
    int rA = wm * 32 + (lane & 15);
    uint32_t PA = Abase + ((rA >> 3) << 10) + ((rA & 7) << 7);
    uint32_t CA = (rA & 7) << 4;
    int aK = (lane >> 4) << 3;
    int nB = wn * 16 + (((lane >> 4) & 1) << 3) + (lane & 7);
    uint32_t PB = Bbase + ((nB >> 3) << 10) + ((nB & 7) << 7);
    uint32_t CB = (nB & 7) << 4;
    int bK = ((lane >> 3) & 1) << 3;
#pragma unroll 4
    for (int s = 0; s < 24; s++) {
        int t3 = s >> 3;
        int kc = (s & 7) << 4;
        int kA = kc + aK + ((t3 == 1) ? 128 : 0);
        int kB = kc + bK + ((t3 == 2) ? 128 : 0);
        uint32_t aA = PA + ((uint32_t)(kA >> 6) << 14) + ((uint32_t)((kA & 63) << 1) ^ CA);
        uint32_t aB = PB + ((uint32_t)(kB >> 6) << 12) + ((uint32_t)((kB & 63) << 1) ^ CB);
        uint32_t a0[4], a1[4], b[4];
        LDSM4(a0[0], a0[1], a0[2], a0[3], aA);
        LDSM4(a1[0], a1[1], a1[2], a1[3], aA + 2048);
        LDSM4(b[0], b[1], b[2], b[3], aB);
        mma_bf16(acc[0][0], a0, b[0], b[1]);
        mma_bf16(acc[1][0], a1, b[0], b[1]);
        mma_bf16(acc[0][1], a0, b[2], b[3]);
        mma_bf16(acc[1][1], a1, b[2], b[3]);
    }
}

// ---------------------------------------------------------------------------
// cp.async: one 16KB chunk, 256 threads x 4 x 16B, one commit group
// ---------------------------------------------------------------------------
__device__ __forceinline__ void cp_chunk(uint32_t dst, const uint4* src, int t) {
    const char* s = (const char*)src;
#pragma unroll
    for (int i = 0; i < 4; i++)
        asm volatile("cp.async.cg.shared.global [%0], [%1], 16;"
                     :: "r"(dst + (uint32_t)(t * 16 + i * 4096)),
                        "l"(s + t * 16 + i * 4096) : "memory");
    asm volatile("cp.async.commit_group;" ::: "memory");
}
#define CP_WAIT1() asm volatile("cp.async.wait_group 1;" ::: "memory")
#define CP_WAIT0() asm volatile("cp.async.wait_group 0;" ::: "memory")

// ---------------------------------------------------------------------------
// Weight prep: split fp32 src[128][ncols] into bf16 hi/lo, swizzle into blobs
// ---------------------------------------------------------------------------
__global__ void prep_kernel(const float* __restrict__ src, int ncols, int dst_id, int chunkoff) {
    int idx = blockIdx.x * blockDim.x + threadIdx.x;
    if (idx >= 128 * ncols) return;
    int k = idx / ncols, n = idx - k * ncols;
    float v = src[k * ncols + n];
    unsigned short hu = f2bfu(v);
    unsigned short lu = f2bfu(v - bfu2f(hu));
    unsigned char* bb = (dst_id == 0) ? (unsigned char*)g_Wiou_sw
                      : (dst_id == 1) ? (unsigned char*)g_U_sw
                                      : (unsigned char*)g_Wout_sw;
    unsigned char* blob = bb + (size_t)(chunkoff + (n >> 5)) * CHUNK_BYTES;
    int row = n & 31;
    *(unsigned short*)(blob + offB32(row, k))       = hu;
    *(unsigned short*)(blob + offB32(row, 128 + k)) = lu;
}

// ---------------------------------------------------------------------------
// SMEM layout (dynamic, 1024-aligned):
//   A tile [0, 65536)          128 x 256 kcat bf16, SW128 blocked (x, later h)
//   B ring [65536, 114688)     3 x 16KB cp.async chunk buffers
//   LN part: reuse [65536,..)  out kernel only, after MMAs drain
// ---------------------------------------------------------------------------
#define SM_B    65536
#define SM_TOT  114688

// build a 128x[hi|lo] split tile from fp32 rows (src row-major, HH cols)
__device__ __forceinline__ void build_tile(char* Ac, const float* src, size_t base,
                                           int n_rows, int t) {
    int row = t >> 1, kh = (t & 1) << 6;
    bool val = row < n_rows;
    const float4* xr = (const float4*)(src + (base + row) * HH + kh);
#pragma unroll
    for (int gg = 0; gg < 8; gg++) {
        float v[8];
        if (val) {
            float4 a = xr[gg * 2], b = xr[gg * 2 + 1];
            v[0]=a.x; v[1]=a.y; v[2]=a.z; v[3]=a.w; v[4]=b.x; v[5]=b.y; v[6]=b.z; v[7]=b.w;
        } else {
#pragma unroll
            for (int q = 0; q < 8; q++) v[q] = 0.f;
        }
        uint32_t hi[4], lo[4];
#pragma unroll
        for (int q = 0; q < 4; q++) split2(v[2*q], v[2*q+1], hi[q], lo[q]);
        int kc = kh + gg * 8;
        *(uint4*)(Ac + offA(row, kc))       = make_uint4(hi[0], hi[1], hi[2], hi[3]);
        *(uint4*)(Ac + offA(row, 128 + kc)) = make_uint4(lo[0], lo[1], lo[2], lo[3]);
    }
}

// blob source for sequence slot in the level kernel (0..11 GEMM1, 12..27 GEMM2)
__device__ __forceinline__ const uint4* lvl_src(int seq) {
    if (seq < 12) {
        int p = seq / 3, sub = seq - p * 3;          // blob chunk = sub*4 + p
        return g_Wiou_sw + (size_t)(sub * 4 + p) * CHUNK_U4;
    }
    return g_U_sw + (size_t)(seq - 12) * CHUNK_U4;
}

// ---------------------------------------------------------------------------
// Fused per-level kernel: one CTA per 128-row tile, 256 threads, 2 CTAs/SM
// ---------------------------------------------------------------------------
__global__ __launch_bounds__(256, 2)
void level_mm(const float* __restrict__ x, const float* __restrict__ b_iou,
              int base0, int n_total, int read_sums, int has_parent) {
    extern __shared__ __align__(1024) char smem[];
    uint32_t sb = smem_to_u32(smem);
    int t = threadIdx.x, lane = t & 31, w = t >> 5;
    int wm = w & 3, wn = w >> 2;
    int q = lane & 3, g = lane >> 2;
    int base = base0 + ((int)blockIdx.x << 7);
    int n_rows = n_total - ((int)blockIdx.x << 7); if (n_rows > 128) n_rows = 128;
    const int NSEQ = has_parent ? 28 : 12;

    // prologue: 2 chunks in flight before building A
    cp_chunk(sb + SM_B, lvl_src(0), t);
    cp_chunk(sb + SM_B + CHUNK_BYTES, lvl_src(1), t);

    build_tile(smem, x, (size_t)base, n_rows, t);

    float accI[2][2][4], accO[2][2][4], accU[2][2][4];
    zacc(accI); zacc(accO); zacc(accU);

    for (int seq = 0; seq < NSEQ; seq++) {
        if (seq + 1 < NSEQ) { CP_WAIT1(); } else { CP_WAIT0(); }
        __syncthreads();                 // chunk seq visible; mma(seq-1) drained
        if (seq + 2 < NSEQ)
            cp_chunk(sb + SM_B + (uint32_t)((seq + 2) % 3) * CHUNK_BYTES,
                     lvl_src(seq + 2), t);
        uint32_t Bb = sb + SM_B + (uint32_t)(seq % 3) * CHUNK_BYTES;

        if (seq < 12) {
            int p = seq / 3, sub = seq - p * 3;
            if (sub == 0)      mma_chunk32(sb, Bb, accI, wm, wn, lane);
            else if (sub == 1) mma_chunk32(sb, Bb, accO, wm, wn, lane);
            else               mma_chunk32(sb, Bb, accU, wm, wn, lane);
            if (sub == 2) {
                // epilogue1 for pass p: gates -> c,h (global)
#pragma unroll
                for (int mi = 0; mi < 2; mi++)
#pragma unroll
                for (int nn = 0; nn < 2; nn++) {
                    int cp = p * 32 + wn * 16 + nn * 8 + 2 * q;
                    float bi0 = __ldg(b_iou + cp),       bi1 = __ldg(b_iou + cp + 1);
                    float bo0 = __ldg(b_iou + 128 + cp), bo1 = __ldg(b_iou + 129 + cp);
                    float bu0 = __ldg(b_iou + 256 + cp), bu1 = __ldg(b_iou + 257 + cp);
#pragma unroll
                    for (int rh = 0; rh < 2; rh++) {
                        int lr = wm * 32 + mi * 16 + g + rh * 8;
                        int rg = base + lr;
                        bool val = lr < n_rows;
                        float2 ui = make_float2(0.f, 0.f), uo = ui, uu = ui, fc = ui;
                        if (val && read_sums) {
                            const float* uh = g_uh + (size_t)rg * NIOU + cp;
                            ui = *(const float2*)(uh);
                            uo = *(const float2*)(uh + 128);
                            uu = *(const float2*)(uh + 256);
                            fc = *(const float2*)(g_fc + (size_t)rg * HH + cp);
                        }
                        float c0 = sigf(accI[mi][nn][rh*2]   + bi0 + ui.x) *
                                   tanh_fast(accU[mi][nn][rh*2]   + bu0 + uu.x) + fc.x;
                        float c1 = sigf(accI[mi][nn][rh*2+1] + bi1 + ui.y) *
                                   tanh_fast(accU[mi][nn][rh*2+1] + bu1 + uu.y) + fc.y;
                        float h0 = sigf(accO[mi][nn][rh*2]   + bo0 + uo.x) * tanh_fast(c0);
                        float h1 = sigf(accO[mi][nn][rh*2+1] + bo1 + uo.y) * tanh_fast(c1);
                        if (val) {
                            *(float2*)(g_c + (size_t)rg * HH + cp) = make_float2(c0, c1);
                            *(float2*)(g_h + (size_t)rg * HH + cp) = make_float2(h0, h1);
                        }
                    }
                }
                zacc(accI); zacc(accO); zacc(accU);
                if (seq == 11 && has_parent) {
                    // rebuild A as h-split; barrier at seq=12 publishes it
                    __syncthreads();            // all warps done reading A (GEMM1)
                    build_tile(smem, g_h, (size_t)base, n_rows, t);
                }
            }
        } else {
            // GEMM2 chunk ch: g = h @ [U_iou | U_f] cols [ch*32, ch*32+32)
            int ch = seq - 12;
            mma_chunk32(sb, Bb, accI, wm, wn, lane);   // reuse accI as accG
#pragma unroll
            for (int mi = 0; mi < 2; mi++)
#pragma unroll
            for (int nn = 0; nn < 2; nn++) {
                int cb = ch * 32 + wn * 16 + nn * 8 + 2 * q;
                float v[4];
                if (ch < 12) {
#pragma unroll
                    for (int r = 0; r < 4; r++) v[r] = accI[mi][nn][r];
                } else {
                    int cfl = cb - 384;
#pragma unroll
                    for (int rh = 0; rh < 2; rh++) {
                        int lr = wm * 32 + mi * 16 + g + rh * 8;
                        int rg = base + lr;
                        if (lr < n_rows) {
                            int pr = (rg - 1) >> 3;
                            float2 xf2 = *(const float2*)(g_xf + (size_t)pr * HH + cfl);
                            float2 c2  = *(const float2*)(g_c  + (size_t)rg * HH + cfl);
                            v[rh*2]   = sigf(accI[mi][nn][rh*2]   + xf2.x) * c2.x;
                            v[rh*2+1] = sigf(accI[mi][nn][rh*2+1] + xf2.y) * c2.y;
                        } else { v[rh*2] = 0.f; v[rh*2+1] = 0.f; }
                    }
                }
#pragma unroll
                for (int r = 0; r < 4; r++) {
                    float s = v[r];
                    s += __shfl_xor_sync(0xffffffffu, s, 4);
                    s += __shfl_xor_sync(0xffffffffu, s, 8);
                    s += __shfl_xor_sync(0xffffffffu, s, 16);
                    v[r] = s;
                }
                if (lane < 4) {
#pragma unroll
                    for (int rh = 0; rh < 2; rh++) {
                        int lr0 = wm * 32 + mi * 16 + rh * 8;
                        if (lr0 < n_rows) {
                            int pr = (base + lr0 - 1) >> 3;
                            if (ch < 12)
                                *(float2*)(g_uh + (size_t)pr * NIOU + cb) =
                                    make_float2(v[rh*2], v[rh*2+1]);
                            else
                                *(float2*)(g_fc + (size_t)pr * HH + (cb - 384)) =
                                    make_float2(v[rh*2], v[rh*2+1]);
                        }
                    }
                }
            }
            zacc(accI);
        }
    }
}

// ---------------------------------------------------------------------------
// Output kernel: out = tanh(LN(h @ W_out + b_out) * gamma + beta)
// ---------------------------------------------------------------------------
__global__ __launch_bounds__(256, 1)
void out_mm(const float* __restrict__ b_out, const float* __restrict__ gamma,
            const float* __restrict__ beta, float* __restrict__ out) {
    extern __shared__ __align__(1024) char smem[];
    uint32_t sb = smem_to_u32(smem);
    int t = threadIdx.x, lane = t & 31, w = t >> 5;
    int wm = w & 3, wn = w >> 2;
    int q = lane & 3, g = lane >> 2;
    int base = (int)blockIdx.x << 7;
    int n_rows = NN - base; if (n_rows > 128) n_rows = 128;

    cp_chunk(sb + SM_B, (const uint4*)g_Wout_sw, t);
    cp_chunk(sb + SM_B + CHUNK_BYTES, g_Wout_sw + CHUNK_U4, t);

    build_tile(smem, g_h, (size_t)base, n_rows, t);

    float acc8[8][2][2][4];
    for (int seq = 0; seq < 8; seq++) {
        if (seq + 1 < 8) { CP_WAIT1(); } else { CP_WAIT0(); }
        __syncthreads();
        if (seq + 2 < 8)
            cp_chunk(sb + SM_B + (uint32_t)((seq + 2) % 3) * CHUNK_BYTES,
                     g_Wout_sw + (size_t)(seq + 2) * CHUNK_U4, t);
        zacc(acc8[seq]);
        mma_chunk32(sb, sb + SM_B + (uint32_t)(seq % 3) * CHUNK_BYTES,
                    acc8[seq], wm, wn, lane);
    }

    // bias + per-row partial sums
    float s[2][2] = {{0.f,0.f},{0.f,0.f}}, sq[2][2] = {{0.f,0.f},{0.f,0.f}};
#pragma unroll
    for (int ch = 0; ch < 8; ch++)
#pragma unroll
    for (int nn = 0; nn < 2; nn++) {
        int cb = ch * 32 + wn * 16 + nn * 8 + 2 * q;
        float b0 = __ldg(b_out + cb), b1 = __ldg(b_out + cb + 1);
#pragma unroll
        for (int mi = 0; mi < 2; mi++)
#pragma unroll
        for (int rh = 0; rh < 2; rh++) {
            float y0 = (acc8[ch][mi][nn][rh*2]   += b0);
            float y1 = (acc8[ch][mi][nn][rh*2+1] += b1);
            s[mi][rh]  += y0 + y1;
            sq[mi][rh] += y0 * y0 + y1 * y1;
        }
    }
#pragma unroll
    for (int mi = 0; mi < 2; mi++)
#pragma unroll
    for (int rh = 0; rh < 2; rh++) {
        s[mi][rh]  += __shfl_xor_sync(0xffffffffu, s[mi][rh], 1);
        s[mi][rh]  += __shfl_xor_sync(0xffffffffu, s[mi][rh], 2);
        sq[mi][rh] += __shfl_xor_sync(0xffffffffu, sq[mi][rh], 1);
        sq[mi][rh] += __shfl_xor_sync(0xffffffffu, sq[mi][rh], 2);
    }
    float2* part = (float2*)(smem + SM_B);   // B ring idle after MMAs drain
    __syncthreads();
    if (q == 0) {
#pragma unroll
        for (int mi = 0; mi < 2; mi++)
#pragma unroll
        for (int rh = 0; rh < 2; rh++) {
            int lr = wm * 32 + mi * 16 + g + rh * 8;
            part[lr * 2 + wn] = make_float2(s[mi][rh], sq[mi][rh]);
        }
    }
    __syncthreads();
    float mu[2][2], rs[2][2];
#pragma unroll
    for (int mi = 0; mi < 2; mi++)
#pragma unroll
    for (int rh = 0; rh < 2; rh++) {
        int lr = wm * 32 + mi * 16 + g + rh * 8;
        float2 a = part[lr * 2], b = part[lr * 2 + 1];
        float m = (a.x + b.x) * (1.f / 256.f);
        float var = (a.y + b.y) * (1.f / 256.f) - m * m;
        mu[mi][rh] = m;
        rs[mi][rh] = rsqrtf(var + 1e-5f);
    }
#pragma unroll
    for (int ch = 0; ch < 8; ch++)
#pragma unroll
    for (int nn = 0; nn < 2; nn++) {
        int cb = ch * 32 + wn * 16 + nn * 8 + 2 * q;
        float g0 = __ldg(gamma + cb), g1 = __ldg(gamma + cb + 1);
        float e0 = __ldg(beta + cb),  e1 = __ldg(beta + cb + 1);
#pragma unroll
        for (int mi = 0; mi < 2; mi++)
#pragma unroll
        for (int rh = 0; rh < 2; rh++) {
            int lr = wm * 32 + mi * 16 + g + rh * 8;
            if (lr < n_rows) {
                float y0 = (acc8[ch][mi][nn][rh*2]   - mu[mi][rh]) * rs[mi][rh] * g0 + e0;
                float y1 = (acc8[ch][mi][nn][rh*2+1] - mu[mi][rh]) * rs[mi][rh] * g1 + e1;
                *(float2*)(out + (size_t)(base + lr) * DDEC + cb) =
                    make_float2(tanh_fast(y0), tanh_fast(y1));
            }
        }
    }
}

// ---------------------------------------------------------------------------
// x_f precompute (FFMA, small): g_xf[r] = x[r] @ W_f + b_f  for r < NPAR
// ---------------------------------------------------------------------------
#define TS 68
__global__ void xf_kernel(const float* __restrict__ x, const float* __restrict__ W_f,
                          const float* __restrict__ b_f) {
    extern __shared__ float sm[];
    float* As = sm;
    float* Ws = sm + 128 * TS;
    int t = threadIdx.x;
    int base = blockIdx.x << 6;
    int n_rows = NPAR - base; if (n_rows > 64) n_rows = 64;
    int m0 = (t & 15) * 4, c0 = (t >> 4) * 4;

#pragma unroll
    for (int i = 0; i < 32; i++) {
        int idx = t + 256 * i;
        int m = idx >> 7, k = idx & 127;
        float v = 0.f;
        if (m < n_rows) v = x[(size_t)(base + m) * HH + k];
        As[k * TS + m] = v;
    }
    for (int ch = 0; ch < 2; ch++) {
        __syncthreads();
#pragma unroll
        for (int i = 0; i < 32; i++) {
            int idx = t + 256 * i;
            int k = idx >> 6, c = idx & 63;
            Ws[k * TS + c] = W_f[k * HH + ch * 64 + c];
        }
        __syncthreads();
        float acc[4][4] = {};
#pragma unroll 8
        for (int k = 0; k < 128; k++) {
            float4 a = *(const float4*)(As + k * TS + m0);
            float4 b = *(const float4*)(Ws + k * TS + c0);
            acc[0][0] += a.x*b.x; acc[0][1] += a.x*b.y; acc[0][2] += a.x*b.z; acc[0][3] += a.x*b.w;
            acc[1][0] += a.y*b.x; acc[1][1] += a.y*b.y; acc[1][2] += a.y*b.z; acc[1][3] += a.y*b.w;
            acc[2][0] += a.z*b.x; acc[2][1] += a.z*b.y; acc[2][2] += a.z*b.z; acc[2][3] += a.z*b.w;
            acc[3][0] += a.w*b.x; acc[3][1] += a.w*b.y; acc[3][2] += a.w*b.z; acc[3][3] += a.w*b.w;
        }
#pragma unroll
        for (int i = 0; i < 4; i++)
#pragma unroll
            for (int j = 0; j < 4; j++) {
                int m = m0 + i, cc = ch * 64 + c0 + j;
                if (m < n_rows)
                    g_xf[(size_t)(base + m) * HH + cc] = acc[i][j] + b_f[cc];
            }
    }
}

// ---------------------------------------------------------------------------
extern "C" void kernel_launch(void* const* d_in, const int* in_sizes, int n_in,
                              void* d_out, int out_size) {
    const float* x = (const float*)d_in[0];
    int wi = 3;
    if (n_in > 3 && in_sizes[3] <= 1) wi = 4;
    const float* W_iou = (const float*)d_in[wi + 0];
    const float* b_iou = (const float*)d_in[wi + 1];
    const float* U_iou = (const float*)d_in[wi + 2];
    const float* W_f   = (const float*)d_in[wi + 3];
    const float* b_f   = (const float*)d_in[wi + 4];
    const float* U_f   = (const float*)d_in[wi + 5];
    const float* W_out = (const float*)d_in[wi + 6];
    const float* b_out = (const float*)d_in[wi + 7];
    const float* gamma = (const float*)d_in[wi + 8];
    const float* beta  = (const float*)d_in[wi + 9];
    float* out = (float*)d_out;

    cudaFuncSetAttribute(level_mm, cudaFuncAttributeMaxDynamicSharedMemorySize, SM_TOT);
    cudaFuncSetAttribute(out_mm,   cudaFuncAttributeMaxDynamicSharedMemorySize, SM_TOT);
    cudaFuncSetAttribute(xf_kernel, cudaFuncAttributeMaxDynamicSharedMemorySize,
                         (2 * 128 * TS) * (int)sizeof(float));

    // weight prep (split + swizzle into 32-col chunks)
    prep_kernel<<<192, 256>>>(W_iou, 384, 0, 0);
    prep_kernel<<<192, 256>>>(U_iou, 384, 1, 0);
    prep_kernel<<< 64, 256>>>(U_f,   128, 1, 12);
    prep_kernel<<<128, 256>>>(W_out, 256, 2, 0);

    xf_kernel<<<(NPAR + 63) / 64, 256, (2 * 128 * TS) * sizeof(float)>>>(x, W_f, b_f);

    const int off[8] = {0, 1, 9, 73, 585, 4681, 37449, 299593};
    for (int l = 6; l >= 0; l--) {
        int base = off[l], n = off[l + 1] - off[l];
        int blocks = (n + 127) / 128;
        level_mm<<<blocks, 256, SM_TOT>>>(x, b_iou, base, n,
                                          (l < 6) ? 1 : 0, (l > 0) ? 1 : 0);
    }
    out_mm<<<(NN + 127) / 128, 256, SM_TOT>>>(b_out, gamma, beta, out);
}

// round 10
// speedup vs baseline: 3.2316x; 1.1944x over previous
#include <cuda_runtime.h>
#include <cuda_bf16.h>
#include <math.h>
#include <stdint.h>

// ---------------------------------------------------------------------------
// Problem constants
// ---------------------------------------------------------------------------
#define NN    299593      // total nodes, complete 8-ary tree, 7 levels
#define HH    128         // D_ENC == D_EMB
#define NIOU  384         // 3*H
#define DDEC  256
#define NPAR  37449       // nodes at levels 0..5 (all parents)

#define CHUNK_BYTES 16384 // one pre-swizzled B chunk: 32 N-rows x 256 Kcat x bf16
#define CHUNK_U4    (CHUNK_BYTES / 16)

// Scratch (device globals: allocation-free per harness rules)
__device__ float g_h [(size_t)NN  * HH];
__device__ float g_c [(size_t)NN  * HH];
__device__ float g_xf[(size_t)NPAR * HH];
__device__ float g_uh[(size_t)NPAR * NIOU];
__device__ float g_fc[(size_t)NPAR * HH];

// Pre-swizzled bf16-split weight blobs ([hi | lo] over Kcat=256), 32-row chunks
__device__ uint4 g_Wiou_sw[12 * CHUNK_U4];
__device__ uint4 g_U_sw   [16 * CHUNK_U4];  // [U_iou(384) | U_f(128)] cols
__device__ uint4 g_Wout_sw[ 8 * CHUNK_U4];

// ---------------------------------------------------------------------------
// Helpers
// ---------------------------------------------------------------------------
__device__ __forceinline__ uint32_t smem_to_u32(const void* p) {
    uint32_t a;
    asm("{ .reg .u64 t; cvta.to.shared.u64 t, %1; cvt.u32.u64 %0, t; }" : "=r"(a) : "l"(p));
    return a;
}
__device__ __forceinline__ uint32_t swz(uint32_t o) { return o ^ ((o >> 3) & 0x70); }
__device__ __forceinline__ uint32_t offA(int row, int k) {  // 128-row tile: 16 atoms/kblk
    return swz((uint32_t)(((row >> 3) + (k >> 6) * 16) * 1024 + (row & 7) * 128 + (k & 63) * 2));
}
__device__ __forceinline__ uint32_t offB32(int row, int k) { // 32-row tile: 4 atoms/kblk
    return swz((uint32_t)(((row >> 3) + (k >> 6) * 4) * 1024 + (row & 7) * 128 + (k & 63) * 2));
}
__device__ __forceinline__ unsigned short f2bfu(float v) {
    __nv_bfloat16 b = __float2bfloat16(v);
    return *reinterpret_cast<unsigned short*>(&b);
}
__device__ __forceinline__ float bfu2f(unsigned short u) {
    __nv_bfloat16 b = *reinterpret_cast<__nv_bfloat16*>(&u);
    return __bfloat162float(b);
}
__device__ __forceinline__ void split2(float a, float b, uint32_t& hi, uint32_t& lo) {
    unsigned short ha = f2bfu(a), hb = f2bfu(b);
    unsigned short la = f2bfu(a - bfu2f(ha)), lb = f2bfu(b - bfu2f(hb));
    hi = (uint32_t)ha | ((uint32_t)hb << 16);
    lo = (uint32_t)la | ((uint32_t)lb << 16);
}
__device__ __forceinline__ float sigf(float v) {
    return __fdividef(1.0f, 1.0f + __expf(-v));
}
__device__ __forceinline__ float tanh_fast(float x) {
    float t = __expf(2.0f * x);
    return 1.0f - __fdividef(2.0f, t + 1.0f);
}

#define LDSM4(R0, R1, R2, R3, ADDR) \
    asm volatile("ldmatrix.sync.aligned.m8n8.x4.shared.b16 {%0,%1,%2,%3}, [%4];" \
                 : "=r"(R0), "=r"(R1), "=r"(R2), "=r"(R3) : "r"(ADDR))

__device__ __forceinline__ void mma_bf16(float (&d)[4], const uint32_t (&a)[4],
                                         uint32_t b0, uint32_t b1) {
    asm volatile("mma.sync.aligned.m16n8k16.row.col.f32.bf16.bf16.f32 "
                 "{%0,%1,%2,%3}, {%4,%5,%6,%7}, {%8,%9}, {%0,%1,%2,%3};"
                 : "+f"(d[0]), "+f"(d[1]), "+f"(d[2]), "+f"(d[3])
                 : "r"(a[0]), "r"(a[1]), "r"(a[2]), "r"(a[3]), "r"(b0), "r"(b1));
}

__device__ __forceinline__ void zacc(float (&a)[2][2][4]) {
#pragma unroll
    for (int i = 0; i < 2; i++)
#pragma unroll
        for (int j = 0; j < 2; j++)
#pragma unroll
            for (int k = 0; k < 4; k++) a[i][j][k] = 0.f;
}

// One 32-col chunk: per-warp C[m32 x n16] += A_cat[128x256] * B_cat[32x256]^T
// 3-term bf16 split, k-outer / term-inner: per kstep load Ah,Al,Bh,Bl ONCE
// (6 LDSM4) and issue all 12 HMMAs: (Ah,Bh),(Al,Bh),(Ah,Bl).
__device__ __forceinline__ void mma_chunk32(uint32_t Abase, uint32_t Bbase,
                                            float (&acc)[2][2][4],
                                            int wm, int wn, int lane) {
    int rA = wm * 32 + (lane & 15);
    uint32_t PA = Abase + ((rA >> 3) << 10) + ((rA & 7) << 7);
    uint32_t CA = (rA & 7) << 4;
    int aK = (lane >> 4) << 3;
    int nB = wn * 16 + (((lane >> 4) & 1) << 3) + (lane & 7);
    uint32_t PB = Bbase + ((nB >> 3) << 10) + ((nB & 7) << 7);
    uint32_t CB = (nB & 7) << 4;
    int bK = ((lane >> 3) & 1) << 3;
#pragma unroll
    for (int s = 0; s < 8; s++) {
        int kA = (s << 4) + aK;          // hi: kA,  lo: kA+128
        int kB = (s << 4) + bK;
        uint32_t aAh = PA + ((uint32_t)(kA >> 6) << 14) + ((uint32_t)((kA & 63) << 1) ^ CA);
        uint32_t aAl = PA + ((uint32_t)((kA + 128) >> 6) << 14) + ((uint32_t)((kA & 63) << 1) ^ CA);
        uint32_t aBh = PB + ((uint32_t)(kB >> 6) << 12) + ((uint32_t)((kB & 63) << 1) ^ CB);
        uint32_t aBl = PB + ((uint32_t)((kB + 128) >> 6) << 12) + ((uint32_t)((kB & 63) << 1) ^ CB);
        uint32_t ah0[4], ah1[4], al0[4], al1[4], bh[4], bl[4];
        LDSM4(ah0[0], ah0[1], ah0[2], ah0[3], aAh);
        LDSM4(ah1[0], ah1[1], ah1[2], ah1[3], aAh + 2048);
        LDSM4(al0[0], al0[1], al0[2], al0[3], aAl);
        LDSM4(al1[0], al1[1], al1[2], al1[3], aAl + 2048);
        LDSM4(bh[0], bh[1], bh[2], bh[3], aBh);
        LDSM4(bl[0], bl[1], bl[2], bl[3], aBl);
        // term0: Ah*Bh
        mma_bf16(acc[0][0], ah0, bh[0], bh[1]);
        mma_bf16(acc[1][0], ah1, bh[0], bh[1]);
        mma_bf16(acc[0][1], ah0, bh[2], bh[3]);
        mma_bf16(acc[1][1], ah1, bh[2], bh[3]);
        // term1: Al*Bh
        mma_bf16(acc[0][0], al0, bh[0], bh[1]);
        mma_bf16(acc[1][0], al1, bh[0], bh[1]);
        mma_bf16(acc[0][1], al0, bh[2], bh[3]);
        mma_bf16(acc[1][1], al1, bh[2], bh[3]);
        // term2: Ah*Bl
        mma_bf16(acc[0][0], ah0, bl[0], bl[1]);
        mma_bf16(acc[1][0], ah1, bl[0], bl[1]);
        mma_bf16(acc[0][1], ah0, bl[2], bl[3]);
        mma_bf16(acc[1][1], ah1, bl[2], bl[3]);
    }
}

// ---------------------------------------------------------------------------
// cp.async: one 16KB chunk, 256 threads x 4 x 16B, one commit group
// ---------------------------------------------------------------------------
__device__ __forceinline__ void cp_chunk(uint32_t dst, const uint4* src, int t) {
    const char* s = (const char*)src;
#pragma unroll
    for (int i = 0; i < 4; i++)
        asm volatile("cp.async.cg.shared.global [%0], [%1], 16;"
                     :: "r"(dst + (uint32_t)(t * 16 + i * 4096)),
                        "l"(s + t * 16 + i * 4096) : "memory");
    asm volatile("cp.async.commit_group;" ::: "memory");
}
#define CP_WAIT1() asm volatile("cp.async.wait_group 1;" ::: "memory")
#define CP_WAIT0() asm volatile("cp.async.wait_group 0;" ::: "memory")

// ---------------------------------------------------------------------------
// Weight prep: split fp32 src[128][ncols] into bf16 hi/lo, swizzle into blobs
// ---------------------------------------------------------------------------
__global__ void prep_kernel(const float* __restrict__ src, int ncols, int dst_id, int chunkoff) {
    int idx = blockIdx.x * blockDim.x + threadIdx.x;
    if (idx >= 128 * ncols) return;
    int k = idx / ncols, n = idx - k * ncols;
    float v = src[k * ncols + n];
    unsigned short hu = f2bfu(v);
    unsigned short lu = f2bfu(v - bfu2f(hu));
    unsigned char* bb = (dst_id == 0) ? (unsigned char*)g_Wiou_sw
                      : (dst_id == 1) ? (unsigned char*)g_U_sw
                                      : (unsigned char*)g_Wout_sw;
    unsigned char* blob = bb + (size_t)(chunkoff + (n >> 5)) * CHUNK_BYTES;
    int row = n & 31;
    *(unsigned short*)(blob + offB32(row, k))       = hu;
    *(unsigned short*)(blob + offB32(row, 128 + k)) = lu;
}

// ---------------------------------------------------------------------------
// SMEM layout (dynamic, 1024-aligned):
//   A tile [0, 65536)          128 x 256 kcat bf16, SW128 blocked (x, later h)
//   B ring [65536, 114688)     3 x 16KB cp.async chunk buffers
//   LN part: reuse [65536,..)  out kernel only, after MMAs drain
// ---------------------------------------------------------------------------
#define SM_B    65536
#define SM_TOT  114688

// build a 128x[hi|lo] split tile from fp32 rows (src row-major, HH cols)
__device__ __forceinline__ void build_tile(char* Ac, const float* src, size_t base,
                                           int n_rows, int t) {
    int row = t >> 1, kh = (t & 1) << 6;
    bool val = row < n_rows;
    const float4* xr = (const float4*)(src + (base + row) * HH + kh);
#pragma unroll
    for (int gg = 0; gg < 8; gg++) {
        float v[8];
        if (val) {
            float4 a = xr[gg * 2], b = xr[gg * 2 + 1];
            v[0]=a.x; v[1]=a.y; v[2]=a.z; v[3]=a.w; v[4]=b.x; v[5]=b.y; v[6]=b.z; v[7]=b.w;
        } else {
#pragma unroll
            for (int q = 0; q < 8; q++) v[q] = 0.f;
        }
        uint32_t hi[4], lo[4];
#pragma unroll
        for (int q = 0; q < 4; q++) split2(v[2*q], v[2*q+1], hi[q], lo[q]);
        int kc = kh + gg * 8;
        *(uint4*)(Ac + offA(row, kc))       = make_uint4(hi[0], hi[1], hi[2], hi[3]);
        *(uint4*)(Ac + offA(row, 128 + kc)) = make_uint4(lo[0], lo[1], lo[2], lo[3]);
    }
}

// blob source for sequence slot in the level kernel (0..11 GEMM1, 12..27 GEMM2)
__device__ __forceinline__ const uint4* lvl_src(int seq) {
    if (seq < 12) {
        int p = seq / 3, sub = seq - p * 3;          // blob chunk = sub*4 + p
        return g_Wiou_sw + (size_t)(sub * 4 + p) * CHUNK_U4;
    }
    return g_U_sw + (size_t)(seq - 12) * CHUNK_U4;
}

// ---------------------------------------------------------------------------
// Fused per-level kernel: one CTA per 128-row tile, 256 threads, 2 CTAs/SM
// ---------------------------------------------------------------------------
__global__ __launch_bounds__(256, 2)
void level_mm(const float* __restrict__ x, const float* __restrict__ b_iou,
              int base0, int n_total, int read_sums, int has_parent) {
    extern __shared__ __align__(1024) char smem[];
    uint32_t sb = smem_to_u32(smem);
    int t = threadIdx.x, lane = t & 31, w = t >> 5;
    int wm = w & 3, wn = w >> 2;
    int q = lane & 3, g = lane >> 2;
    int base = base0 + ((int)blockIdx.x << 7);
    int n_rows = n_total - ((int)blockIdx.x << 7); if (n_rows > 128) n_rows = 128;
    const int NSEQ = has_parent ? 28 : 12;

    // prologue: 2 chunks in flight before building A
    cp_chunk(sb + SM_B, lvl_src(0), t);
    cp_chunk(sb + SM_B + CHUNK_BYTES, lvl_src(1), t);

    build_tile(smem, x, (size_t)base, n_rows, t);

    float accI[2][2][4], accO[2][2][4], accU[2][2][4];
    zacc(accI); zacc(accO); zacc(accU);

    for (int seq = 0; seq < NSEQ; seq++) {
        if (seq + 1 < NSEQ) { CP_WAIT1(); } else { CP_WAIT0(); }
        __syncthreads();                 // chunk seq visible; mma(seq-1) drained
        if (seq + 2 < NSEQ)
            cp_chunk(sb + SM_B + (uint32_t)((seq + 2) % 3) * CHUNK_BYTES,
                     lvl_src(seq + 2), t);
        uint32_t Bb = sb + SM_B + (uint32_t)(seq % 3) * CHUNK_BYTES;

        if (seq < 12) {
            int p = seq / 3, sub = seq - p * 3;
            if (sub == 0)      mma_chunk32(sb, Bb, accI, wm, wn, lane);
            else if (sub == 1) mma_chunk32(sb, Bb, accO, wm, wn, lane);
            else               mma_chunk32(sb, Bb, accU, wm, wn, lane);
            if (sub == 2) {
                // epilogue1 for pass p: gates -> c,h (global)
#pragma unroll
                for (int mi = 0; mi < 2; mi++)
#pragma unroll
                for (int nn = 0; nn < 2; nn++) {
                    int cp = p * 32 + wn * 16 + nn * 8 + 2 * q;
                    float bi0 = __ldg(b_iou + cp),       bi1 = __ldg(b_iou + cp + 1);
                    float bo0 = __ldg(b_iou + 128 + cp), bo1 = __ldg(b_iou + 129 + cp);
                    float bu0 = __ldg(b_iou + 256 + cp), bu1 = __ldg(b_iou + 257 + cp);
#pragma unroll
                    for (int rh = 0; rh < 2; rh++) {
                        int lr = wm * 32 + mi * 16 + g + rh * 8;
                        int rg = base + lr;
                        bool val = lr < n_rows;
                        float2 ui = make_float2(0.f, 0.f), uo = ui, uu = ui, fc = ui;
                        if (val && read_sums) {
                            const float* uh = g_uh + (size_t)rg * NIOU + cp;
                            ui = *(const float2*)(uh);
                            uo = *(const float2*)(uh + 128);
                            uu = *(const float2*)(uh + 256);
                            fc = *(const float2*)(g_fc + (size_t)rg * HH + cp);
                        }
                        float c0 = sigf(accI[mi][nn][rh*2]   + bi0 + ui.x) *
                                   tanh_fast(accU[mi][nn][rh*2]   + bu0 + uu.x) + fc.x;
                        float c1 = sigf(accI[mi][nn][rh*2+1] + bi1 + ui.y) *
                                   tanh_fast(accU[mi][nn][rh*2+1] + bu1 + uu.y) + fc.y;
                        float h0 = sigf(accO[mi][nn][rh*2]   + bo0 + uo.x) * tanh_fast(c0);
                        float h1 = sigf(accO[mi][nn][rh*2+1] + bo1 + uo.y) * tanh_fast(c1);
                        if (val) {
                            *(float2*)(g_c + (size_t)rg * HH + cp) = make_float2(c0, c1);
                            *(float2*)(g_h + (size_t)rg * HH + cp) = make_float2(h0, h1);
                        }
                    }
                }
                zacc(accI); zacc(accO); zacc(accU);
                if (seq == 11 && has_parent) {
                    // rebuild A as h-split; barrier at seq=12 publishes it
                    __syncthreads();            // all warps done reading A (GEMM1)
                    build_tile(smem, g_h, (size_t)base, n_rows, t);
                }
            }
        } else {
            // GEMM2 chunk ch: g = h @ [U_iou | U_f] cols [ch*32, ch*32+32)
            int ch = seq - 12;
            mma_chunk32(sb, Bb, accI, wm, wn, lane);   // reuse accI as accG
#pragma unroll
            for (int mi = 0; mi < 2; mi++)
#pragma unroll
            for (int nn = 0; nn < 2; nn++) {
                int cb = ch * 32 + wn * 16 + nn * 8 + 2 * q;
                float v[4];
                if (ch < 12) {
#pragma unroll
                    for (int r = 0; r < 4; r++) v[r] = accI[mi][nn][r];
                } else {
                    int cfl = cb - 384;
#pragma unroll
                    for (int rh = 0; rh < 2; rh++) {
                        int lr = wm * 32 + mi * 16 + g + rh * 8;
                        int rg = base + lr;
                        if (lr < n_rows) {
                            int pr = (rg - 1) >> 3;
                            float2 xf2 = *(const float2*)(g_xf + (size_t)pr * HH + cfl);
                            float2 c2  = *(const float2*)(g_c  + (size_t)rg * HH + cfl);
                            v[rh*2]   = sigf(accI[mi][nn][rh*2]   + xf2.x) * c2.x;
                            v[rh*2+1] = sigf(accI[mi][nn][rh*2+1] + xf2.y) * c2.y;
                        } else { v[rh*2] = 0.f; v[rh*2+1] = 0.f; }
                    }
                }
#pragma unroll
                for (int r = 0; r < 4; r++) {
                    float s = v[r];
                    s += __shfl_xor_sync(0xffffffffu, s, 4);
                    s += __shfl_xor_sync(0xffffffffu, s, 8);
                    s += __shfl_xor_sync(0xffffffffu, s, 16);
                    v[r] = s;
                }
                if (lane < 4) {
#pragma unroll
                    for (int rh = 0; rh < 2; rh++) {
                        int lr0 = wm * 32 + mi * 16 + rh * 8;
                        if (lr0 < n_rows) {
                            int pr = (base + lr0 - 1) >> 3;
                            if (ch < 12)
                                *(float2*)(g_uh + (size_t)pr * NIOU + cb) =
                                    make_float2(v[rh*2], v[rh*2+1]);
                            else
                                *(float2*)(g_fc + (size_t)pr * HH + (cb - 384)) =
                                    make_float2(v[rh*2], v[rh*2+1]);
                        }
                    }
                }
            }
            zacc(accI);
        }
    }
}

// ---------------------------------------------------------------------------
// Output kernel: out = tanh(LN(h @ W_out + b_out) * gamma + beta)
// ---------------------------------------------------------------------------
__global__ __launch_bounds__(256, 1)
void out_mm(const float* __restrict__ b_out, const float* __restrict__ gamma,
            const float* __restrict__ beta, float* __restrict__ out) {
    extern __shared__ __align__(1024) char smem[];
    uint32_t sb = smem_to_u32(smem);
    int t = threadIdx.x, lane = t & 31, w = t >> 5;
    int wm = w & 3, wn = w >> 2;
    int q = lane & 3, g = lane >> 2;
    int base = (int)blockIdx.x << 7;
    int n_rows = NN - base; if (n_rows > 128) n_rows = 128;

    cp_chunk(sb + SM_B, (const uint4*)g_Wout_sw, t);
    cp_chunk(sb + SM_B + CHUNK_BYTES, g_Wout_sw + CHUNK_U4, t);

    build_tile(smem, g_h, (size_t)base, n_rows, t);

    float acc8[8][2][2][4];
    for (int seq = 0; seq < 8; seq++) {
        if (seq + 1 < 8) { CP_WAIT1(); } else { CP_WAIT0(); }
        __syncthreads();
        if (seq + 2 < 8)
            cp_chunk(sb + SM_B + (uint32_t)((seq + 2) % 3) * CHUNK_BYTES,
                     g_Wout_sw + (size_t)(seq + 2) * CHUNK_U4, t);
        zacc(acc8[seq]);
        mma_chunk32(sb, sb + SM_B + (uint32_t)(seq % 3) * CHUNK_BYTES,
                    acc8[seq], wm, wn, lane);
    }

    // bias + per-row partial sums
    float s[2][2] = {{0.f,0.f},{0.f,0.f}}, sq[2][2] = {{0.f,0.f},{0.f,0.f}};
#pragma unroll
    for (int ch = 0; ch < 8; ch++)
#pragma unroll
    for (int nn = 0; nn < 2; nn++) {
        int cb = ch * 32 + wn * 16 + nn * 8 + 2 * q;
        float b0 = __ldg(b_out + cb), b1 = __ldg(b_out + cb + 1);
#pragma unroll
        for (int mi = 0; mi < 2; mi++)
#pragma unroll
        for (int rh = 0; rh < 2; rh++) {
            float y0 = (acc8[ch][mi][nn][rh*2]   += b0);
            float y1 = (acc8[ch][mi][nn][rh*2+1] += b1);
            s[mi][rh]  += y0 + y1;
            sq[mi][rh] += y0 * y0 + y1 * y1;
        }
    }
#pragma unroll
    for (int mi = 0; mi < 2; mi++)
#pragma unroll
    for (int rh = 0; rh < 2; rh++) {
        s[mi][rh]  += __shfl_xor_sync(0xffffffffu, s[mi][rh], 1);
        s[mi][rh]  += __shfl_xor_sync(0xffffffffu, s[mi][rh], 2);
        sq[mi][rh] += __shfl_xor_sync(0xffffffffu, sq[mi][rh], 1);
        sq[mi][rh] += __shfl_xor_sync(0xffffffffu, sq[mi][rh], 2);
    }
    float2* part = (float2*)(smem + SM_B);   // B ring idle after MMAs drain
    __syncthreads();
    if (q == 0) {
#pragma unroll
        for (int mi = 0; mi < 2; mi++)
#pragma unroll
        for (int rh = 0; rh < 2; rh++) {
            int lr = wm * 32 + mi * 16 + g + rh * 8;
            part[lr * 2 + wn] = make_float2(s[mi][rh], sq[mi][rh]);
        }
    }
    __syncthreads();
    float mu[2][2], rs[2][2];
#pragma unroll
    for (int mi = 0; mi < 2; mi++)
#pragma unroll
    for (int rh = 0; rh < 2; rh++) {
        int lr = wm * 32 + mi * 16 + g + rh * 8;
        float2 a = part[lr * 2], b = part[lr * 2 + 1];
        float m = (a.x + b.x) * (1.f / 256.f);
        float var = (a.y + b.y) * (1.f / 256.f) - m * m;
        mu[mi][rh] = m;
        rs[mi][rh] = rsqrtf(var + 1e-5f);
    }
#pragma unroll
    for (int ch = 0; ch < 8; ch++)
#pragma unroll
    for (int nn = 0; nn < 2; nn++) {
        int cb = ch * 32 + wn * 16 + nn * 8 + 2 * q;
        float g0 = __ldg(gamma + cb), g1 = __ldg(gamma + cb + 1);
        float e0 = __ldg(beta + cb),  e1 = __ldg(beta + cb + 1);
#pragma unroll
        for (int mi = 0; mi < 2; mi++)
#pragma unroll
        for (int rh = 0; rh < 2; rh++) {
            int lr = wm * 32 + mi * 16 + g + rh * 8;
            if (lr < n_rows) {
                float y0 = (acc8[ch][mi][nn][rh*2]   - mu[mi][rh]) * rs[mi][rh] * g0 + e0;
                float y1 = (acc8[ch][mi][nn][rh*2+1] - mu[mi][rh]) * rs[mi][rh] * g1 + e1;
                *(float2*)(out + (size_t)(base + lr) * DDEC + cb) =
                    make_float2(tanh_fast(y0), tanh_fast(y1));
            }
        }
    }
}

// ---------------------------------------------------------------------------
// x_f precompute (FFMA, small): g_xf[r] = x[r] @ W_f + b_f  for r < NPAR
// ---------------------------------------------------------------------------
#define TS 68
__global__ void xf_kernel(const float* __restrict__ x, const float* __restrict__ W_f,
                          const float* __restrict__ b_f) {
    extern __shared__ float sm[];
    float* As = sm;
    float* Ws = sm + 128 * TS;
    int t = threadIdx.x;
    int base = blockIdx.x << 6;
    int n_rows = NPAR - base; if (n_rows > 64) n_rows = 64;
    int m0 = (t & 15) * 4, c0 = (t >> 4) * 4;

#pragma unroll
    for (int i = 0; i < 32; i++) {
        int idx = t + 256 * i;
        int m = idx >> 7, k = idx & 127;
        float v = 0.f;
        if (m < n_rows) v = x[(size_t)(base + m) * HH + k];
        As[k * TS + m] = v;
    }
    for (int ch = 0; ch < 2; ch++) {
        __syncthreads();
#pragma unroll
        for (int i = 0; i < 32; i++) {
            int idx = t + 256 * i;
            int k = idx >> 6, c = idx & 63;
            Ws[k * TS + c] = W_f[k * HH + ch * 64 + c];
        }
        __syncthreads();
        float acc[4][4] = {};
#pragma unroll 8
        for (int k = 0; k < 128; k++) {
            float4 a = *(const float4*)(As + k * TS + m0);
            float4 b = *(const float4*)(Ws + k * TS + c0);
            acc[0][0] += a.x*b.x; acc[0][1] += a.x*b.y; acc[0][2] += a.x*b.z; acc[0][3] += a.x*b.w;
            acc[1][0] += a.y*b.x; acc[1][1] += a.y*b.y; acc[1][2] += a.y*b.z; acc[1][3] += a.y*b.w;
            acc[2][0] += a.z*b.x; acc[2][1] += a.z*b.y; acc[2][2] += a.z*b.z; acc[2][3] += a.z*b.w;
            acc[3][0] += a.w*b.x; acc[3][1] += a.w*b.y; acc[3][2] += a.w*b.z; acc[3][3] += a.w*b.w;
        }
#pragma unroll
        for (int i = 0; i < 4; i++)
#pragma unroll
            for (int j = 0; j < 4; j++) {
                int m = m0 + i, cc = ch * 64 + c0 + j;
                if (m < n_rows)
                    g_xf[(size_t)(base + m) * HH + cc] = acc[i][j] + b_f[cc];
            }
    }
}

// ---------------------------------------------------------------------------
extern "C" void kernel_launch(void* const* d_in, const int* in_sizes, int n_in,
                              void* d_out, int out_size) {
    const float* x = (const float*)d_in[0];
    int wi = 3;
    if (n_in > 3 && in_sizes[3] <= 1) wi = 4;
    const float* W_iou = (const float*)d_in[wi + 0];
    const float* b_iou = (const float*)d_in[wi + 1];
    const float* U_iou = (const float*)d_in[wi + 2];
    const float* W_f   = (const float*)d_in[wi + 3];
    const float* b_f   = (const float*)d_in[wi + 4];
    const float* U_f   = (const float*)d_in[wi + 5];
    const float* W_out = (const float*)d_in[wi + 6];
    const float* b_out = (const float*)d_in[wi + 7];
    const float* gamma = (const float*)d_in[wi + 8];
    const float* beta  = (const float*)d_in[wi + 9];
    float* out = (float*)d_out;

    cudaFuncSetAttribute(level_mm, cudaFuncAttributeMaxDynamicSharedMemorySize, SM_TOT);
    cudaFuncSetAttribute(out_mm,   cudaFuncAttributeMaxDynamicSharedMemorySize, SM_TOT);
    cudaFuncSetAttribute(xf_kernel, cudaFuncAttributeMaxDynamicSharedMemorySize,
                         (2 * 128 * TS) * (int)sizeof(float));

    // weight prep (split + swizzle into 32-col chunks)
    prep_kernel<<<192, 256>>>(W_iou, 384, 0, 0);
    prep_kernel<<<192, 256>>>(U_iou, 384, 1, 0);
    prep_kernel<<< 64, 256>>>(U_f,   128, 1, 12);
    prep_kernel<<<128, 256>>>(W_out, 256, 2, 0);

    xf_kernel<<<(NPAR + 63) / 64, 256, (2 * 128 * TS) * sizeof(float)>>>(x, W_f, b_f);

    const int off[8] = {0, 1, 9, 73, 585, 4681, 37449, 299593};
    for (int l = 6; l >= 0; l--) {
        int base = off[l], n = off[l + 1] - off[l];
        int blocks = (n + 127) / 128;
        level_mm<<<blocks, 256, SM_TOT>>>(x, b_iou, base, n,
                                          (l < 6) ? 1 : 0, (l > 0) ? 1 : 0);
    }
    out_mm<<<(NN + 127) / 128, 256, SM_TOT>>>(b_out, gamma, beta, out);
}

// round 11
// speedup vs baseline: 3.6391x; 1.1261x over previous
#include <cuda_runtime.h>
#include <cuda_fp16.h>
#include <math.h>
#include <stdint.h>

// ---------------------------------------------------------------------------
// Problem constants
// ---------------------------------------------------------------------------
#define NN    299593      // total nodes, complete 8-ary tree, 7 levels
#define HH    128         // D_ENC == D_EMB
#define NIOU  384         // 3*H
#define DDEC  256
#define NPAR  37449       // nodes at levels 0..5 (all parents)

#define CHUNK_BYTES 8192  // one pre-swizzled B chunk: 32 N-rows x 128 K x fp16
#define CHUNK_U4    (CHUNK_BYTES / 16)

// Scratch (device globals: allocation-free per harness rules)
__device__ float g_h [(size_t)NN  * HH];
__device__ float g_c [(size_t)NN  * HH];
__device__ float g_xf[(size_t)NPAR * HH];
__device__ float g_uh[(size_t)NPAR * NIOU];
__device__ float g_fc[(size_t)NPAR * HH];

// Pre-swizzled fp16 weight blobs (single-rounded B), 32-row x 128-K chunks
__device__ uint4 g_Wiou_sw[12 * CHUNK_U4];
__device__ uint4 g_U_sw   [16 * CHUNK_U4];  // [U_iou(384) | U_f(128)] cols
__device__ uint4 g_Wout_sw[ 8 * CHUNK_U4];

// ---------------------------------------------------------------------------
// Helpers
// ---------------------------------------------------------------------------
__device__ __forceinline__ uint32_t smem_to_u32(const void* p) {
    uint32_t a;
    asm("{ .reg .u64 t; cvta.to.shared.u64 t, %1; cvt.u32.u64 %0, t; }" : "=r"(a) : "l"(p));
    return a;
}
__device__ __forceinline__ uint32_t swz(uint32_t o) { return o ^ ((o >> 3) & 0x70); }
__device__ __forceinline__ uint32_t offA(int row, int k) {  // 128-row tile: 16 atoms/kblk
    return swz((uint32_t)(((row >> 3) + (k >> 6) * 16) * 1024 + (row & 7) * 128 + (k & 63) * 2));
}
__device__ __forceinline__ uint32_t offB32(int row, int k) { // 32-row tile: 4 atoms/kblk
    return swz((uint32_t)(((row >> 3) + (k >> 6) * 4) * 1024 + (row & 7) * 128 + (k & 63) * 2));
}
// fp16 split: hi = rn(v), lo = rn(v - hi); pack pairs
__device__ __forceinline__ void split2(float a, float b, uint32_t& hi, uint32_t& lo) {
    __half ha = __float2half_rn(a), hb = __float2half_rn(b);
    __half la = __float2half_rn(a - __half2float(ha));
    __half lb = __float2half_rn(b - __half2float(hb));
    hi = (uint32_t)__half_as_ushort(ha) | ((uint32_t)__half_as_ushort(hb) << 16);
    lo = (uint32_t)__half_as_ushort(la) | ((uint32_t)__half_as_ushort(lb) << 16);
}
__device__ __forceinline__ float sigf(float v) {
    return __fdividef(1.0f, 1.0f + __expf(-v));
}
__device__ __forceinline__ float tanh_fast(float x) {
    float t = __expf(2.0f * x);
    return 1.0f - __fdividef(2.0f, t + 1.0f);
}

#define LDSM4(R0, R1, R2, R3, ADDR) \
    asm volatile("ldmatrix.sync.aligned.m8n8.x4.shared.b16 {%0,%1,%2,%3}, [%4];" \
                 : "=r"(R0), "=r"(R1), "=r"(R2), "=r"(R3) : "r"(ADDR))

__device__ __forceinline__ void mma_f16(float (&d)[4], const uint32_t (&a)[4],
                                        uint32_t b0, uint32_t b1) {
    asm volatile("mma.sync.aligned.m16n8k16.row.col.f32.f16.f16.f32 "
                 "{%0,%1,%2,%3}, {%4,%5,%6,%7}, {%8,%9}, {%0,%1,%2,%3};"
                 : "+f"(d[0]), "+f"(d[1]), "+f"(d[2]), "+f"(d[3])
                 : "r"(a[0]), "r"(a[1]), "r"(a[2]), "r"(a[3]), "r"(b0), "r"(b1));
}

__device__ __forceinline__ void zacc(float (&a)[2][2][4]) {
#pragma unroll
    for (int i = 0; i < 2; i++)
#pragma unroll
        for (int j = 0; j < 2; j++)
#pragma unroll
            for (int k = 0; k < 4; k++) a[i][j][k] = 0.f;
}

// One 32-col chunk: per-warp C[m32 x n16] += A[128x128] * B[32x128]^T
// fp16 2-term split (A = Ah + Al, B single-rounded): per kstep load
// Ah(2), Al(2), Bh(1) LDSM4 and issue 8 HMMAs: (Ah,Bh),(Al,Bh).
__device__ __forceinline__ void mma_chunk32(uint32_t Abase, uint32_t Bbase,
                                            float (&acc)[2][2][4],
                                            int wm, int wn, int lane) {
    int rA = wm * 32 + (lane & 15);
    uint32_t PA = Abase + ((rA >> 3) << 10) + ((rA & 7) << 7);
    uint32_t CA = (rA & 7) << 4;
    int aK = (lane >> 4) << 3;
    int nB = wn * 16 + (((lane >> 4) & 1) << 3) + (lane & 7);
    uint32_t PB = Bbase + ((nB >> 3) << 10) + ((nB & 7) << 7);
    uint32_t CB = (nB & 7) << 4;
    int bK = ((lane >> 3) & 1) << 3;
#pragma unroll
    for (int s = 0; s < 8; s++) {
        int kA = (s << 4) + aK;          // hi: kA,  lo: kA+128 (A tile kcat=256)
        int kB = (s << 4) + bK;          // B tile K=128
        uint32_t aAh = PA + ((uint32_t)(kA >> 6) << 14) + ((uint32_t)((kA & 63) << 1) ^ CA);
        uint32_t aAl = PA + ((uint32_t)((kA + 128) >> 6) << 14) + ((uint32_t)((kA & 63) << 1) ^ CA);
        uint32_t aBh = PB + ((uint32_t)(kB >> 6) << 12) + ((uint32_t)((kB & 63) << 1) ^ CB);
        uint32_t ah0[4], ah1[4], al0[4], al1[4], bh[4];
        LDSM4(ah0[0], ah0[1], ah0[2], ah0[3], aAh);
        LDSM4(ah1[0], ah1[1], ah1[2], ah1[3], aAh + 2048);
        LDSM4(al0[0], al0[1], al0[2], al0[3], aAl);
        LDSM4(al1[0], al1[1], al1[2], al1[3], aAl + 2048);
        LDSM4(bh[0], bh[1], bh[2], bh[3], aBh);
        // term0: Ah*Bh
        mma_f16(acc[0][0], ah0, bh[0], bh[1]);
        mma_f16(acc[1][0], ah1, bh[0], bh[1]);
        mma_f16(acc[0][1], ah0, bh[2], bh[3]);
        mma_f16(acc[1][1], ah1, bh[2], bh[3]);
        // term1: Al*Bh
        mma_f16(acc[0][0], al0, bh[0], bh[1]);
        mma_f16(acc[1][0], al1, bh[0], bh[1]);
        mma_f16(acc[0][1], al0, bh[2], bh[3]);
        mma_f16(acc[1][1], al1, bh[2], bh[3]);
    }
}

// ---------------------------------------------------------------------------
// cp.async: one 8KB chunk, 256 threads x 2 x 16B, one commit group
// ---------------------------------------------------------------------------
__device__ __forceinline__ void cp_chunk(uint32_t dst, const uint4* src, int t) {
    const char* s = (const char*)src;
#pragma unroll
    for (int i = 0; i < 2; i++)
        asm volatile("cp.async.cg.shared.global [%0], [%1], 16;"
                     :: "r"(dst + (uint32_t)(t * 16 + i * 4096)),
                        "l"(s + t * 16 + i * 4096) : "memory");
    asm volatile("cp.async.commit_group;" ::: "memory");
}
#define CP_WAIT1() asm volatile("cp.async.wait_group 1;" ::: "memory")
#define CP_WAIT0() asm volatile("cp.async.wait_group 0;" ::: "memory")

// ---------------------------------------------------------------------------
// Weight prep: round fp32 src[128][ncols] to fp16, swizzle into blobs
// ---------------------------------------------------------------------------
__global__ void prep_kernel(const float* __restrict__ src, int ncols, int dst_id, int chunkoff) {
    int idx = blockIdx.x * blockDim.x + threadIdx.x;
    if (idx >= 128 * ncols) return;
    int k = idx / ncols, n = idx - k * ncols;
    float v = src[k * ncols + n];
    unsigned short hu = __half_as_ushort(__float2half_rn(v));
    unsigned char* bb = (dst_id == 0) ? (unsigned char*)g_Wiou_sw
                      : (dst_id == 1) ? (unsigned char*)g_U_sw
                                      : (unsigned char*)g_Wout_sw;
    unsigned char* blob = bb + (size_t)(chunkoff + (n >> 5)) * CHUNK_BYTES;
    int row = n & 31;
    *(unsigned short*)(blob + offB32(row, k)) = hu;
}

// ---------------------------------------------------------------------------
// SMEM layout (dynamic, 1024-aligned):
//   A tile [0, 65536)          128 x 256 kcat fp16 [hi|lo], SW128 blocked
//   B ring [65536, 90112)      3 x 8KB cp.async chunk buffers
//   LN part: reuse [65536,..)  out kernel only, after MMAs drain
// ---------------------------------------------------------------------------
#define SM_B    65536
#define SM_TOT  90112

// build a 128x[hi|lo] split tile from fp32 rows (src row-major, HH cols)
__device__ __forceinline__ void build_tile(char* Ac, const float* src, size_t base,
                                           int n_rows, int t) {
    int row = t >> 1, kh = (t & 1) << 6;
    bool val = row < n_rows;
    const float4* xr = (const float4*)(src + (base + row) * HH + kh);
#pragma unroll
    for (int gg = 0; gg < 8; gg++) {
        float v[8];
        if (val) {
            float4 a = xr[gg * 2], b = xr[gg * 2 + 1];
            v[0]=a.x; v[1]=a.y; v[2]=a.z; v[3]=a.w; v[4]=b.x; v[5]=b.y; v[6]=b.z; v[7]=b.w;
        } else {
#pragma unroll
            for (int q = 0; q < 8; q++) v[q] = 0.f;
        }
        uint32_t hi[4], lo[4];
#pragma unroll
        for (int q = 0; q < 4; q++) split2(v[2*q], v[2*q+1], hi[q], lo[q]);
        int kc = kh + gg * 8;
        *(uint4*)(Ac + offA(row, kc))       = make_uint4(hi[0], hi[1], hi[2], hi[3]);
        *(uint4*)(Ac + offA(row, 128 + kc)) = make_uint4(lo[0], lo[1], lo[2], lo[3]);
    }
}

// blob source for sequence slot in the level kernel (0..11 GEMM1, 12..27 GEMM2)
__device__ __forceinline__ const uint4* lvl_src(int seq) {
    if (seq < 12) {
        int p = seq / 3, sub = seq - p * 3;          // blob chunk = sub*4 + p
        return g_Wiou_sw + (size_t)(sub * 4 + p) * CHUNK_U4;
    }
    return g_U_sw + (size_t)(seq - 12) * CHUNK_U4;
}

// ---------------------------------------------------------------------------
// Fused per-level kernel: one CTA per 128-row tile, 256 threads, 2 CTAs/SM
// ---------------------------------------------------------------------------
__global__ __launch_bounds__(256, 2)
void level_mm(const float* __restrict__ x, const float* __restrict__ b_iou,
              int base0, int n_total, int read_sums, int has_parent) {
    extern __shared__ __align__(1024) char smem[];
    uint32_t sb = smem_to_u32(smem);
    int t = threadIdx.x, lane = t & 31, w = t >> 5;
    int wm = w & 3, wn = w >> 2;
    int q = lane & 3, g = lane >> 2;
    int base = base0 + ((int)blockIdx.x << 7);
    int n_rows = n_total - ((int)blockIdx.x << 7); if (n_rows > 128) n_rows = 128;
    const int NSEQ = has_parent ? 28 : 12;

    // prologue: 2 chunks in flight before building A
    cp_chunk(sb + SM_B, lvl_src(0), t);
    cp_chunk(sb + SM_B + CHUNK_BYTES, lvl_src(1), t);

    build_tile(smem, x, (size_t)base, n_rows, t);

    float accI[2][2][4], accO[2][2][4], accU[2][2][4];
    zacc(accI); zacc(accO); zacc(accU);

    for (int seq = 0; seq < NSEQ; seq++) {
        if (seq + 1 < NSEQ) { CP_WAIT1(); } else { CP_WAIT0(); }
        __syncthreads();                 // chunk seq visible; mma(seq-1) drained
        if (seq + 2 < NSEQ)
            cp_chunk(sb + SM_B + (uint32_t)((seq + 2) % 3) * CHUNK_BYTES,
                     lvl_src(seq + 2), t);
        uint32_t Bb = sb + SM_B + (uint32_t)(seq % 3) * CHUNK_BYTES;

        if (seq < 12) {
            int p = seq / 3, sub = seq - p * 3;
            if (sub == 0)      mma_chunk32(sb, Bb, accI, wm, wn, lane);
            else if (sub == 1) mma_chunk32(sb, Bb, accO, wm, wn, lane);
            else               mma_chunk32(sb, Bb, accU, wm, wn, lane);
            if (sub == 2) {
                // epilogue1 for pass p: gates -> c,h (global)
#pragma unroll
                for (int mi = 0; mi < 2; mi++)
#pragma unroll
                for (int nn = 0; nn < 2; nn++) {
                    int cp = p * 32 + wn * 16 + nn * 8 + 2 * q;
                    float bi0 = __ldg(b_iou + cp),       bi1 = __ldg(b_iou + cp + 1);
                    float bo0 = __ldg(b_iou + 128 + cp), bo1 = __ldg(b_iou + 129 + cp);
                    float bu0 = __ldg(b_iou + 256 + cp), bu1 = __ldg(b_iou + 257 + cp);
#pragma unroll
                    for (int rh = 0; rh < 2; rh++) {
                        int lr = wm * 32 + mi * 16 + g + rh * 8;
                        int rg = base + lr;
                        bool val = lr < n_rows;
                        float2 ui = make_float2(0.f, 0.f), uo = ui, uu = ui, fc = ui;
                        if (val && read_sums) {
                            const float* uh = g_uh + (size_t)rg * NIOU + cp;
                            ui = *(const float2*)(uh);
                            uo = *(const float2*)(uh + 128);
                            uu = *(const float2*)(uh + 256);
                            fc = *(const float2*)(g_fc + (size_t)rg * HH + cp);
                        }
                        float c0 = sigf(accI[mi][nn][rh*2]   + bi0 + ui.x) *
                                   tanh_fast(accU[mi][nn][rh*2]   + bu0 + uu.x) + fc.x;
                        float c1 = sigf(accI[mi][nn][rh*2+1] + bi1 + ui.y) *
                                   tanh_fast(accU[mi][nn][rh*2+1] + bu1 + uu.y) + fc.y;
                        float h0 = sigf(accO[mi][nn][rh*2]   + bo0 + uo.x) * tanh_fast(c0);
                        float h1 = sigf(accO[mi][nn][rh*2+1] + bo1 + uo.y) * tanh_fast(c1);
                        if (val) {
                            *(float2*)(g_c + (size_t)rg * HH + cp) = make_float2(c0, c1);
                            *(float2*)(g_h + (size_t)rg * HH + cp) = make_float2(h0, h1);
                        }
                    }
                }
                zacc(accI); zacc(accO); zacc(accU);
                if (seq == 11 && has_parent) {
                    // rebuild A as h-split; barrier at seq=12 publishes it
                    __syncthreads();            // all warps done reading A (GEMM1)
                    build_tile(smem, g_h, (size_t)base, n_rows, t);
                }
            }
        } else {
            // GEMM2 chunk ch: g = h @ [U_iou | U_f] cols [ch*32, ch*32+32)
            int ch = seq - 12;
            mma_chunk32(sb, Bb, accI, wm, wn, lane);   // reuse accI as accG
#pragma unroll
            for (int mi = 0; mi < 2; mi++)
#pragma unroll
            for (int nn = 0; nn < 2; nn++) {
                int cb = ch * 32 + wn * 16 + nn * 8 + 2 * q;
                float v[4];
                if (ch < 12) {
#pragma unroll
                    for (int r = 0; r < 4; r++) v[r] = accI[mi][nn][r];
                } else {
                    int cfl = cb - 384;
#pragma unroll
                    for (int rh = 0; rh < 2; rh++) {
                        int lr = wm * 32 + mi * 16 + g + rh * 8;
                        int rg = base + lr;
                        if (lr < n_rows) {
                            int pr = (rg - 1) >> 3;
                            float2 xf2 = *(const float2*)(g_xf + (size_t)pr * HH + cfl);
                            float2 c2  = *(const float2*)(g_c  + (size_t)rg * HH + cfl);
                            v[rh*2]   = sigf(accI[mi][nn][rh*2]   + xf2.x) * c2.x;
                            v[rh*2+1] = sigf(accI[mi][nn][rh*2+1] + xf2.y) * c2.y;
                        } else { v[rh*2] = 0.f; v[rh*2+1] = 0.f; }
                    }
                }
#pragma unroll
                for (int r = 0; r < 4; r++) {
                    float s = v[r];
                    s += __shfl_xor_sync(0xffffffffu, s, 4);
                    s += __shfl_xor_sync(0xffffffffu, s, 8);
                    s += __shfl_xor_sync(0xffffffffu, s, 16);
                    v[r] = s;
                }
                if (lane < 4) {
#pragma unroll
                    for (int rh = 0; rh < 2; rh++) {
                        int lr0 = wm * 32 + mi * 16 + rh * 8;
                        if (lr0 < n_rows) {
                            int pr = (base + lr0 - 1) >> 3;
                            if (ch < 12)
                                *(float2*)(g_uh + (size_t)pr * NIOU + cb) =
                                    make_float2(v[rh*2], v[rh*2+1]);
                            else
                                *(float2*)(g_fc + (size_t)pr * HH + (cb - 384)) =
                                    make_float2(v[rh*2], v[rh*2+1]);
                        }
                    }
                }
            }
            zacc(accI);
        }
    }
}

// ---------------------------------------------------------------------------
// Output kernel: out = tanh(LN(h @ W_out + b_out) * gamma + beta)
// ---------------------------------------------------------------------------
__global__ __launch_bounds__(256, 1)
void out_mm(const float* __restrict__ b_out, const float* __restrict__ gamma,
            const float* __restrict__ beta, float* __restrict__ out) {
    extern __shared__ __align__(1024) char smem[];
    uint32_t sb = smem_to_u32(smem);
    int t = threadIdx.x, lane = t & 31, w = t >> 5;
    int wm = w & 3, wn = w >> 2;
    int q = lane & 3, g = lane >> 2;
    int base = (int)blockIdx.x << 7;
    int n_rows = NN - base; if (n_rows > 128) n_rows = 128;

    cp_chunk(sb + SM_B, (const uint4*)g_Wout_sw, t);
    cp_chunk(sb + SM_B + CHUNK_BYTES, g_Wout_sw + CHUNK_U4, t);

    build_tile(smem, g_h, (size_t)base, n_rows, t);

    float acc8[8][2][2][4];
    for (int seq = 0; seq < 8; seq++) {
        if (seq + 1 < 8) { CP_WAIT1(); } else { CP_WAIT0(); }
        __syncthreads();
        if (seq + 2 < 8)
            cp_chunk(sb + SM_B + (uint32_t)((seq + 2) % 3) * CHUNK_BYTES,
                     g_Wout_sw + (size_t)(seq + 2) * CHUNK_U4, t);
        zacc(acc8[seq]);
        mma_chunk32(sb, sb + SM_B + (uint32_t)(seq % 3) * CHUNK_BYTES,
                    acc8[seq], wm, wn, lane);
    }

    // bias + per-row partial sums
    float s[2][2] = {{0.f,0.f},{0.f,0.f}}, sq[2][2] = {{0.f,0.f},{0.f,0.f}};
#pragma unroll
    for (int ch = 0; ch < 8; ch++)
#pragma unroll
    for (int nn = 0; nn < 2; nn++) {
        int cb = ch * 32 + wn * 16 + nn * 8 + 2 * q;
        float b0 = __ldg(b_out + cb), b1 = __ldg(b_out + cb + 1);
#pragma unroll
        for (int mi = 0; mi < 2; mi++)
#pragma unroll
        for (int rh = 0; rh < 2; rh++) {
            float y0 = (acc8[ch][mi][nn][rh*2]   += b0);
            float y1 = (acc8[ch][mi][nn][rh*2+1] += b1);
            s[mi][rh]  += y0 + y1;
            sq[mi][rh] += y0 * y0 + y1 * y1;
        }
    }
#pragma unroll
    for (int mi = 0; mi < 2; mi++)
#pragma unroll
    for (int rh = 0; rh < 2; rh++) {
        s[mi][rh]  += __shfl_xor_sync(0xffffffffu, s[mi][rh], 1);
        s[mi][rh]  += __shfl_xor_sync(0xffffffffu, s[mi][rh], 2);
        sq[mi][rh] += __shfl_xor_sync(0xffffffffu, sq[mi][rh], 1);
        sq[mi][rh] += __shfl_xor_sync(0xffffffffu, sq[mi][rh], 2);
    }
    float2* part = (float2*)(smem + SM_B);   // B ring idle after MMAs drain
    __syncthreads();
    if (q == 0) {
#pragma unroll
        for (int mi = 0; mi < 2; mi++)
#pragma unroll
        for (int rh = 0; rh < 2; rh++) {
            int lr = wm * 32 + mi * 16 + g + rh * 8;
            part[lr * 2 + wn] = make_float2(s[mi][rh], sq[mi][rh]);
        }
    }
    __syncthreads();
    float mu[2][2], rs[2][2];
#pragma unroll
    for (int mi = 0; mi < 2; mi++)
#pragma unroll
    for (int rh = 0; rh < 2; rh++) {
        int lr = wm * 32 + mi * 16 + g + rh * 8;
        float2 a = part[lr * 2], b = part[lr * 2 + 1];
        float m = (a.x + b.x) * (1.f / 256.f);
        float var = (a.y + b.y) * (1.f / 256.f) - m * m;
        mu[mi][rh] = m;
        rs[mi][rh] = rsqrtf(var + 1e-5f);
    }
#pragma unroll
    for (int ch = 0; ch < 8; ch++)
#pragma unroll
    for (int nn = 0; nn < 2; nn++) {
        int cb = ch * 32 + wn * 16 + nn * 8 + 2 * q;
        float g0 = __ldg(gamma + cb), g1 = __ldg(gamma + cb + 1);
        float e0 = __ldg(beta + cb),  e1 = __ldg(beta + cb + 1);
#pragma unroll
        for (int mi = 0; mi < 2; mi++)
#pragma unroll
        for (int rh = 0; rh < 2; rh++) {
            int lr = wm * 32 + mi * 16 + g + rh * 8;
            if (lr < n_rows) {
                float y0 = (acc8[ch][mi][nn][rh*2]   - mu[mi][rh]) * rs[mi][rh] * g0 + e0;
                float y1 = (acc8[ch][mi][nn][rh*2+1] - mu[mi][rh]) * rs[mi][rh] * g1 + e1;
                *(float2*)(out + (size_t)(base + lr) * DDEC + cb) =
                    make_float2(tanh_fast(y0), tanh_fast(y1));
            }
        }
    }
}

// ---------------------------------------------------------------------------
// x_f precompute (FFMA, small): g_xf[r] = x[r] @ W_f + b_f  for r < NPAR
// ---------------------------------------------------------------------------
#define TS 68
__global__ void xf_kernel(const float* __restrict__ x, const float* __restrict__ W_f,
                          const float* __restrict__ b_f) {
    extern __shared__ float sm[];
    float* As = sm;
    float* Ws = sm + 128 * TS;
    int t = threadIdx.x;
    int base = blockIdx.x << 6;
    int n_rows = NPAR - base; if (n_rows > 64) n_rows = 64;
    int m0 = (t & 15) * 4, c0 = (t >> 4) * 4;

#pragma unroll
    for (int i = 0; i < 32; i++) {
        int idx = t + 256 * i;
        int m = idx >> 7, k = idx & 127;
        float v = 0.f;
        if (m < n_rows) v = x[(size_t)(base + m) * HH + k];
        As[k * TS + m] = v;
    }
    for (int ch = 0; ch < 2; ch++) {
        __syncthreads();
#pragma unroll
        for (int i = 0; i < 32; i++) {
            int idx = t + 256 * i;
            int k = idx >> 6, c = idx & 63;
            Ws[k * TS + c] = W_f[k * HH + ch * 64 + c];
        }
        __syncthreads();
        float acc[4][4] = {};
#pragma unroll 8
        for (int k = 0; k < 128; k++) {
            float4 a = *(const float4*)(As + k * TS + m0);
            float4 b = *(const float4*)(Ws + k * TS + c0);
            acc[0][0] += a.x*b.x; acc[0][1] += a.x*b.y; acc[0][2] += a.x*b.z; acc[0][3] += a.x*b.w;
            acc[1][0] += a.y*b.x; acc[1][1] += a.y*b.y; acc[1][2] += a.y*b.z; acc[1][3] += a.y*b.w;
            acc[2][0] += a.z*b.x; acc[2][1] += a.z*b.y; acc[2][2] += a.z*b.z; acc[2][3] += a.z*b.w;
            acc[3][0] += a.w*b.x; acc[3][1] += a.w*b.y; acc[3][2] += a.w*b.z; acc[3][3] += a.w*b.w;
        }
#pragma unroll
        for (int i = 0; i < 4; i++)
#pragma unroll
            for (int j = 0; j < 4; j++) {
                int m = m0 + i, cc = ch * 64 + c0 + j;
                if (m < n_rows)
                    g_xf[(size_t)(base + m) * HH + cc] = acc[i][j] + b_f[cc];
            }
    }
}

// ---------------------------------------------------------------------------
extern "C" void kernel_launch(void* const* d_in, const int* in_sizes, int n_in,
                              void* d_out, int out_size) {
    const float* x = (const float*)d_in[0];
    int wi = 3;
    if (n_in > 3 && in_sizes[3] <= 1) wi = 4;
    const float* W_iou = (const float*)d_in[wi + 0];
    const float* b_iou = (const float*)d_in[wi + 1];
    const float* U_iou = (const float*)d_in[wi + 2];
    const float* W_f   = (const float*)d_in[wi + 3];
    const float* b_f   = (const float*)d_in[wi + 4];
    const float* U_f   = (const float*)d_in[wi + 5];
    const float* W_out = (const float*)d_in[wi + 6];
    const float* b_out = (const float*)d_in[wi + 7];
    const float* gamma = (const float*)d_in[wi + 8];
    const float* beta  = (const float*)d_in[wi + 9];
    float* out = (float*)d_out;

    cudaFuncSetAttribute(level_mm, cudaFuncAttributeMaxDynamicSharedMemorySize, SM_TOT);
    cudaFuncSetAttribute(out_mm,   cudaFuncAttributeMaxDynamicSharedMemorySize, SM_TOT);
    cudaFuncSetAttribute(xf_kernel, cudaFuncAttributeMaxDynamicSharedMemorySize,
                         (2 * 128 * TS) * (int)sizeof(float));

    // weight prep (fp16 round + swizzle into 32-col chunks)
    prep_kernel<<<192, 256>>>(W_iou, 384, 0, 0);
    prep_kernel<<<192, 256>>>(U_iou, 384, 1, 0);
    prep_kernel<<< 64, 256>>>(U_f,   128, 1, 12);
    prep_kernel<<<128, 256>>>(W_out, 256, 2, 0);

    xf_kernel<<<(NPAR + 63) / 64, 256, (2 * 128 * TS) * sizeof(float)>>>(x, W_f, b_f);

    const int off[8] = {0, 1, 9, 73, 585, 4681, 37449, 299593};
    for (int l = 6; l >= 0; l--) {
        int base = off[l], n = off[l + 1] - off[l];
        int blocks = (n + 127) / 128;
        level_mm<<<blocks, 256, SM_TOT>>>(x, b_iou, base, n,
                                          (l < 6) ? 1 : 0, (l > 0) ? 1 : 0);
    }
    out_mm<<<(NN + 127) / 128, 256, SM_TOT>>>(b_out, gamma, beta, out);
}

// round 12
// speedup vs baseline: 3.8639x; 1.0618x over previous
#include <cuda_runtime.h>
#include <cuda_fp16.h>
#include <math.h>
#include <stdint.h>

// ---------------------------------------------------------------------------
// Problem constants
// ---------------------------------------------------------------------------
#define NN    299593      // total nodes, complete 8-ary tree, 7 levels
#define HH    128         // D_ENC == D_EMB
#define NIOU  384         // 3*H
#define DDEC  256
#define NPAR  37449       // nodes at levels 0..5 (all parents)

#define CHUNK_BYTES 8192  // one pre-swizzled B chunk: 32 N-rows x 128 K x fp16
#define CHUNK_U4    (CHUNK_BYTES / 16)

// Scratch (device globals: allocation-free per harness rules)
__device__ float g_h [(size_t)NN  * HH];
__device__ float g_c [(size_t)NN  * HH];
__device__ float g_xf[(size_t)NPAR * HH];
__device__ float g_uh[(size_t)NPAR * NIOU];
__device__ float g_fc[(size_t)NPAR * HH];

// Pre-swizzled fp16 weight blobs (single-rounded B), 32-row x 128-K chunks
__device__ uint4 g_Wiou_sw[12 * CHUNK_U4];
__device__ uint4 g_U_sw   [16 * CHUNK_U4];  // [U_iou(384) | U_f(128)] cols
__device__ uint4 g_Wout_sw[ 8 * CHUNK_U4];

// ---------------------------------------------------------------------------
// Helpers
// ---------------------------------------------------------------------------
__device__ __forceinline__ uint32_t smem_to_u32(const void* p) {
    uint32_t a;
    asm("{ .reg .u64 t; cvta.to.shared.u64 t, %1; cvt.u32.u64 %0, t; }" : "=r"(a) : "l"(p));
    return a;
}
__device__ __forceinline__ uint32_t swz(uint32_t o) { return o ^ ((o >> 3) & 0x70); }
__device__ __forceinline__ uint32_t offA(int row, int k) {   // 128-row tile: 16 atoms/kblk
    return swz((uint32_t)(((row >> 3) + (k >> 6) * 16) * 1024 + (row & 7) * 128 + (k & 63) * 2));
}
__device__ __forceinline__ uint32_t offA16(int row, int k) { // 16-row tile: 2 atoms/kblk
    return swz((uint32_t)(((row >> 3) + (k >> 6) * 2) * 1024 + (row & 7) * 128 + (k & 63) * 2));
}
__device__ __forceinline__ uint32_t offB32(int row, int k) { // 32-row tile: 4 atoms/kblk
    return swz((uint32_t)(((row >> 3) + (k >> 6) * 4) * 1024 + (row & 7) * 128 + (k & 63) * 2));
}
// fp16 split: hi = rn(v), lo = rn(v - hi); pack pairs
__device__ __forceinline__ void split2(float a, float b, uint32_t& hi, uint32_t& lo) {
    __half ha = __float2half_rn(a), hb = __float2half_rn(b);
    __half la = __float2half_rn(a - __half2float(ha));
    __half lb = __float2half_rn(b - __half2float(hb));
    hi = (uint32_t)__half_as_ushort(ha) | ((uint32_t)__half_as_ushort(hb) << 16);
    lo = (uint32_t)__half_as_ushort(la) | ((uint32_t)__half_as_ushort(lb) << 16);
}
__device__ __forceinline__ float sigf(float v) {
    return __fdividef(1.0f, 1.0f + __expf(-v));
}
__device__ __forceinline__ float tanh_fast(float x) {
    float t = __expf(2.0f * x);
    return 1.0f - __fdividef(2.0f, t + 1.0f);
}

#define LDSM4(R0, R1, R2, R3, ADDR) \
    asm volatile("ldmatrix.sync.aligned.m8n8.x4.shared.b16 {%0,%1,%2,%3}, [%4];" \
                 : "=r"(R0), "=r"(R1), "=r"(R2), "=r"(R3) : "r"(ADDR))
#define LDSM2(R0, R1, ADDR) \
    asm volatile("ldmatrix.sync.aligned.m8n8.x2.shared.b16 {%0,%1}, [%2];" \
                 : "=r"(R0), "=r"(R1) : "r"(ADDR))

__device__ __forceinline__ void mma_f16(float (&d)[4], const uint32_t (&a)[4],
                                        uint32_t b0, uint32_t b1) {
    asm volatile("mma.sync.aligned.m16n8k16.row.col.f32.f16.f16.f32 "
                 "{%0,%1,%2,%3}, {%4,%5,%6,%7}, {%8,%9}, {%0,%1,%2,%3};"
                 : "+f"(d[0]), "+f"(d[1]), "+f"(d[2]), "+f"(d[3])
                 : "r"(a[0]), "r"(a[1]), "r"(a[2]), "r"(a[3]), "r"(b0), "r"(b1));
}

__device__ __forceinline__ void zacc(float (&a)[2][2][4]) {
#pragma unroll
    for (int i = 0; i < 2; i++)
#pragma unroll
        for (int j = 0; j < 2; j++)
#pragma unroll
            for (int k = 0; k < 4; k++) a[i][j][k] = 0.f;
}

// One 32-col chunk: per-warp C[m32 x n16] += A[128x128] * B[32x128]^T
// fp16 2-term split (A = Ah + Al, B single-rounded): per kstep load
// Ah(2), Al(2), Bh(1) LDSM4 and issue 8 HMMAs: (Ah,Bh),(Al,Bh).
__device__ __forceinline__ void mma_chunk32(uint32_t Abase, uint32_t Bbase,
                                            float (&acc)[2][2][4],
                                            int wm, int wn, int lane) {
    int rA = wm * 32 + (lane & 15);
    uint32_t PA = Abase + ((rA >> 3) << 10) + ((rA & 7) << 7);
    uint32_t CA = (rA & 7) << 4;
    int aK = (lane >> 4) << 3;
    int nB = wn * 16 + (((lane >> 4) & 1) << 3) + (lane & 7);
    uint32_t PB = Bbase + ((nB >> 3) << 10) + ((nB & 7) << 7);
    uint32_t CB = (nB & 7) << 4;
    int bK = ((lane >> 3) & 1) << 3;
#pragma unroll
    for (int s = 0; s < 8; s++) {
        int kA = (s << 4) + aK;          // hi: kA,  lo: kA+128 (A tile kcat=256)
        int kB = (s << 4) + bK;          // B tile K=128
        uint32_t aAh = PA + ((uint32_t)(kA >> 6) << 14) + ((uint32_t)((kA & 63) << 1) ^ CA);
        uint32_t aAl = PA + ((uint32_t)((kA + 128) >> 6) << 14) + ((uint32_t)((kA & 63) << 1) ^ CA);
        uint32_t aBh = PB + ((uint32_t)(kB >> 6) << 12) + ((uint32_t)((kB & 63) << 1) ^ CB);
        uint32_t ah0[4], ah1[4], al0[4], al1[4], bh[4];
        LDSM4(ah0[0], ah0[1], ah0[2], ah0[3], aAh);
        LDSM4(ah1[0], ah1[1], ah1[2], ah1[3], aAh + 2048);
        LDSM4(al0[0], al0[1], al0[2], al0[3], aAl);
        LDSM4(al1[0], al1[1], al1[2], al1[3], aAl + 2048);
        LDSM4(bh[0], bh[1], bh[2], bh[3], aBh);
        // term0: Ah*Bh
        mma_f16(acc[0][0], ah0, bh[0], bh[1]);
        mma_f16(acc[1][0], ah1, bh[0], bh[1]);
        mma_f16(acc[0][1], ah0, bh[2], bh[3]);
        mma_f16(acc[1][1], ah1, bh[2], bh[3]);
        // term1: Al*Bh
        mma_f16(acc[0][0], al0, bh[0], bh[1]);
        mma_f16(acc[1][0], al1, bh[0], bh[1]);
        mma_f16(acc[0][1], al0, bh[2], bh[3]);
        mma_f16(acc[1][1], al1, bh[2], bh[3]);
    }
}

// ---------------------------------------------------------------------------
// cp.async: one 8KB chunk, 256 threads x 2 x 16B, one commit group
// ---------------------------------------------------------------------------
__device__ __forceinline__ void cp_chunk(uint32_t dst, const uint4* src, int t) {
    const char* s = (const char*)src;
#pragma unroll
    for (int i = 0; i < 2; i++)
        asm volatile("cp.async.cg.shared.global [%0], [%1], 16;"
                     :: "r"(dst + (uint32_t)(t * 16 + i * 4096)),
                        "l"(s + t * 16 + i * 4096) : "memory");
    asm volatile("cp.async.commit_group;" ::: "memory");
}
#define CP_WAIT1() asm volatile("cp.async.wait_group 1;" ::: "memory")
#define CP_WAIT0() asm volatile("cp.async.wait_group 0;" ::: "memory")

// ---------------------------------------------------------------------------
// Weight prep: round fp32 src[128][ncols] to fp16, swizzle into blobs
// ---------------------------------------------------------------------------
__global__ void prep_kernel(const float* __restrict__ src, int ncols, int dst_id, int chunkoff) {
    int idx = blockIdx.x * blockDim.x + threadIdx.x;
    if (idx >= 128 * ncols) return;
    int k = idx / ncols, n = idx - k * ncols;
    float v = src[k * ncols + n];
    unsigned short hu = __half_as_ushort(__float2half_rn(v));
    unsigned char* bb = (dst_id == 0) ? (unsigned char*)g_Wiou_sw
                      : (dst_id == 1) ? (unsigned char*)g_U_sw
                                      : (unsigned char*)g_Wout_sw;
    unsigned char* blob = bb + (size_t)(chunkoff + (n >> 5)) * CHUNK_BYTES;
    int row = n & 31;
    *(unsigned short*)(blob + offB32(row, k)) = hu;
}

// ---------------------------------------------------------------------------
// SMEM layout (dynamic, 1024-aligned):
//   A tile  [0, 65536)       128 x 256 kcat fp16 [hi|lo], SW128 blocked
//   A2 tile [65536, 73728)   16 x 256 kcat fp16 [hi|lo]  (sibling-summed h)
//   B ring  [73728, 98304)   3 x 8KB cp.async chunk buffers
//   LN part: reuse ring      out kernel only, after MMAs drain
// ---------------------------------------------------------------------------
#define SM_A2   65536
#define SM_B    73728
#define SM_TOT  98304

// build a 128x[hi|lo] split tile from fp32 rows (src row-major, HH cols)
__device__ __forceinline__ void build_tile(char* Ac, const float* src, size_t base,
                                           int n_rows, int t) {
    int row = t >> 1, kh = (t & 1) << 6;
    bool val = row < n_rows;
    const float4* xr = (const float4*)(src + (base + row) * HH + kh);
#pragma unroll
    for (int gg = 0; gg < 8; gg++) {
        float v[8];
        if (val) {
            float4 a = xr[gg * 2], b = xr[gg * 2 + 1];
            v[0]=a.x; v[1]=a.y; v[2]=a.z; v[3]=a.w; v[4]=b.x; v[5]=b.y; v[6]=b.z; v[7]=b.w;
        } else {
#pragma unroll
            for (int q = 0; q < 8; q++) v[q] = 0.f;
        }
        uint32_t hi[4], lo[4];
#pragma unroll
        for (int q = 0; q < 4; q++) split2(v[2*q], v[2*q+1], hi[q], lo[q]);
        int kc = kh + gg * 8;
        *(uint4*)(Ac + offA(row, kc))       = make_uint4(hi[0], hi[1], hi[2], hi[3]);
        *(uint4*)(Ac + offA(row, 128 + kc)) = make_uint4(lo[0], lo[1], lo[2], lo[3]);
    }
}

// blob source for sequence slot in the level kernel (0..11 GEMM1, 12..27 GEMM2)
__device__ __forceinline__ const uint4* lvl_src(int seq) {
    if (seq < 12) {
        int p = seq / 3, sub = seq - p * 3;          // blob chunk = sub*4 + p
        return g_Wiou_sw + (size_t)(sub * 4 + p) * CHUNK_U4;
    }
    return g_U_sw + (size_t)(seq - 12) * CHUNK_U4;
}

// ---------------------------------------------------------------------------
// Fused per-level kernel: one CTA per 128-row tile, 256 threads, 2 CTAs/SM
// seq 0..11 : GEMM1 x@W_iou (+Uh/fc) -> gates -> c,h; builds A2 = sibling-sum h
// seq 12..23: GEMM2a hsum(16 rows) @ U_iou -> g_uh directly (Uh linearity)
// seq 24..27: GEMM2b h(128 rows) @ U_f -> f-gate -> reduce -> g_fc
// ---------------------------------------------------------------------------
__global__ __launch_bounds__(256, 2)
void level_mm(const float* __restrict__ x, const float* __restrict__ b_iou,
              int base0, int n_total, int read_sums, int has_parent) {
    extern __shared__ __align__(1024) char smem[];
    uint32_t sb = smem_to_u32(smem);
    int t = threadIdx.x, lane = t & 31, w = t >> 5;
    int wm = w & 3, wn = w >> 2;
    int q = lane & 3, g = lane >> 2;
    int base = base0 + ((int)blockIdx.x << 7);
    int n_rows = n_total - ((int)blockIdx.x << 7); if (n_rows > 128) n_rows = 128;
    int pbase = (base - 1) >> 3;
    const int NSEQ = has_parent ? 28 : 12;

    // prologue: 2 chunks in flight before building A
    cp_chunk(sb + SM_B, lvl_src(0), t);
    cp_chunk(sb + SM_B + CHUNK_BYTES, lvl_src(1), t);

    build_tile(smem, x, (size_t)base, n_rows, t);

    float accI[2][2][4], accO[2][2][4], accU[2][2][4];
    zacc(accI); zacc(accO); zacc(accU);

    for (int seq = 0; seq < NSEQ; seq++) {
        if (seq + 1 < NSEQ) { CP_WAIT1(); } else { CP_WAIT0(); }
        __syncthreads();                 // chunk seq visible; mma(seq-1) drained
        if (seq + 2 < NSEQ)
            cp_chunk(sb + SM_B + (uint32_t)((seq + 2) % 3) * CHUNK_BYTES,
                     lvl_src(seq + 2), t);
        uint32_t Bb = sb + SM_B + (uint32_t)(seq % 3) * CHUNK_BYTES;

        if (seq < 12) {
            int p = seq / 3, sub = seq - p * 3;
            if (sub == 0)      mma_chunk32(sb, Bb, accI, wm, wn, lane);
            else if (sub == 1) mma_chunk32(sb, Bb, accO, wm, wn, lane);
            else               mma_chunk32(sb, Bb, accU, wm, wn, lane);
            if (sub == 2) {
                // epilogue1 for pass p: gates -> c,h (global) + A2 sibling sums
#pragma unroll
                for (int mi = 0; mi < 2; mi++)
#pragma unroll
                for (int nn = 0; nn < 2; nn++) {
                    int cp = p * 32 + wn * 16 + nn * 8 + 2 * q;
                    float bi0 = __ldg(b_iou + cp),       bi1 = __ldg(b_iou + cp + 1);
                    float bo0 = __ldg(b_iou + 128 + cp), bo1 = __ldg(b_iou + 129 + cp);
                    float bu0 = __ldg(b_iou + 256 + cp), bu1 = __ldg(b_iou + 257 + cp);
#pragma unroll
                    for (int rh = 0; rh < 2; rh++) {
                        int lr = wm * 32 + mi * 16 + g + rh * 8;
                        int rg = base + lr;
                        bool val = lr < n_rows;
                        float2 ui = make_float2(0.f, 0.f), uo = ui, uu = ui, fc = ui;
                        if (val && read_sums) {
                            const float* uh = g_uh + (size_t)rg * NIOU + cp;
                            ui = *(const float2*)(uh);
                            uo = *(const float2*)(uh + 128);
                            uu = *(const float2*)(uh + 256);
                            fc = *(const float2*)(g_fc + (size_t)rg * HH + cp);
                        }
                        float c0 = sigf(accI[mi][nn][rh*2]   + bi0 + ui.x) *
                                   tanh_fast(accU[mi][nn][rh*2]   + bu0 + uu.x) + fc.x;
                        float c1 = sigf(accI[mi][nn][rh*2+1] + bi1 + ui.y) *
                                   tanh_fast(accU[mi][nn][rh*2+1] + bu1 + uu.y) + fc.y;
                        float h0 = sigf(accO[mi][nn][rh*2]   + bo0 + uo.x) * tanh_fast(c0);
                        float h1 = sigf(accO[mi][nn][rh*2+1] + bo1 + uo.y) * tanh_fast(c1);
                        if (val) {
                            *(float2*)(g_c + (size_t)rg * HH + cp) = make_float2(c0, c1);
                            *(float2*)(g_h + (size_t)rg * HH + cp) = make_float2(h0, h1);
                        }
                        if (has_parent) {
                            // sibling sum over g (lanes stride 4,8,16), exact fp32
                            float hs0 = val ? h0 : 0.f, hs1 = val ? h1 : 0.f;
                            hs0 += __shfl_xor_sync(0xffffffffu, hs0, 4);
                            hs0 += __shfl_xor_sync(0xffffffffu, hs0, 8);
                            hs0 += __shfl_xor_sync(0xffffffffu, hs0, 16);
                            hs1 += __shfl_xor_sync(0xffffffffu, hs1, 4);
                            hs1 += __shfl_xor_sync(0xffffffffu, hs1, 8);
                            hs1 += __shfl_xor_sync(0xffffffffu, hs1, 16);
                            if (lane < 4) {   // g==0 lanes, one per column pair
                                int row2 = 4 * wm + 2 * mi + rh;   // sibling group
                                uint32_t hi, lo;
                                split2(hs0, hs1, hi, lo);
                                *(uint32_t*)(smem + SM_A2 + offA16(row2, cp))       = hi;
                                *(uint32_t*)(smem + SM_A2 + offA16(row2, 128 + cp)) = lo;
                            }
                        }
                    }
                }
                zacc(accI); zacc(accO); zacc(accU);
                if (seq == 11 && has_parent) {
                    // rebuild A as h-split (needed for GEMM2b / U_f)
                    __syncthreads();            // all warps done reading A (GEMM1)
                    build_tile(smem, g_h, (size_t)base, n_rows, t);
                }
            }
        } else if (seq < 24) {
            // GEMM2a chunk ch: Uh_sum[16 rows] = hsum @ U_iou cols [ch*32,+32)
            int ch = seq - 12;
            if (w < 4) {
                float acc2[4] = {0.f, 0.f, 0.f, 0.f};
                int rA2 = lane & 15;
                uint32_t PA2 = (sb + SM_A2) + ((uint32_t)(rA2 >> 3) << 10)
                                            + ((uint32_t)(rA2 & 7) << 7);
                uint32_t CA2 = (rA2 & 7) << 4;
                int aK = (lane >> 4) << 3;
                int nB2 = w * 8 + (lane & 7);
                uint32_t PB2 = Bb + ((uint32_t)(nB2 >> 3) << 10)
                                  + ((uint32_t)(nB2 & 7) << 7);
                uint32_t CB2 = (nB2 & 7) << 4;
                int kB2 = ((lane >> 3) & 1) << 3;
#pragma unroll
                for (int s = 0; s < 8; s++) {
                    int kA = (s << 4) + aK;
                    int kB = (s << 4) + kB2;
                    uint32_t aAh = PA2 + ((uint32_t)(kA >> 6) << 11)
                                       + (((uint32_t)(kA & 63) << 1) ^ CA2);
                    uint32_t aAl = PA2 + ((uint32_t)((kA + 128) >> 6) << 11)
                                       + (((uint32_t)(kA & 63) << 1) ^ CA2);
                    uint32_t aB  = PB2 + ((uint32_t)(kB >> 6) << 12)
                                       + (((uint32_t)(kB & 63) << 1) ^ CB2);
                    uint32_t a2h[4], a2l[4], b0, b1;
                    LDSM4(a2h[0], a2h[1], a2h[2], a2h[3], aAh);
                    LDSM4(a2l[0], a2l[1], a2l[2], a2l[3], aAl);
                    LDSM2(b0, b1, aB);
                    mma_f16(acc2, a2h, b0, b1);
                    mma_f16(acc2, a2l, b0, b1);
                }
                // D frag m16n8 -> direct parent stores
                int cb2 = ch * 32 + w * 8 + 2 * (lane & 3);
                int gr0 = lane >> 2;
                if (gr0 * 8 < n_rows)
                    *(float2*)(g_uh + (size_t)(pbase + gr0) * NIOU + cb2) =
                        make_float2(acc2[0], acc2[1]);
                if ((gr0 + 8) * 8 < n_rows)
                    *(float2*)(g_uh + (size_t)(pbase + gr0 + 8) * NIOU + cb2) =
                        make_float2(acc2[2], acc2[3]);
            }
        } else {
            // GEMM2b chunk: f = sigmoid(h@U_f + xf[par]); fc = f*c; reduce
            int ch = seq - 12;   // 12..15
            mma_chunk32(sb, Bb, accI, wm, wn, lane);   // reuse accI as accG
#pragma unroll
            for (int mi = 0; mi < 2; mi++)
#pragma unroll
            for (int nn = 0; nn < 2; nn++) {
                int cfl = (ch - 12) * 32 + wn * 16 + nn * 8 + 2 * q;
                float v[4];
#pragma unroll
                for (int rh = 0; rh < 2; rh++) {
                    int lr = wm * 32 + mi * 16 + g + rh * 8;
                    int rg = base + lr;
                    if (lr < n_rows) {
                        int pr = (rg - 1) >> 3;
                        float2 xf2 = *(const float2*)(g_xf + (size_t)pr * HH + cfl);
                        float2 c2  = *(const float2*)(g_c  + (size_t)rg * HH + cfl);
                        v[rh*2]   = sigf(accI[mi][nn][rh*2]   + xf2.x) * c2.x;
                        v[rh*2+1] = sigf(accI[mi][nn][rh*2+1] + xf2.y) * c2.y;
                    } else { v[rh*2] = 0.f; v[rh*2+1] = 0.f; }
                }
#pragma unroll
                for (int r = 0; r < 4; r++) {
                    float s = v[r];
                    s += __shfl_xor_sync(0xffffffffu, s, 4);
                    s += __shfl_xor_sync(0xffffffffu, s, 8);
                    s += __shfl_xor_sync(0xffffffffu, s, 16);
                    v[r] = s;
                }
                if (lane < 4) {
#pragma unroll
                    for (int rh = 0; rh < 2; rh++) {
                        int lr0 = wm * 32 + mi * 16 + rh * 8;
                        if (lr0 < n_rows) {
                            int pr = (base + lr0 - 1) >> 3;
                            *(float2*)(g_fc + (size_t)pr * HH + cfl) =
                                make_float2(v[rh*2], v[rh*2+1]);
                        }
                    }
                }
            }
            zacc(accI);
        }
    }
}

// ---------------------------------------------------------------------------
// Output kernel: out = tanh(LN(h @ W_out + b_out) * gamma + beta)
// ---------------------------------------------------------------------------
__global__ __launch_bounds__(256, 1)
void out_mm(const float* __restrict__ b_out, const float* __restrict__ gamma,
            const float* __restrict__ beta, float* __restrict__ out) {
    extern __shared__ __align__(1024) char smem[];
    uint32_t sb = smem_to_u32(smem);
    int t = threadIdx.x, lane = t & 31, w = t >> 5;
    int wm = w & 3, wn = w >> 2;
    int q = lane & 3, g = lane >> 2;
    int base = (int)blockIdx.x << 7;
    int n_rows = NN - base; if (n_rows > 128) n_rows = 128;

    cp_chunk(sb + SM_B, (const uint4*)g_Wout_sw, t);
    cp_chunk(sb + SM_B + CHUNK_BYTES, g_Wout_sw + CHUNK_U4, t);

    build_tile(smem, g_h, (size_t)base, n_rows, t);

    float acc8[8][2][2][4];
    for (int seq = 0; seq < 8; seq++) {
        if (seq + 1 < 8) { CP_WAIT1(); } else { CP_WAIT0(); }
        __syncthreads();
        if (seq + 2 < 8)
            cp_chunk(sb + SM_B + (uint32_t)((seq + 2) % 3) * CHUNK_BYTES,
                     g_Wout_sw + (size_t)(seq + 2) * CHUNK_U4, t);
        zacc(acc8[seq]);
        mma_chunk32(sb, sb + SM_B + (uint32_t)(seq % 3) * CHUNK_BYTES,
                    acc8[seq], wm, wn, lane);
    }

    // bias + per-row partial sums
    float s[2][2] = {{0.f,0.f},{0.f,0.f}}, sq[2][2] = {{0.f,0.f},{0.f,0.f}};
#pragma unroll
    for (int ch = 0; ch < 8; ch++)
#pragma unroll
    for (int nn = 0; nn < 2; nn++) {
        int cb = ch * 32 + wn * 16 + nn * 8 + 2 * q;
        float b0 = __ldg(b_out + cb), b1 = __ldg(b_out + cb + 1);
#pragma unroll
        for (int mi = 0; mi < 2; mi++)
#pragma unroll
        for (int rh = 0; rh < 2; rh++) {
            float y0 = (acc8[ch][mi][nn][rh*2]   += b0);
            float y1 = (acc8[ch][mi][nn][rh*2+1] += b1);
            s[mi][rh]  += y0 + y1;
            sq[mi][rh] += y0 * y0 + y1 * y1;
        }
    }
#pragma unroll
    for (int mi = 0; mi < 2; mi++)
#pragma unroll
    for (int rh = 0; rh < 2; rh++) {
        s[mi][rh]  += __shfl_xor_sync(0xffffffffu, s[mi][rh], 1);
        s[mi][rh]  += __shfl_xor_sync(0xffffffffu, s[mi][rh], 2);
        sq[mi][rh] += __shfl_xor_sync(0xffffffffu, sq[mi][rh], 1);
        sq[mi][rh] += __shfl_xor_sync(0xffffffffu, sq[mi][rh], 2);
    }
    float2* part = (float2*)(smem + SM_B);   // B ring idle after MMAs drain
    __syncthreads();
    if (q == 0) {
#pragma unroll
        for (int mi = 0; mi < 2; mi++)
#pragma unroll
        for (int rh = 0; rh < 2; rh++) {
            int lr = wm * 32 + mi * 16 + g + rh * 8;
            part[lr * 2 + wn] = make_float2(s[mi][rh], sq[mi][rh]);
        }
    }
    __syncthreads();
    float mu[2][2], rs[2][2];
#pragma unroll
    for (int mi = 0; mi < 2; mi++)
#pragma unroll
    for (int rh = 0; rh < 2; rh++) {
        int lr = wm * 32 + mi * 16 + g + rh * 8;
        float2 a = part[lr * 2], b = part[lr * 2 + 1];
        float m = (a.x + b.x) * (1.f / 256.f);
        float var = (a.y + b.y) * (1.f / 256.f) - m * m;
        mu[mi][rh] = m;
        rs[mi][rh] = rsqrtf(var + 1e-5f);
    }
#pragma unroll
    for (int ch = 0; ch < 8; ch++)
#pragma unroll
    for (int nn = 0; nn < 2; nn++) {
        int cb = ch * 32 + wn * 16 + nn * 8 + 2 * q;
        float g0 = __ldg(gamma + cb), g1 = __ldg(gamma + cb + 1);
        float e0 = __ldg(beta + cb),  e1 = __ldg(beta + cb + 1);
#pragma unroll
        for (int mi = 0; mi < 2; mi++)
#pragma unroll
        for (int rh = 0; rh < 2; rh++) {
            int lr = wm * 32 + mi * 16 + g + rh * 8;
            if (lr < n_rows) {
                float y0 = (acc8[ch][mi][nn][rh*2]   - mu[mi][rh]) * rs[mi][rh] * g0 + e0;
                float y1 = (acc8[ch][mi][nn][rh*2+1] - mu[mi][rh]) * rs[mi][rh] * g1 + e1;
                *(float2*)(out + (size_t)(base + lr) * DDEC + cb) =
                    make_float2(tanh_fast(y0), tanh_fast(y1));
            }
        }
    }
}

// ---------------------------------------------------------------------------
// x_f precompute (FFMA, small): g_xf[r] = x[r] @ W_f + b_f  for r < NPAR
// ---------------------------------------------------------------------------
#define TS 68
__global__ void xf_kernel(const float* __restrict__ x, const float* __restrict__ W_f,
                          const float* __restrict__ b_f) {
    extern __shared__ float sm[];
    float* As = sm;
    float* Ws = sm + 128 * TS;
    int t = threadIdx.x;
    int base = blockIdx.x << 6;
    int n_rows = NPAR - base; if (n_rows > 64) n_rows = 64;
    int m0 = (t & 15) * 4, c0 = (t >> 4) * 4;

#pragma unroll
    for (int i = 0; i < 32; i++) {
        int idx = t + 256 * i;
        int m = idx >> 7, k = idx & 127;
        float v = 0.f;
        if (m < n_rows) v = x[(size_t)(base + m) * HH + k];
        As[k * TS + m] = v;
    }
    for (int ch = 0; ch < 2; ch++) {
        __syncthreads();
#pragma unroll
        for (int i = 0; i < 32; i++) {
            int idx = t + 256 * i;
            int k = idx >> 6, c = idx & 63;
            Ws[k * TS + c] = W_f[k * HH + ch * 64 + c];
        }
        __syncthreads();
        float acc[4][4] = {};
#pragma unroll 8
        for (int k = 0; k < 128; k++) {
            float4 a = *(const float4*)(As + k * TS + m0);
            float4 b = *(const float4*)(Ws + k * TS + c0);
            acc[0][0] += a.x*b.x; acc[0][1] += a.x*b.y; acc[0][2] += a.x*b.z; acc[0][3] += a.x*b.w;
            acc[1][0] += a.y*b.x; acc[1][1] += a.y*b.y; acc[1][2] += a.y*b.z; acc[1][3] += a.y*b.w;
            acc[2][0] += a.z*b.x; acc[2][1] += a.z*b.y; acc[2][2] += a.z*b.z; acc[2][3] += a.z*b.w;
            acc[3][0] += a.w*b.x; acc[3][1] += a.w*b.y; acc[3][2] += a.w*b.z; acc[3][3] += a.w*b.w;
        }
#pragma unroll
        for (int i = 0; i < 4; i++)
#pragma unroll
            for (int j = 0; j < 4; j++) {
                int m = m0 + i, cc = ch * 64 + c0 + j;
                if (m < n_rows)
                    g_xf[(size_t)(base + m) * HH + cc] = acc[i][j] + b_f[cc];
            }
    }
}

// ---------------------------------------------------------------------------
extern "C" void kernel_launch(void* const* d_in, const int* in_sizes, int n_in,
                              void* d_out, int out_size) {
    const float* x = (const float*)d_in[0];
    int wi = 3;
    if (n_in > 3 && in_sizes[3] <= 1) wi = 4;
    const float* W_iou = (const float*)d_in[wi + 0];
    const float* b_iou = (const float*)d_in[wi + 1];
    const float* U_iou = (const float*)d_in[wi + 2];
    const float* W_f   = (const float*)d_in[wi + 3];
    const float* b_f   = (const float*)d_in[wi + 4];
    const float* U_f   = (const float*)d_in[wi + 5];
    const float* W_out = (const float*)d_in[wi + 6];
    const float* b_out = (const float*)d_in[wi + 7];
    const float* gamma = (const float*)d_in[wi + 8];
    const float* beta  = (const float*)d_in[wi + 9];
    float* out = (float*)d_out;

    cudaFuncSetAttribute(level_mm, cudaFuncAttributeMaxDynamicSharedMemorySize, SM_TOT);
    cudaFuncSetAttribute(out_mm,   cudaFuncAttributeMaxDynamicSharedMemorySize, SM_TOT);
    cudaFuncSetAttribute(xf_kernel, cudaFuncAttributeMaxDynamicSharedMemorySize,
                         (2 * 128 * TS) * (int)sizeof(float));

    // weight prep (fp16 round + swizzle into 32-col chunks)
    prep_kernel<<<192, 256>>>(W_iou, 384, 0, 0);
    prep_kernel<<<192, 256>>>(U_iou, 384, 1, 0);
    prep_kernel<<< 64, 256>>>(U_f,   128, 1, 12);
    prep_kernel<<<128, 256>>>(W_out, 256, 2, 0);

    xf_kernel<<<(NPAR + 63) / 64, 256, (2 * 128 * TS) * sizeof(float)>>>(x, W_f, b_f);

    const int off[8] = {0, 1, 9, 73, 585, 4681, 37449, 299593};
    for (int l = 6; l >= 0; l--) {
        int base = off[l], n = off[l + 1] - off[l];
        int blocks = (n + 127) / 128;
        level_mm<<<blocks, 256, SM_TOT>>>(x, b_iou, base, n,
                                          (l < 6) ? 1 : 0, (l > 0) ? 1 : 0);
    }
    out_mm<<<(NN + 127) / 128, 256, SM_TOT>>>(b_out, gamma, beta, out);
}

// round 13
// speedup vs baseline: 4.3324x; 1.1213x over previous
#include <cuda_runtime.h>
#include <cuda_fp16.h>
#include <math.h>
#include <stdint.h>

// ---------------------------------------------------------------------------
// Problem constants
// ---------------------------------------------------------------------------
#define NN    299593      // total nodes, complete 8-ary tree, 7 levels
#define HH    128         // D_ENC == D_EMB
#define NIOU  384         // 3*H
#define DDEC  256
#define NPAR  37449       // nodes at levels 0..5 (all parents)

#define CHUNK_BYTES 8192  // one pre-swizzled B chunk: 32 N-rows x 128 K x fp16
#define CHUNK_U4    (CHUNK_BYTES / 16)

// Scratch (device globals: allocation-free per harness rules)
__device__ float g_h [(size_t)NN  * HH];
__device__ float g_c [(size_t)NN  * HH];
__device__ float g_xf[(size_t)NPAR * HH];
__device__ float g_uh[(size_t)NPAR * NIOU];
__device__ float g_fc[(size_t)NPAR * HH];

// Pre-swizzled fp16 weight blobs (single-rounded B), 32-row x 128-K chunks
__device__ uint4 g_Wiou_sw[12 * CHUNK_U4];
__device__ uint4 g_U_sw   [16 * CHUNK_U4];  // [U_iou(384) | U_f(128)] cols
__device__ uint4 g_Wout_sw[ 8 * CHUNK_U4];

// ---------------------------------------------------------------------------
// Helpers
// ---------------------------------------------------------------------------
__device__ __forceinline__ uint32_t smem_to_u32(const void* p) {
    uint32_t a;
    asm("{ .reg .u64 t; cvta.to.shared.u64 t, %1; cvt.u32.u64 %0, t; }" : "=r"(a) : "l"(p));
    return a;
}
__device__ __forceinline__ uint32_t swz(uint32_t o) { return o ^ ((o >> 3) & 0x70); }
__device__ __forceinline__ uint32_t offA(int row, int k) {   // 128-row tile: 16 atoms/kblk
    return swz((uint32_t)(((row >> 3) + (k >> 6) * 16) * 1024 + (row & 7) * 128 + (k & 63) * 2));
}
__device__ __forceinline__ uint32_t offA64(int row, int k) { // 64-row tile: 8 atoms/kblk
    return swz((uint32_t)(((row >> 3) + (k >> 6) * 8) * 1024 + (row & 7) * 128 + (k & 63) * 2));
}
__device__ __forceinline__ uint32_t offA16(int row, int k) { // 16-row tile: 2 atoms/kblk
    return swz((uint32_t)(((row >> 3) + (k >> 6) * 2) * 1024 + (row & 7) * 128 + (k & 63) * 2));
}
__device__ __forceinline__ uint32_t offB32(int row, int k) { // 32-row tile: 4 atoms/kblk
    return swz((uint32_t)(((row >> 3) + (k >> 6) * 4) * 1024 + (row & 7) * 128 + (k & 63) * 2));
}
// fp16 split: hi = rn(v), lo = rn(v - hi); pack pairs
__device__ __forceinline__ void split2(float a, float b, uint32_t& hi, uint32_t& lo) {
    __half ha = __float2half_rn(a), hb = __float2half_rn(b);
    __half la = __float2half_rn(a - __half2float(ha));
    __half lb = __float2half_rn(b - __half2float(hb));
    hi = (uint32_t)__half_as_ushort(ha) | ((uint32_t)__half_as_ushort(hb) << 16);
    lo = (uint32_t)__half_as_ushort(la) | ((uint32_t)__half_as_ushort(lb) << 16);
}
__device__ __forceinline__ float sigf(float v) {
    return __fdividef(1.0f, 1.0f + __expf(-v));
}
__device__ __forceinline__ float tanh_fast(float x) {
    float t = __expf(2.0f * x);
    return 1.0f - __fdividef(2.0f, t + 1.0f);
}

#define LDSM4(R0, R1, R2, R3, ADDR) \
    asm volatile("ldmatrix.sync.aligned.m8n8.x4.shared.b16 {%0,%1,%2,%3}, [%4];" \
                 : "=r"(R0), "=r"(R1), "=r"(R2), "=r"(R3) : "r"(ADDR))
#define LDSM2(R0, R1, ADDR) \
    asm volatile("ldmatrix.sync.aligned.m8n8.x2.shared.b16 {%0,%1}, [%2];" \
                 : "=r"(R0), "=r"(R1) : "r"(ADDR))

__device__ __forceinline__ void mma_f16(float (&d)[4], const uint32_t (&a)[4],
                                        uint32_t b0, uint32_t b1) {
    asm volatile("mma.sync.aligned.m16n8k16.row.col.f32.f16.f16.f32 "
                 "{%0,%1,%2,%3}, {%4,%5,%6,%7}, {%8,%9}, {%0,%1,%2,%3};"
                 : "+f"(d[0]), "+f"(d[1]), "+f"(d[2]), "+f"(d[3])
                 : "r"(a[0]), "r"(a[1]), "r"(a[2]), "r"(a[3]), "r"(b0), "r"(b1));
}

__device__ __forceinline__ void zacc(float (&a)[2][2][4]) {
#pragma unroll
    for (int i = 0; i < 2; i++)
#pragma unroll
        for (int j = 0; j < 2; j++)
#pragma unroll
            for (int k = 0; k < 4; k++) a[i][j][k] = 0.f;
}

// One 32-col chunk: per-warp C[m32 x n16] += A[128x128] * B[32x128]^T
// fp16 2-term split (A = Ah + Al, B single-rounded).
__device__ __forceinline__ void mma_chunk32(uint32_t Abase, uint32_t Bbase,
                                            float (&acc)[2][2][4],
                                            int wm, int wn, int lane) {
    int rA = wm * 32 + (lane & 15);
    uint32_t PA = Abase + ((rA >> 3) << 10) + ((rA & 7) << 7);
    uint32_t CA = (rA & 7) << 4;
    int aK = (lane >> 4) << 3;
    int nB = wn * 16 + (((lane >> 4) & 1) << 3) + (lane & 7);
    uint32_t PB = Bbase + ((nB >> 3) << 10) + ((nB & 7) << 7);
    uint32_t CB = (nB & 7) << 4;
    int bK = ((lane >> 3) & 1) << 3;
#pragma unroll
    for (int s = 0; s < 8; s++) {
        int kA = (s << 4) + aK;
        int kB = (s << 4) + bK;
        uint32_t aAh = PA + ((uint32_t)(kA >> 6) << 14) + ((uint32_t)((kA & 63) << 1) ^ CA);
        uint32_t aAl = PA + ((uint32_t)((kA + 128) >> 6) << 14) + ((uint32_t)((kA & 63) << 1) ^ CA);
        uint32_t aBh = PB + ((uint32_t)(kB >> 6) << 12) + ((uint32_t)((kB & 63) << 1) ^ CB);
        uint32_t ah0[4], ah1[4], al0[4], al1[4], bh[4];
        LDSM4(ah0[0], ah0[1], ah0[2], ah0[3], aAh);
        LDSM4(ah1[0], ah1[1], ah1[2], ah1[3], aAh + 2048);
        LDSM4(al0[0], al0[1], al0[2], al0[3], aAl);
        LDSM4(al1[0], al1[1], al1[2], al1[3], aAl + 2048);
        LDSM4(bh[0], bh[1], bh[2], bh[3], aBh);
        mma_f16(acc[0][0], ah0, bh[0], bh[1]);
        mma_f16(acc[1][0], ah1, bh[0], bh[1]);
        mma_f16(acc[0][1], ah0, bh[2], bh[3]);
        mma_f16(acc[1][1], ah1, bh[2], bh[3]);
        mma_f16(acc[0][0], al0, bh[0], bh[1]);
        mma_f16(acc[1][0], al1, bh[0], bh[1]);
        mma_f16(acc[0][1], al0, bh[2], bh[3]);
        mma_f16(acc[1][1], al1, bh[2], bh[3]);
    }
}

// 64-row-tile variant: per-warp C[m32 x n8], warps 2(wm) x 4(wn)
__device__ __forceinline__ void mma_chunk64(uint32_t Abase, uint32_t Bbase,
                                            float (&acc)[2][4],
                                            int wm, int wn, int lane) {
    int rA = wm * 32 + (lane & 15);
    uint32_t PA = Abase + ((rA >> 3) << 10) + ((rA & 7) << 7);
    uint32_t CA = (rA & 7) << 4;
    int aK = (lane >> 4) << 3;
    int nB = wn * 8 + (lane & 7);
    uint32_t PB = Bbase + ((nB >> 3) << 10) + ((nB & 7) << 7);
    uint32_t CB = (nB & 7) << 4;
    int bK = ((lane >> 3) & 1) << 3;
#pragma unroll
    for (int s = 0; s < 8; s++) {
        int kA = (s << 4) + aK;
        int kB = (s << 4) + bK;
        uint32_t aAh = PA + ((uint32_t)(kA >> 6) << 13) + ((uint32_t)((kA & 63) << 1) ^ CA);
        uint32_t aAl = PA + ((uint32_t)((kA + 128) >> 6) << 13) + ((uint32_t)((kA & 63) << 1) ^ CA);
        uint32_t aB  = PB + ((uint32_t)(kB >> 6) << 12) + ((uint32_t)((kB & 63) << 1) ^ CB);
        uint32_t ah0[4], ah1[4], al0[4], al1[4], b0, b1;
        LDSM4(ah0[0], ah0[1], ah0[2], ah0[3], aAh);
        LDSM4(ah1[0], ah1[1], ah1[2], ah1[3], aAh + 2048);
        LDSM4(al0[0], al0[1], al0[2], al0[3], aAl);
        LDSM4(al1[0], al1[1], al1[2], al1[3], aAl + 2048);
        LDSM2(b0, b1, aB);
        mma_f16(acc[0], ah0, b0, b1);
        mma_f16(acc[1], ah1, b0, b1);
        mma_f16(acc[0], al0, b0, b1);
        mma_f16(acc[1], al1, b0, b1);
    }
}

// ---------------------------------------------------------------------------
// cp.async: one 8KB chunk, 256 threads x 2 x 16B, one commit group
// ---------------------------------------------------------------------------
__device__ __forceinline__ void cp_chunk(uint32_t dst, const uint4* src, int t) {
    const char* s = (const char*)src;
#pragma unroll
    for (int i = 0; i < 2; i++)
        asm volatile("cp.async.cg.shared.global [%0], [%1], 16;"
                     :: "r"(dst + (uint32_t)(t * 16 + i * 4096)),
                        "l"(s + t * 16 + i * 4096) : "memory");
    asm volatile("cp.async.commit_group;" ::: "memory");
}
#define CP_WAIT0() asm volatile("cp.async.wait_group 0;" ::: "memory")

// ---------------------------------------------------------------------------
// Weight prep (single launch): fp16 round + swizzle all four blobs
// grid: 576 blocks x 256 threads, block ranges select source
// ---------------------------------------------------------------------------
__global__ void prep_all(const float* __restrict__ W_iou, const float* __restrict__ U_iou,
                         const float* __restrict__ U_f, const float* __restrict__ W_out) {
    int b = blockIdx.x;
    const float* src; int ncols, dst_id, chunkoff, rel;
    if (b < 192)      { src = W_iou; ncols = 384; dst_id = 0; chunkoff = 0;  rel = b; }
    else if (b < 384) { src = U_iou; ncols = 384; dst_id = 1; chunkoff = 0;  rel = b - 192; }
    else if (b < 448) { src = U_f;   ncols = 128; dst_id = 1; chunkoff = 12; rel = b - 384; }
    else              { src = W_out; ncols = 256; dst_id = 2; chunkoff = 0;  rel = b - 448; }
    int idx = rel * 256 + threadIdx.x;
    if (idx >= 128 * ncols) return;
    int k = idx / ncols, n = idx - k * ncols;
    float v = src[k * ncols + n];
    unsigned short hu = __half_as_ushort(__float2half_rn(v));
    unsigned char* bb = (dst_id == 0) ? (unsigned char*)g_Wiou_sw
                      : (dst_id == 1) ? (unsigned char*)g_U_sw
                                      : (unsigned char*)g_Wout_sw;
    unsigned char* blob = bb + (size_t)(chunkoff + (n >> 5)) * CHUNK_BYTES;
    int row = n & 31;
    *(unsigned short*)(blob + offB32(row, k)) = hu;
}

// ---------------------------------------------------------------------------
// Level kernel SMEM layout (occ 2: 104KB x 2 <= 228KB):
//   A tile  [0, 65536)       128 x 256 kcat fp16 [hi|lo]
//   A2 tile [65536, 73728)   16 x 256 kcat fp16 [hi|lo] (sibling-summed h)
//   B ring  [73728, 106496)  4 x 8KB (step-parity pairs)
// ---------------------------------------------------------------------------
#define SM_A2    65536
#define SM_B     73728
#define SM_LVL   106496
// Out kernel SMEM: A64 [0,32768) | ring [32768,65536) | part [65536,67584)
#define SM_OB    32768
#define SM_OPART 65536
#define SM_OUT   67584

// build a 128x[hi|lo] split tile from fp32 rows (src row-major, HH cols)
__device__ __forceinline__ void build_tile(char* Ac, const float* src, size_t base,
                                           int n_rows, int t) {
    int row = t >> 1, kh = (t & 1) << 6;
    bool val = row < n_rows;
    const float4* xr = (const float4*)(src + (base + row) * HH + kh);
#pragma unroll
    for (int gg = 0; gg < 8; gg++) {
        float v[8];
        if (val) {
            float4 a = xr[gg * 2], b = xr[gg * 2 + 1];
            v[0]=a.x; v[1]=a.y; v[2]=a.z; v[3]=a.w; v[4]=b.x; v[5]=b.y; v[6]=b.z; v[7]=b.w;
        } else {
#pragma unroll
            for (int q = 0; q < 8; q++) v[q] = 0.f;
        }
        uint32_t hi[4], lo[4];
#pragma unroll
        for (int q = 0; q < 4; q++) split2(v[2*q], v[2*q+1], hi[q], lo[q]);
        int kc = kh + gg * 8;
        *(uint4*)(Ac + offA(row, kc))       = make_uint4(hi[0], hi[1], hi[2], hi[3]);
        *(uint4*)(Ac + offA(row, 128 + kc)) = make_uint4(lo[0], lo[1], lo[2], lo[3]);
    }
}

// 64-row variant (4 threads per row, 32 K each)
__device__ __forceinline__ void build_tile64(char* Ac, const float* src, size_t base,
                                             int n_rows, int t) {
    int row = t >> 2, kh = (t & 3) << 5;
    bool val = row < n_rows;
    const float4* xr = (const float4*)(src + (base + row) * HH + kh);
#pragma unroll
    for (int gg = 0; gg < 4; gg++) {
        float v[8];
        if (val) {
            float4 a = xr[gg * 2], b = xr[gg * 2 + 1];
            v[0]=a.x; v[1]=a.y; v[2]=a.z; v[3]=a.w; v[4]=b.x; v[5]=b.y; v[6]=b.z; v[7]=b.w;
        } else {
#pragma unroll
            for (int q = 0; q < 8; q++) v[q] = 0.f;
        }
        uint32_t hi[4], lo[4];
#pragma unroll
        for (int q = 0; q < 4; q++) split2(v[2*q], v[2*q+1], hi[q], lo[q]);
        int kc = kh + gg * 8;
        *(uint4*)(Ac + offA64(row, kc))       = make_uint4(hi[0], hi[1], hi[2], hi[3]);
        *(uint4*)(Ac + offA64(row, 128 + kc)) = make_uint4(lo[0], lo[1], lo[2], lo[3]);
    }
}

// chunk c -> blob source (0..11 GEMM1, 12..27 GEMM2)
__device__ __forceinline__ const uint4* lvl_src(int c) {
    if (c < 12) {
        int p = c / 3, sub = c - p * 3;              // blob chunk = sub*4 + p
        return g_Wiou_sw + (size_t)(sub * 4 + p) * CHUNK_U4;
    }
    return g_U_sw + (size_t)(c - 12) * CHUNK_U4;
}
// step s -> first chunk / count  (s<8: GEMM1 pairs (I,O),(U); s>=8: pairs of 2)
__device__ __forceinline__ int st_start(int s) {
    return (s < 8) ? s + ((s + 1) >> 1) : 12 + (s - 8) * 2;
}
__device__ __forceinline__ int st_cnt(int s) {
    return (s < 8) ? ((s & 1) ? 1 : 2) : 2;
}
__device__ __forceinline__ void issue_group(uint32_t sb, int s, int t) {
    int st = st_start(s), cn = st_cnt(s);
    uint32_t slot = (uint32_t)((s & 1) * 2);
    for (int j = 0; j < cn; j++)
        cp_chunk(sb + SM_B + (slot + j) * CHUNK_BYTES, lvl_src(st + j), t);
}

// ---------------------------------------------------------------------------
// Fused per-level kernel: one CTA per 128-row tile, 256 threads, 2 CTAs/SM
// 16 paired steps: 8 GEMM1 (+epilogue on odd), 6 tiny GEMM2a, 2 GEMM2b
// ---------------------------------------------------------------------------
__global__ __launch_bounds__(256, 2)
void level_mm(const float* __restrict__ x, const float* __restrict__ b_iou,
              int base0, int n_total, int read_sums, int has_parent) {
    extern __shared__ __align__(1024) char smem[];
    uint32_t sb = smem_to_u32(smem);
    int t = threadIdx.x, lane = t & 31, w = t >> 5;
    int wm = w & 3, wn = w >> 2;
    int q = lane & 3, g = lane >> 2;
    int base = base0 + ((int)blockIdx.x << 7);
    int n_rows = n_total - ((int)blockIdx.x << 7); if (n_rows > 128) n_rows = 128;
    int pbase = (base - 1) >> 3;
    const int n_steps = has_parent ? 16 : 8;

    issue_group(sb, 0, t);
    build_tile(smem, x, (size_t)base, n_rows, t);

    float accI[2][2][4], accO[2][2][4], accU[2][2][4];
    zacc(accI); zacc(accO); zacc(accU);

    for (int s = 0; s < n_steps; s++) {
        CP_WAIT0();
        __syncthreads();               // group s landed; prior step's reads done
        if (s + 1 < n_steps) issue_group(sb, s + 1, t);
        uint32_t B0 = sb + SM_B + (uint32_t)((s & 1) * 2) * CHUNK_BYTES;

        if (s < 8) {
            if (!(s & 1)) {
                mma_chunk32(sb, B0, accI, wm, wn, lane);
                mma_chunk32(sb, B0 + CHUNK_BYTES, accO, wm, wn, lane);
            } else {
                mma_chunk32(sb, B0, accU, wm, wn, lane);
                int p = s >> 1;
                // epilogue1 for pass p: gates -> c,h (global) + A2 sibling sums
#pragma unroll
                for (int mi = 0; mi < 2; mi++)
#pragma unroll
                for (int nn = 0; nn < 2; nn++) {
                    int cp = p * 32 + wn * 16 + nn * 8 + 2 * q;
                    float bi0 = __ldg(b_iou + cp),       bi1 = __ldg(b_iou + cp + 1);
                    float bo0 = __ldg(b_iou + 128 + cp), bo1 = __ldg(b_iou + 129 + cp);
                    float bu0 = __ldg(b_iou + 256 + cp), bu1 = __ldg(b_iou + 257 + cp);
#pragma unroll
                    for (int rh = 0; rh < 2; rh++) {
                        int lr = wm * 32 + mi * 16 + g + rh * 8;
                        int rg = base + lr;
                        bool val = lr < n_rows;
                        float2 ui = make_float2(0.f, 0.f), uo = ui, uu = ui, fc = ui;
                        if (val && read_sums) {
                            const float* uh = g_uh + (size_t)rg * NIOU + cp;
                            ui = *(const float2*)(uh);
                            uo = *(const float2*)(uh + 128);
                            uu = *(const float2*)(uh + 256);
                            fc = *(const float2*)(g_fc + (size_t)rg * HH + cp);
                        }
                        float c0 = sigf(accI[mi][nn][rh*2]   + bi0 + ui.x) *
                                   tanh_fast(accU[mi][nn][rh*2]   + bu0 + uu.x) + fc.x;
                        float c1 = sigf(accI[mi][nn][rh*2+1] + bi1 + ui.y) *
                                   tanh_fast(accU[mi][nn][rh*2+1] + bu1 + uu.y) + fc.y;
                        float h0 = sigf(accO[mi][nn][rh*2]   + bo0 + uo.x) * tanh_fast(c0);
                        float h1 = sigf(accO[mi][nn][rh*2+1] + bo1 + uo.y) * tanh_fast(c1);
                        if (val) {
                            *(float2*)(g_c + (size_t)rg * HH + cp) = make_float2(c0, c1);
                            *(float2*)(g_h + (size_t)rg * HH + cp) = make_float2(h0, h1);
                        }
                        if (has_parent) {
                            float hs0 = val ? h0 : 0.f, hs1 = val ? h1 : 0.f;
                            hs0 += __shfl_xor_sync(0xffffffffu, hs0, 4);
                            hs0 += __shfl_xor_sync(0xffffffffu, hs0, 8);
                            hs0 += __shfl_xor_sync(0xffffffffu, hs0, 16);
                            hs1 += __shfl_xor_sync(0xffffffffu, hs1, 4);
                            hs1 += __shfl_xor_sync(0xffffffffu, hs1, 8);
                            hs1 += __shfl_xor_sync(0xffffffffu, hs1, 16);
                            if (lane < 4) {
                                int row2 = 4 * wm + 2 * mi + rh;
                                uint32_t hi, lo;
                                split2(hs0, hs1, hi, lo);
                                *(uint32_t*)(smem + SM_A2 + offA16(row2, cp))       = hi;
                                *(uint32_t*)(smem + SM_A2 + offA16(row2, 128 + cp)) = lo;
                            }
                        }
                    }
                }
                zacc(accI); zacc(accO); zacc(accU);
                if (s == 7 && has_parent) {
                    __syncthreads();           // all warps done reading A (GEMM1)
                    build_tile(smem, g_h, (size_t)base, n_rows, t);
                }
            }
        } else if (s < 14) {
            // two tiny GEMM2a chunks: Uh_sum[16 rows] = hsum @ U_iou
            int ch0 = st_start(s) - 12;
            if (w < 4) {
#pragma unroll
                for (int jj = 0; jj < 2; jj++) {
                    int ch = ch0 + jj;
                    uint32_t Bb = B0 + (uint32_t)jj * CHUNK_BYTES;
                    float acc2[4] = {0.f, 0.f, 0.f, 0.f};
                    int rA2 = lane & 15;
                    uint32_t PA2 = (sb + SM_A2) + ((uint32_t)(rA2 >> 3) << 10)
                                                + ((uint32_t)(rA2 & 7) << 7);
                    uint32_t CA2 = (rA2 & 7) << 4;
                    int aK = (lane >> 4) << 3;
                    int nB2 = w * 8 + (lane & 7);
                    uint32_t PB2 = Bb + ((uint32_t)(nB2 >> 3) << 10)
                                      + ((uint32_t)(nB2 & 7) << 7);
                    uint32_t CB2 = (nB2 & 7) << 4;
                    int kB2 = ((lane >> 3) & 1) << 3;
#pragma unroll
                    for (int ks = 0; ks < 8; ks++) {
                        int kA = (ks << 4) + aK;
                        int kB = (ks << 4) + kB2;
                        uint32_t aAh = PA2 + ((uint32_t)(kA >> 6) << 11)
                                           + (((uint32_t)(kA & 63) << 1) ^ CA2);
                        uint32_t aAl = PA2 + ((uint32_t)((kA + 128) >> 6) << 11)
                                           + (((uint32_t)(kA & 63) << 1) ^ CA2);
                        uint32_t aB  = PB2 + ((uint32_t)(kB >> 6) << 12)
                                           + (((uint32_t)(kB & 63) << 1) ^ CB2);
                        uint32_t a2h[4], a2l[4], b0, b1;
                        LDSM4(a2h[0], a2h[1], a2h[2], a2h[3], aAh);
                        LDSM4(a2l[0], a2l[1], a2l[2], a2l[3], aAl);
                        LDSM2(b0, b1, aB);
                        mma_f16(acc2, a2h, b0, b1);
                        mma_f16(acc2, a2l, b0, b1);
                    }
                    int cb2 = ch * 32 + w * 8 + 2 * (lane & 3);
                    int gr0 = lane >> 2;
                    if (gr0 * 8 < n_rows)
                        *(float2*)(g_uh + (size_t)(pbase + gr0) * NIOU + cb2) =
                            make_float2(acc2[0], acc2[1]);
                    if ((gr0 + 8) * 8 < n_rows)
                        *(float2*)(g_uh + (size_t)(pbase + gr0 + 8) * NIOU + cb2) =
                            make_float2(acc2[2], acc2[3]);
                }
            }
        } else {
            // two GEMM2b chunks: f = sigmoid(h@U_f + xf[par]); fc = f*c; reduce
            int cf0 = st_start(s) - 24;    // 0 or 2
            mma_chunk32(sb, B0, accI, wm, wn, lane);
            mma_chunk32(sb, B0 + CHUNK_BYTES, accO, wm, wn, lane);
#pragma unroll
            for (int jj = 0; jj < 2; jj++) {
#pragma unroll
                for (int mi = 0; mi < 2; mi++)
#pragma unroll
                for (int nn = 0; nn < 2; nn++) {
                    int cfl = (cf0 + jj) * 32 + wn * 16 + nn * 8 + 2 * q;
                    float v[4];
#pragma unroll
                    for (int rh = 0; rh < 2; rh++) {
                        int lr = wm * 32 + mi * 16 + g + rh * 8;
                        int rg = base + lr;
                        float a0 = jj ? accO[mi][nn][rh*2]   : accI[mi][nn][rh*2];
                        float a1 = jj ? accO[mi][nn][rh*2+1] : accI[mi][nn][rh*2+1];
                        if (lr < n_rows) {
                            int pr = (rg - 1) >> 3;
                            float2 xf2 = *(const float2*)(g_xf + (size_t)pr * HH + cfl);
                            float2 c2  = *(const float2*)(g_c  + (size_t)rg * HH + cfl);
                            v[rh*2]   = sigf(a0 + xf2.x) * c2.x;
                            v[rh*2+1] = sigf(a1 + xf2.y) * c2.y;
                        } else { v[rh*2] = 0.f; v[rh*2+1] = 0.f; }
                    }
#pragma unroll
                    for (int r = 0; r < 4; r++) {
                        float sv = v[r];
                        sv += __shfl_xor_sync(0xffffffffu, sv, 4);
                        sv += __shfl_xor_sync(0xffffffffu, sv, 8);
                        sv += __shfl_xor_sync(0xffffffffu, sv, 16);
                        v[r] = sv;
                    }
                    if (lane < 4) {
#pragma unroll
                        for (int rh = 0; rh < 2; rh++) {
                            int lr0 = wm * 32 + mi * 16 + rh * 8;
                            if (lr0 < n_rows) {
                                int pr = (base + lr0 - 1) >> 3;
                                *(float2*)(g_fc + (size_t)pr * HH + cfl) =
                                    make_float2(v[rh*2], v[rh*2+1]);
                            }
                        }
                    }
                }
            }
            zacc(accI); zacc(accO);
        }
    }
}

// ---------------------------------------------------------------------------
// Output kernel: 64-row tiles, occupancy 2, 4 paired steps
// out = tanh(LN(h @ W_out + b_out) * gamma + beta)
// ---------------------------------------------------------------------------
__global__ __launch_bounds__(256, 2)
void out_mm(const float* __restrict__ b_out, const float* __restrict__ gamma,
            const float* __restrict__ beta, float* __restrict__ out) {
    extern __shared__ __align__(1024) char smem[];
    uint32_t sb = smem_to_u32(smem);
    int t = threadIdx.x, lane = t & 31, w = t >> 5;
    int wm = w & 1, wn = w >> 1;           // 2 x 4 warp grid
    int q = lane & 3, g = lane >> 2;
    int base = (int)blockIdx.x << 6;
    int n_rows = NN - base; if (n_rows > 64) n_rows = 64;

    // step 0 group: chunks 0,1 -> slots 0,1
    cp_chunk(sb + SM_OB, (const uint4*)g_Wout_sw, t);
    cp_chunk(sb + SM_OB + CHUNK_BYTES, g_Wout_sw + CHUNK_U4, t);

    build_tile64(smem, g_h, (size_t)base, n_rows, t);

    float acc8[8][2][4];
#pragma unroll
    for (int c = 0; c < 8; c++)
#pragma unroll
        for (int i = 0; i < 2; i++)
#pragma unroll
            for (int k = 0; k < 4; k++) acc8[c][i][k] = 0.f;

    for (int s = 0; s < 4; s++) {
        CP_WAIT0();
        __syncthreads();
        if (s + 1 < 4) {
            uint32_t slot = (uint32_t)(((s + 1) & 1) * 2);
            cp_chunk(sb + SM_OB + slot * CHUNK_BYTES,
                     g_Wout_sw + (size_t)(2 * s + 2) * CHUNK_U4, t);
            cp_chunk(sb + SM_OB + (slot + 1) * CHUNK_BYTES,
                     g_Wout_sw + (size_t)(2 * s + 3) * CHUNK_U4, t);
        }
        uint32_t B0 = sb + SM_OB + (uint32_t)((s & 1) * 2) * CHUNK_BYTES;
        mma_chunk64(sb, B0, acc8[2 * s], wm, wn, lane);
        mma_chunk64(sb, B0 + CHUNK_BYTES, acc8[2 * s + 1], wm, wn, lane);
    }

    // bias + per-row partial sums
    float s2[2][2] = {{0.f,0.f},{0.f,0.f}}, sq[2][2] = {{0.f,0.f},{0.f,0.f}};
#pragma unroll
    for (int ch = 0; ch < 8; ch++) {
        int cb = ch * 32 + wn * 8 + 2 * q;
        float b0 = __ldg(b_out + cb), b1 = __ldg(b_out + cb + 1);
#pragma unroll
        for (int mi = 0; mi < 2; mi++)
#pragma unroll
        for (int rh = 0; rh < 2; rh++) {
            float y0 = (acc8[ch][mi][rh*2]   += b0);
            float y1 = (acc8[ch][mi][rh*2+1] += b1);
            s2[mi][rh] += y0 + y1;
            sq[mi][rh] += y0 * y0 + y1 * y1;
        }
    }
#pragma unroll
    for (int mi = 0; mi < 2; mi++)
#pragma unroll
    for (int rh = 0; rh < 2; rh++) {
        s2[mi][rh] += __shfl_xor_sync(0xffffffffu, s2[mi][rh], 1);
        s2[mi][rh] += __shfl_xor_sync(0xffffffffu, s2[mi][rh], 2);
        sq[mi][rh] += __shfl_xor_sync(0xffffffffu, sq[mi][rh], 1);
        sq[mi][rh] += __shfl_xor_sync(0xffffffffu, sq[mi][rh], 2);
    }
    float2* part = (float2*)(smem + SM_OPART);   // [64][4]
    __syncthreads();
    if (q == 0) {
#pragma unroll
        for (int mi = 0; mi < 2; mi++)
#pragma unroll
        for (int rh = 0; rh < 2; rh++) {
            int lr = wm * 32 + mi * 16 + g + rh * 8;
            part[lr * 4 + wn] = make_float2(s2[mi][rh], sq[mi][rh]);
        }
    }
    __syncthreads();
    float mu[2][2], rs[2][2];
#pragma unroll
    for (int mi = 0; mi < 2; mi++)
#pragma unroll
    for (int rh = 0; rh < 2; rh++) {
        int lr = wm * 32 + mi * 16 + g + rh * 8;
        float ssum = 0.f, qsum = 0.f;
#pragma unroll
        for (int j = 0; j < 4; j++) {
            float2 p = part[lr * 4 + j];
            ssum += p.x; qsum += p.y;
        }
        float m = ssum * (1.f / 256.f);
        float var = qsum * (1.f / 256.f) - m * m;
        mu[mi][rh] = m;
        rs[mi][rh] = rsqrtf(var + 1e-5f);
    }
#pragma unroll
    for (int ch = 0; ch < 8; ch++) {
        int cb = ch * 32 + wn * 8 + 2 * q;
        float g0 = __ldg(gamma + cb), g1 = __ldg(gamma + cb + 1);
        float e0 = __ldg(beta + cb),  e1 = __ldg(beta + cb + 1);
#pragma unroll
        for (int mi = 0; mi < 2; mi++)
#pragma unroll
        for (int rh = 0; rh < 2; rh++) {
            int lr = wm * 32 + mi * 16 + g + rh * 8;
            if (lr < n_rows) {
                float y0 = (acc8[ch][mi][rh*2]   - mu[mi][rh]) * rs[mi][rh] * g0 + e0;
                float y1 = (acc8[ch][mi][rh*2+1] - mu[mi][rh]) * rs[mi][rh] * g1 + e1;
                *(float2*)(out + (size_t)(base + lr) * DDEC + cb) =
                    make_float2(tanh_fast(y0), tanh_fast(y1));
            }
        }
    }
}

// ---------------------------------------------------------------------------
// x_f precompute (FFMA, small): g_xf[r] = x[r] @ W_f + b_f  for r < NPAR
// ---------------------------------------------------------------------------
#define TS 68
__global__ void xf_kernel(const float* __restrict__ x, const float* __restrict__ W_f,
                          const float* __restrict__ b_f) {
    extern __shared__ float sm[];
    float* As = sm;
    float* Ws = sm + 128 * TS;
    int t = threadIdx.x;
    int base = blockIdx.x << 6;
    int n_rows = NPAR - base; if (n_rows > 64) n_rows = 64;
    int m0 = (t & 15) * 4, c0 = (t >> 4) * 4;

#pragma unroll
    for (int i = 0; i < 32; i++) {
        int idx = t + 256 * i;
        int m = idx >> 7, k = idx & 127;
        float v = 0.f;
        if (m < n_rows) v = x[(size_t)(base + m) * HH + k];
        As[k * TS + m] = v;
    }
    for (int ch = 0; ch < 2; ch++) {
        __syncthreads();
#pragma unroll
        for (int i = 0; i < 32; i++) {
            int idx = t + 256 * i;
            int k = idx >> 6, c = idx & 63;
            Ws[k * TS + c] = W_f[k * HH + ch * 64 + c];
        }
        __syncthreads();
        float acc[4][4] = {};
#pragma unroll 8
        for (int k = 0; k < 128; k++) {
            float4 a = *(const float4*)(As + k * TS + m0);
            float4 b = *(const float4*)(Ws + k * TS + c0);
            acc[0][0] += a.x*b.x; acc[0][1] += a.x*b.y; acc[0][2] += a.x*b.z; acc[0][3] += a.x*b.w;
            acc[1][0] += a.y*b.x; acc[1][1] += a.y*b.y; acc[1][2] += a.y*b.z; acc[1][3] += a.y*b.w;
            acc[2][0] += a.z*b.x; acc[2][1] += a.z*b.y; acc[2][2] += a.z*b.z; acc[2][3] += a.z*b.w;
            acc[3][0] += a.w*b.x; acc[3][1] += a.w*b.y; acc[3][2] += a.w*b.z; acc[3][3] += a.w*b.w;
        }
#pragma unroll
        for (int i = 0; i < 4; i++)
#pragma unroll
            for (int j = 0; j < 4; j++) {
                int m = m0 + i, cc = ch * 64 + c0 + j;
                if (m < n_rows)
                    g_xf[(size_t)(base + m) * HH + cc] = acc[i][j] + b_f[cc];
            }
    }
}

// ---------------------------------------------------------------------------
extern "C" void kernel_launch(void* const* d_in, const int* in_sizes, int n_in,
                              void* d_out, int out_size) {
    const float* x = (const float*)d_in[0];
    int wi = 3;
    if (n_in > 3 && in_sizes[3] <= 1) wi = 4;
    const float* W_iou = (const float*)d_in[wi + 0];
    const float* b_iou = (const float*)d_in[wi + 1];
    const float* U_iou = (const float*)d_in[wi + 2];
    const float* W_f   = (const float*)d_in[wi + 3];
    const float* b_f   = (const float*)d_in[wi + 4];
    const float* U_f   = (const float*)d_in[wi + 5];
    const float* W_out = (const float*)d_in[wi + 6];
    const float* b_out = (const float*)d_in[wi + 7];
    const float* gamma = (const float*)d_in[wi + 8];
    const float* beta  = (const float*)d_in[wi + 9];
    float* out = (float*)d_out;

    cudaFuncSetAttribute(level_mm, cudaFuncAttributeMaxDynamicSharedMemorySize, SM_LVL);
    cudaFuncSetAttribute(out_mm,   cudaFuncAttributeMaxDynamicSharedMemorySize, SM_OUT);
    cudaFuncSetAttribute(xf_kernel, cudaFuncAttributeMaxDynamicSharedMemorySize,
                         (2 * 128 * TS) * (int)sizeof(float));

    prep_all<<<576, 256>>>(W_iou, U_iou, U_f, W_out);
    xf_kernel<<<(NPAR + 63) / 64, 256, (2 * 128 * TS) * sizeof(float)>>>(x, W_f, b_f);

    const int off[8] = {0, 1, 9, 73, 585, 4681, 37449, 299593};
    for (int l = 6; l >= 0; l--) {
        int base = off[l], n = off[l + 1] - off[l];
        int blocks = (n + 127) / 128;
        level_mm<<<blocks, 256, SM_LVL>>>(x, b_iou, base, n,
                                          (l < 6) ? 1 : 0, (l > 0) ? 1 : 0);
    }
    out_mm<<<(NN + 63) / 64, 256, SM_OUT>>>(b_out, gamma, beta, out);
}

// round 14
// speedup vs baseline: 5.3162x; 1.2271x over previous
#include <cuda_runtime.h>
#include <cuda_fp16.h>
#include <math.h>
#include <stdint.h>

// ---------------------------------------------------------------------------
// Problem constants
// ---------------------------------------------------------------------------
#define NN    299593      // total nodes, complete 8-ary tree, 7 levels
#define HH    128         // D_ENC == D_EMB
#define NIOU  384         // 3*H
#define DDEC  256
#define NPAR  37449       // nodes at levels 0..5 (all parents)

#define CHUNK_BYTES 8192  // one pre-swizzled B chunk: 32 N-rows x 128 K x fp16
#define CHUNK_U4    (CHUNK_BYTES / 16)

// Scratch (device globals: allocation-free per harness rules)
__device__ float g_h [(size_t)NN  * HH];
__device__ float g_c [(size_t)NN  * HH];
__device__ float g_xf[(size_t)NPAR * HH];
__device__ float g_uh[(size_t)NPAR * NIOU];
__device__ float g_fc[(size_t)NPAR * HH];

// Pre-swizzled fp16 weight blobs (single-rounded), 32-row x 128-K chunks
__device__ uint4 g_Wiou_sw[12 * CHUNK_U4];
__device__ uint4 g_U_sw   [16 * CHUNK_U4];  // [U_iou(384) | U_f(128)] cols
__device__ uint4 g_Wout_sw[ 8 * CHUNK_U4];

// ---------------------------------------------------------------------------
// Helpers
// ---------------------------------------------------------------------------
__device__ __forceinline__ uint32_t smem_to_u32(const void* p) {
    uint32_t a;
    asm("{ .reg .u64 t; cvta.to.shared.u64 t, %1; cvt.u32.u64 %0, t; }" : "=r"(a) : "l"(p));
    return a;
}
__device__ __forceinline__ uint32_t swz(uint32_t o) { return o ^ ((o >> 3) & 0x70); }
__device__ __forceinline__ uint32_t offA(int row, int k) {   // 128-row tile: 16 atoms/kblk
    return swz((uint32_t)(((row >> 3) + (k >> 6) * 16) * 1024 + (row & 7) * 128 + (k & 63) * 2));
}
__device__ __forceinline__ uint32_t offA64(int row, int k) { // 64-row tile: 8 atoms/kblk
    return swz((uint32_t)(((row >> 3) + (k >> 6) * 8) * 1024 + (row & 7) * 128 + (k & 63) * 2));
}
__device__ __forceinline__ uint32_t offA16(int row, int k) { // 16-row tile: 2 atoms/kblk
    return swz((uint32_t)(((row >> 3) + (k >> 6) * 2) * 1024 + (row & 7) * 128 + (k & 63) * 2));
}
__device__ __forceinline__ uint32_t offB32(int row, int k) { // 32-row tile: 4 atoms/kblk
    return swz((uint32_t)(((row >> 3) + (k >> 6) * 4) * 1024 + (row & 7) * 128 + (k & 63) * 2));
}
__device__ __forceinline__ uint32_t packh2(float a, float b) {
    __half2 h = __floats2half2_rn(a, b);
    return *reinterpret_cast<uint32_t*>(&h);
}
__device__ __forceinline__ float sigf(float v) {
    return __fdividef(1.0f, 1.0f + __expf(-v));
}
__device__ __forceinline__ float tanh_fast(float x) {
    float t = __expf(2.0f * x);
    return 1.0f - __fdividef(2.0f, t + 1.0f);
}

#define LDSM4(R0, R1, R2, R3, ADDR) \
    asm volatile("ldmatrix.sync.aligned.m8n8.x4.shared.b16 {%0,%1,%2,%3}, [%4];" \
                 : "=r"(R0), "=r"(R1), "=r"(R2), "=r"(R3) : "r"(ADDR))
#define LDSM2(R0, R1, ADDR) \
    asm volatile("ldmatrix.sync.aligned.m8n8.x2.shared.b16 {%0,%1}, [%2];" \
                 : "=r"(R0), "=r"(R1) : "r"(ADDR))

__device__ __forceinline__ void mma_f16(float (&d)[4], const uint32_t (&a)[4],
                                        uint32_t b0, uint32_t b1) {
    asm volatile("mma.sync.aligned.m16n8k16.row.col.f32.f16.f16.f32 "
                 "{%0,%1,%2,%3}, {%4,%5,%6,%7}, {%8,%9}, {%0,%1,%2,%3};"
                 : "+f"(d[0]), "+f"(d[1]), "+f"(d[2]), "+f"(d[3])
                 : "r"(a[0]), "r"(a[1]), "r"(a[2]), "r"(a[3]), "r"(b0), "r"(b1));
}

__device__ __forceinline__ void zacc(float (&a)[2][2][4]) {
#pragma unroll
    for (int i = 0; i < 2; i++)
#pragma unroll
        for (int j = 0; j < 2; j++)
#pragma unroll
            for (int k = 0; k < 4; k++) a[i][j][k] = 0.f;
}

// One 32-col chunk: per-warp C[m32 x n16] += A[128x128] * B[32x128]^T
// pure fp16 (A and B single-rounded), fp32 accumulate: 3 LDSM4 -> 4 HMMAs/kstep
__device__ __forceinline__ void mma_chunk32(uint32_t Abase, uint32_t Bbase,
                                            float (&acc)[2][2][4],
                                            int wm, int wn, int lane) {
    int rA = wm * 32 + (lane & 15);
    uint32_t PA = Abase + ((rA >> 3) << 10) + ((rA & 7) << 7);
    uint32_t CA = (rA & 7) << 4;
    int aK = (lane >> 4) << 3;
    int nB = wn * 16 + (((lane >> 4) & 1) << 3) + (lane & 7);
    uint32_t PB = Bbase + ((nB >> 3) << 10) + ((nB & 7) << 7);
    uint32_t CB = (nB & 7) << 4;
    int bK = ((lane >> 3) & 1) << 3;
#pragma unroll
    for (int s = 0; s < 8; s++) {
        int kA = (s << 4) + aK;
        int kB = (s << 4) + bK;
        uint32_t aAh = PA + ((uint32_t)(kA >> 6) << 14) + ((uint32_t)((kA & 63) << 1) ^ CA);
        uint32_t aBh = PB + ((uint32_t)(kB >> 6) << 12) + ((uint32_t)((kB & 63) << 1) ^ CB);
        uint32_t ah0[4], ah1[4], bh[4];
        LDSM4(ah0[0], ah0[1], ah0[2], ah0[3], aAh);
        LDSM4(ah1[0], ah1[1], ah1[2], ah1[3], aAh + 2048);
        LDSM4(bh[0], bh[1], bh[2], bh[3], aBh);
        mma_f16(acc[0][0], ah0, bh[0], bh[1]);
        mma_f16(acc[1][0], ah1, bh[0], bh[1]);
        mma_f16(acc[0][1], ah0, bh[2], bh[3]);
        mma_f16(acc[1][1], ah1, bh[2], bh[3]);
    }
}

// 64-row-tile variant: per-warp C[m32 x n8], warps 2(wm) x 4(wn)
__device__ __forceinline__ void mma_chunk64(uint32_t Abase, uint32_t Bbase,
                                            float (&acc)[2][4],
                                            int wm, int wn, int lane) {
    int rA = wm * 32 + (lane & 15);
    uint32_t PA = Abase + ((rA >> 3) << 10) + ((rA & 7) << 7);
    uint32_t CA = (rA & 7) << 4;
    int aK = (lane >> 4) << 3;
    int nB = wn * 8 + (lane & 7);
    uint32_t PB = Bbase + ((nB >> 3) << 10) + ((nB & 7) << 7);
    uint32_t CB = (nB & 7) << 4;
    int bK = ((lane >> 3) & 1) << 3;
#pragma unroll
    for (int s = 0; s < 8; s++) {
        int kA = (s << 4) + aK;
        int kB = (s << 4) + bK;
        uint32_t aAh = PA + ((uint32_t)(kA >> 6) << 13) + ((uint32_t)((kA & 63) << 1) ^ CA);
        uint32_t aB  = PB + ((uint32_t)(kB >> 6) << 12) + ((uint32_t)((kB & 63) << 1) ^ CB);
        uint32_t ah0[4], ah1[4], b0, b1;
        LDSM4(ah0[0], ah0[1], ah0[2], ah0[3], aAh);
        LDSM4(ah1[0], ah1[1], ah1[2], ah1[3], aAh + 2048);
        LDSM2(b0, b1, aB);
        mma_f16(acc[0], ah0, b0, b1);
        mma_f16(acc[1], ah1, b0, b1);
    }
}

// ---------------------------------------------------------------------------
// cp.async: one 8KB chunk, 256 threads x 2 x 16B, one commit group
// ---------------------------------------------------------------------------
__device__ __forceinline__ void cp_chunk(uint32_t dst, const uint4* src, int t) {
    const char* s = (const char*)src;
#pragma unroll
    for (int i = 0; i < 2; i++)
        asm volatile("cp.async.cg.shared.global [%0], [%1], 16;"
                     :: "r"(dst + (uint32_t)(t * 16 + i * 4096)),
                        "l"(s + t * 16 + i * 4096) : "memory");
    asm volatile("cp.async.commit_group;" ::: "memory");
}
#define CP_WAIT0() asm volatile("cp.async.wait_group 0;" ::: "memory")

// ---------------------------------------------------------------------------
// Weight prep (single launch): fp16 round + swizzle all four blobs
// ---------------------------------------------------------------------------
__global__ void prep_all(const float* __restrict__ W_iou, const float* __restrict__ U_iou,
                         const float* __restrict__ U_f, const float* __restrict__ W_out) {
    int b = blockIdx.x;
    const float* src; int ncols, dst_id, chunkoff, rel;
    if (b < 192)      { src = W_iou; ncols = 384; dst_id = 0; chunkoff = 0;  rel = b; }
    else if (b < 384) { src = U_iou; ncols = 384; dst_id = 1; chunkoff = 0;  rel = b - 192; }
    else if (b < 448) { src = U_f;   ncols = 128; dst_id = 1; chunkoff = 12; rel = b - 384; }
    else              { src = W_out; ncols = 256; dst_id = 2; chunkoff = 0;  rel = b - 448; }
    int idx = rel * 256 + threadIdx.x;
    if (idx >= 128 * ncols) return;
    int k = idx / ncols, n = idx - k * ncols;
    float v = src[k * ncols + n];
    unsigned short hu = __half_as_ushort(__float2half_rn(v));
    unsigned char* bb = (dst_id == 0) ? (unsigned char*)g_Wiou_sw
                      : (dst_id == 1) ? (unsigned char*)g_U_sw
                                      : (unsigned char*)g_Wout_sw;
    unsigned char* blob = bb + (size_t)(chunkoff + (n >> 5)) * CHUNK_BYTES;
    int row = n & 31;
    *(unsigned short*)(blob + offB32(row, k)) = hu;
}

// ---------------------------------------------------------------------------
// Level kernel SMEM (occ 2): A [0,32768) | A2 [32768,36864) | ring [36864,69632)
// Out kernel SMEM: A64 [0,16384) | ring [16384,49152) | part [49152,51200)
// ---------------------------------------------------------------------------
#define SM_A2    32768
#define SM_B     36864
#define SM_LVL   69632
#define SM_OB    16384
#define SM_OPART 49152
#define SM_OUT   51200

// build a 128x128 fp16 tile from fp32 rows (src row-major, HH cols)
__device__ __forceinline__ void build_tile(char* Ac, const float* src, size_t base,
                                           int n_rows, int t) {
    int row = t >> 1, kh = (t & 1) << 6;
    bool val = row < n_rows;
    const float4* xr = (const float4*)(src + (base + row) * HH + kh);
#pragma unroll
    for (int gg = 0; gg < 8; gg++) {
        float v[8];
        if (val) {
            float4 a = xr[gg * 2], b = xr[gg * 2 + 1];
            v[0]=a.x; v[1]=a.y; v[2]=a.z; v[3]=a.w; v[4]=b.x; v[5]=b.y; v[6]=b.z; v[7]=b.w;
        } else {
#pragma unroll
            for (int q = 0; q < 8; q++) v[q] = 0.f;
        }
        *(uint4*)(Ac + offA(row, kh + gg * 8)) =
            make_uint4(packh2(v[0], v[1]), packh2(v[2], v[3]),
                       packh2(v[4], v[5]), packh2(v[6], v[7]));
    }
}

// 64-row variant (4 threads per row, 32 K each)
__device__ __forceinline__ void build_tile64(char* Ac, const float* src, size_t base,
                                             int n_rows, int t) {
    int row = t >> 2, kh = (t & 3) << 5;
    bool val = row < n_rows;
    const float4* xr = (const float4*)(src + (base + row) * HH + kh);
#pragma unroll
    for (int gg = 0; gg < 4; gg++) {
        float v[8];
        if (val) {
            float4 a = xr[gg * 2], b = xr[gg * 2 + 1];
            v[0]=a.x; v[1]=a.y; v[2]=a.z; v[3]=a.w; v[4]=b.x; v[5]=b.y; v[6]=b.z; v[7]=b.w;
        } else {
#pragma unroll
            for (int q = 0; q < 8; q++) v[q] = 0.f;
        }
        *(uint4*)(Ac + offA64(row, kh + gg * 8)) =
            make_uint4(packh2(v[0], v[1]), packh2(v[2], v[3]),
                       packh2(v[4], v[5]), packh2(v[6], v[7]));
    }
}

// chunk c -> blob source (0..11 GEMM1, 12..27 GEMM2)
__device__ __forceinline__ const uint4* lvl_src(int c) {
    if (c < 12) {
        int p = c / 3, sub = c - p * 3;              // blob chunk = sub*4 + p
        return g_Wiou_sw + (size_t)(sub * 4 + p) * CHUNK_U4;
    }
    return g_U_sw + (size_t)(c - 12) * CHUNK_U4;
}
// step s -> first chunk / count  (s<8: GEMM1 pairs (I,O),(U); s>=8: pairs of 2)
__device__ __forceinline__ int st_start(int s) {
    return (s < 8) ? s + ((s + 1) >> 1) : 12 + (s - 8) * 2;
}
__device__ __forceinline__ int st_cnt(int s) {
    return (s < 8) ? ((s & 1) ? 1 : 2) : 2;
}
__device__ __forceinline__ void issue_group(uint32_t sb, int s, int t) {
    int st = st_start(s), cn = st_cnt(s);
    uint32_t slot = (uint32_t)((s & 1) * 2);
    for (int j = 0; j < cn; j++)
        cp_chunk(sb + SM_B + (slot + j) * CHUNK_BYTES, lvl_src(st + j), t);
}

// ---------------------------------------------------------------------------
// Fused per-level kernel: one CTA per 128-row tile, 256 threads, 2 CTAs/SM
// ---------------------------------------------------------------------------
__global__ __launch_bounds__(256, 2)
void level_mm(const float* __restrict__ x, const float* __restrict__ b_iou,
              int base0, int n_total, int read_sums, int has_parent) {
    extern __shared__ __align__(1024) char smem[];
    uint32_t sb = smem_to_u32(smem);
    int t = threadIdx.x, lane = t & 31, w = t >> 5;
    int wm = w & 3, wn = w >> 2;
    int q = lane & 3, g = lane >> 2;
    int base = base0 + ((int)blockIdx.x << 7);
    int n_rows = n_total - ((int)blockIdx.x << 7); if (n_rows > 128) n_rows = 128;
    int pbase = (base - 1) >> 3;
    const int n_steps = has_parent ? 16 : 8;

    issue_group(sb, 0, t);
    build_tile(smem, x, (size_t)base, n_rows, t);

    float accI[2][2][4], accO[2][2][4], accU[2][2][4];
    zacc(accI); zacc(accO); zacc(accU);

    for (int s = 0; s < n_steps; s++) {
        CP_WAIT0();
        __syncthreads();               // group s landed; prior step's reads done
        if (s + 1 < n_steps) issue_group(sb, s + 1, t);
        uint32_t B0 = sb + SM_B + (uint32_t)((s & 1) * 2) * CHUNK_BYTES;

        if (s < 8) {
            if (!(s & 1)) {
                mma_chunk32(sb, B0, accI, wm, wn, lane);
                mma_chunk32(sb, B0 + CHUNK_BYTES, accO, wm, wn, lane);
            } else {
                mma_chunk32(sb, B0, accU, wm, wn, lane);
                int p = s >> 1;
                // epilogue1 for pass p: gates -> c,h (global) + A2 sibling sums
#pragma unroll
                for (int mi = 0; mi < 2; mi++)
#pragma unroll
                for (int nn = 0; nn < 2; nn++) {
                    int cp = p * 32 + wn * 16 + nn * 8 + 2 * q;
                    float bi0 = __ldg(b_iou + cp),       bi1 = __ldg(b_iou + cp + 1);
                    float bo0 = __ldg(b_iou + 128 + cp), bo1 = __ldg(b_iou + 129 + cp);
                    float bu0 = __ldg(b_iou + 256 + cp), bu1 = __ldg(b_iou + 257 + cp);
#pragma unroll
                    for (int rh = 0; rh < 2; rh++) {
                        int lr = wm * 32 + mi * 16 + g + rh * 8;
                        int rg = base + lr;
                        bool val = lr < n_rows;
                        float2 ui = make_float2(0.f, 0.f), uo = ui, uu = ui, fc = ui;
                        if (val && read_sums) {
                            const float* uh = g_uh + (size_t)rg * NIOU + cp;
                            ui = *(const float2*)(uh);
                            uo = *(const float2*)(uh + 128);
                            uu = *(const float2*)(uh + 256);
                            fc = *(const float2*)(g_fc + (size_t)rg * HH + cp);
                        }
                        float c0 = sigf(accI[mi][nn][rh*2]   + bi0 + ui.x) *
                                   tanh_fast(accU[mi][nn][rh*2]   + bu0 + uu.x) + fc.x;
                        float c1 = sigf(accI[mi][nn][rh*2+1] + bi1 + ui.y) *
                                   tanh_fast(accU[mi][nn][rh*2+1] + bu1 + uu.y) + fc.y;
                        float h0 = sigf(accO[mi][nn][rh*2]   + bo0 + uo.x) * tanh_fast(c0);
                        float h1 = sigf(accO[mi][nn][rh*2+1] + bo1 + uo.y) * tanh_fast(c1);
                        if (val) {
                            *(float2*)(g_c + (size_t)rg * HH + cp) = make_float2(c0, c1);
                            *(float2*)(g_h + (size_t)rg * HH + cp) = make_float2(h0, h1);
                        }
                        if (has_parent) {
                            float hs0 = val ? h0 : 0.f, hs1 = val ? h1 : 0.f;
                            hs0 += __shfl_xor_sync(0xffffffffu, hs0, 4);
                            hs0 += __shfl_xor_sync(0xffffffffu, hs0, 8);
                            hs0 += __shfl_xor_sync(0xffffffffu, hs0, 16);
                            hs1 += __shfl_xor_sync(0xffffffffu, hs1, 4);
                            hs1 += __shfl_xor_sync(0xffffffffu, hs1, 8);
                            hs1 += __shfl_xor_sync(0xffffffffu, hs1, 16);
                            if (lane < 4) {
                                int row2 = 4 * wm + 2 * mi + rh;
                                *(uint32_t*)(smem + SM_A2 + offA16(row2, cp)) =
                                    packh2(hs0, hs1);
                            }
                        }
                    }
                }
                zacc(accI); zacc(accO); zacc(accU);
                if (s == 7 && has_parent) {
                    __syncthreads();           // all warps done reading A (GEMM1)
                    build_tile(smem, g_h, (size_t)base, n_rows, t);
                }
            }
        } else if (s < 14) {
            // two tiny GEMM2a chunks: Uh_sum[16 rows] = hsum @ U_iou
            int ch0 = st_start(s) - 12;
            if (w < 4) {
#pragma unroll
                for (int jj = 0; jj < 2; jj++) {
                    int ch = ch0 + jj;
                    uint32_t Bb = B0 + (uint32_t)jj * CHUNK_BYTES;
                    float acc2[4] = {0.f, 0.f, 0.f, 0.f};
                    int rA2 = lane & 15;
                    uint32_t PA2 = (sb + SM_A2) + ((uint32_t)(rA2 >> 3) << 10)
                                                + ((uint32_t)(rA2 & 7) << 7);
                    uint32_t CA2 = (rA2 & 7) << 4;
                    int aK = (lane >> 4) << 3;
                    int nB2 = w * 8 + (lane & 7);
                    uint32_t PB2 = Bb + ((uint32_t)(nB2 >> 3) << 10)
                                      + ((uint32_t)(nB2 & 7) << 7);
                    uint32_t CB2 = (nB2 & 7) << 4;
                    int kB2 = ((lane >> 3) & 1) << 3;
#pragma unroll
                    for (int ks = 0; ks < 8; ks++) {
                        int kA = (ks << 4) + aK;
                        int kB = (ks << 4) + kB2;
                        uint32_t aAh = PA2 + ((uint32_t)(kA >> 6) << 11)
                                           + (((uint32_t)(kA & 63) << 1) ^ CA2);
                        uint32_t aB  = PB2 + ((uint32_t)(kB >> 6) << 12)
                                           + (((uint32_t)(kB & 63) << 1) ^ CB2);
                        uint32_t a2h[4], b0, b1;
                        LDSM4(a2h[0], a2h[1], a2h[2], a2h[3], aAh);
                        LDSM2(b0, b1, aB);
                        mma_f16(acc2, a2h, b0, b1);
                    }
                    int cb2 = ch * 32 + w * 8 + 2 * (lane & 3);
                    int gr0 = lane >> 2;
                    if (gr0 * 8 < n_rows)
                        *(float2*)(g_uh + (size_t)(pbase + gr0) * NIOU + cb2) =
                            make_float2(acc2[0], acc2[1]);
                    if ((gr0 + 8) * 8 < n_rows)
                        *(float2*)(g_uh + (size_t)(pbase + gr0 + 8) * NIOU + cb2) =
                            make_float2(acc2[2], acc2[3]);
                }
            }
        } else {
            // two GEMM2b chunks: f = sigmoid(h@U_f + xf[par]); fc = f*c; reduce
            int cf0 = st_start(s) - 24;    // 0 or 2
            mma_chunk32(sb, B0, accI, wm, wn, lane);
            mma_chunk32(sb, B0 + CHUNK_BYTES, accO, wm, wn, lane);
#pragma unroll
            for (int jj = 0; jj < 2; jj++) {
#pragma unroll
                for (int mi = 0; mi < 2; mi++)
#pragma unroll
                for (int nn = 0; nn < 2; nn++) {
                    int cfl = (cf0 + jj) * 32 + wn * 16 + nn * 8 + 2 * q;
                    float v[4];
#pragma unroll
                    for (int rh = 0; rh < 2; rh++) {
                        int lr = wm * 32 + mi * 16 + g + rh * 8;
                        int rg = base + lr;
                        float a0 = jj ? accO[mi][nn][rh*2]   : accI[mi][nn][rh*2];
                        float a1 = jj ? accO[mi][nn][rh*2+1] : accI[mi][nn][rh*2+1];
                        if (lr < n_rows) {
                            int pr = (rg - 1) >> 3;
                            float2 xf2 = *(const float2*)(g_xf + (size_t)pr * HH + cfl);
                            float2 c2  = *(const float2*)(g_c  + (size_t)rg * HH + cfl);
                            v[rh*2]   = sigf(a0 + xf2.x) * c2.x;
                            v[rh*2+1] = sigf(a1 + xf2.y) * c2.y;
                        } else { v[rh*2] = 0.f; v[rh*2+1] = 0.f; }
                    }
#pragma unroll
                    for (int r = 0; r < 4; r++) {
                        float sv = v[r];
                        sv += __shfl_xor_sync(0xffffffffu, sv, 4);
                        sv += __shfl_xor_sync(0xffffffffu, sv, 8);
                        sv += __shfl_xor_sync(0xffffffffu, sv, 16);
                        v[r] = sv;
                    }
                    if (lane < 4) {
#pragma unroll
                        for (int rh = 0; rh < 2; rh++) {
                            int lr0 = wm * 32 + mi * 16 + rh * 8;
                            if (lr0 < n_rows) {
                                int pr = (base + lr0 - 1) >> 3;
                                *(float2*)(g_fc + (size_t)pr * HH + cfl) =
                                    make_float2(v[rh*2], v[rh*2+1]);
                            }
                        }
                    }
                }
            }
            zacc(accI); zacc(accO);
        }
    }
}

// ---------------------------------------------------------------------------
// Output kernel: 64-row tiles, occupancy 2, 4 paired steps
// ---------------------------------------------------------------------------
__global__ __launch_bounds__(256, 2)
void out_mm(const float* __restrict__ b_out, const float* __restrict__ gamma,
            const float* __restrict__ beta, float* __restrict__ out) {
    extern __shared__ __align__(1024) char smem[];
    uint32_t sb = smem_to_u32(smem);
    int t = threadIdx.x, lane = t & 31, w = t >> 5;
    int wm = w & 1, wn = w >> 1;           // 2 x 4 warp grid
    int q = lane & 3, g = lane >> 2;
    int base = (int)blockIdx.x << 6;
    int n_rows = NN - base; if (n_rows > 64) n_rows = 64;

    cp_chunk(sb + SM_OB, (const uint4*)g_Wout_sw, t);
    cp_chunk(sb + SM_OB + CHUNK_BYTES, g_Wout_sw + CHUNK_U4, t);

    build_tile64(smem, g_h, (size_t)base, n_rows, t);

    float acc8[8][2][4];
#pragma unroll
    for (int c = 0; c < 8; c++)
#pragma unroll
        for (int i = 0; i < 2; i++)
#pragma unroll
            for (int k = 0; k < 4; k++) acc8[c][i][k] = 0.f;

    for (int s = 0; s < 4; s++) {
        CP_WAIT0();
        __syncthreads();
        if (s + 1 < 4) {
            uint32_t slot = (uint32_t)(((s + 1) & 1) * 2);
            cp_chunk(sb + SM_OB + slot * CHUNK_BYTES,
                     g_Wout_sw + (size_t)(2 * s + 2) * CHUNK_U4, t);
            cp_chunk(sb + SM_OB + (slot + 1) * CHUNK_BYTES,
                     g_Wout_sw + (size_t)(2 * s + 3) * CHUNK_U4, t);
        }
        uint32_t B0 = sb + SM_OB + (uint32_t)((s & 1) * 2) * CHUNK_BYTES;
        mma_chunk64(sb, B0, acc8[2 * s], wm, wn, lane);
        mma_chunk64(sb, B0 + CHUNK_BYTES, acc8[2 * s + 1], wm, wn, lane);
    }

    // bias + per-row partial sums
    float s2[2][2] = {{0.f,0.f},{0.f,0.f}}, sq[2][2] = {{0.f,0.f},{0.f,0.f}};
#pragma unroll
    for (int ch = 0; ch < 8; ch++) {
        int cb = ch * 32 + wn * 8 + 2 * q;
        float b0 = __ldg(b_out + cb), b1 = __ldg(b_out + cb + 1);
#pragma unroll
        for (int mi = 0; mi < 2; mi++)
#pragma unroll
        for (int rh = 0; rh < 2; rh++) {
            float y0 = (acc8[ch][mi][rh*2]   += b0);
            float y1 = (acc8[ch][mi][rh*2+1] += b1);
            s2[mi][rh] += y0 + y1;
            sq[mi][rh] += y0 * y0 + y1 * y1;
        }
    }
#pragma unroll
    for (int mi = 0; mi < 2; mi++)
#pragma unroll
    for (int rh = 0; rh < 2; rh++) {
        s2[mi][rh] += __shfl_xor_sync(0xffffffffu, s2[mi][rh], 1);
        s2[mi][rh] += __shfl_xor_sync(0xffffffffu, s2[mi][rh], 2);
        sq[mi][rh] += __shfl_xor_sync(0xffffffffu, sq[mi][rh], 1);
        sq[mi][rh] += __shfl_xor_sync(0xffffffffu, sq[mi][rh], 2);
    }
    float2* part = (float2*)(smem + SM_OPART);   // [64][4]
    __syncthreads();
    if (q == 0) {
#pragma unroll
        for (int mi = 0; mi < 2; mi++)
#pragma unroll
        for (int rh = 0; rh < 2; rh++) {
            int lr = wm * 32 + mi * 16 + g + rh * 8;
            part[lr * 4 + wn] = make_float2(s2[mi][rh], sq[mi][rh]);
        }
    }
    __syncthreads();
    float mu[2][2], rs[2][2];
#pragma unroll
    for (int mi = 0; mi < 2; mi++)
#pragma unroll
    for (int rh = 0; rh < 2; rh++) {
        int lr = wm * 32 + mi * 16 + g + rh * 8;
        float ssum = 0.f, qsum = 0.f;
#pragma unroll
        for (int j = 0; j < 4; j++) {
            float2 p = part[lr * 4 + j];
            ssum += p.x; qsum += p.y;
        }
        float m = ssum * (1.f / 256.f);
        float var = qsum * (1.f / 256.f) - m * m;
        mu[mi][rh] = m;
        rs[mi][rh] = rsqrtf(var + 1e-5f);
    }
#pragma unroll
    for (int ch = 0; ch < 8; ch++) {
        int cb = ch * 32 + wn * 8 + 2 * q;
        float g0 = __ldg(gamma + cb), g1 = __ldg(gamma + cb + 1);
        float e0 = __ldg(beta + cb),  e1 = __ldg(beta + cb + 1);
#pragma unroll
        for (int mi = 0; mi < 2; mi++)
#pragma unroll
        for (int rh = 0; rh < 2; rh++) {
            int lr = wm * 32 + mi * 16 + g + rh * 8;
            if (lr < n_rows) {
                float y0 = (acc8[ch][mi][rh*2]   - mu[mi][rh]) * rs[mi][rh] * g0 + e0;
                float y1 = (acc8[ch][mi][rh*2+1] - mu[mi][rh]) * rs[mi][rh] * g1 + e1;
                *(float2*)(out + (size_t)(base + lr) * DDEC + cb) =
                    make_float2(tanh_fast(y0), tanh_fast(y1));
            }
        }
    }
}

// ---------------------------------------------------------------------------
// x_f precompute (FFMA, small): g_xf[r] = x[r] @ W_f + b_f  for r < NPAR
// ---------------------------------------------------------------------------
#define TS 68
__global__ void xf_kernel(const float* __restrict__ x, const float* __restrict__ W_f,
                          const float* __restrict__ b_f) {
    extern __shared__ float sm[];
    float* As = sm;
    float* Ws = sm + 128 * TS;
    int t = threadIdx.x;
    int base = blockIdx.x << 6;
    int n_rows = NPAR - base; if (n_rows > 64) n_rows = 64;
    int m0 = (t & 15) * 4, c0 = (t >> 4) * 4;

#pragma unroll
    for (int i = 0; i < 32; i++) {
        int idx = t + 256 * i;
        int m = idx >> 7, k = idx & 127;
        float v = 0.f;
        if (m < n_rows) v = x[(size_t)(base + m) * HH + k];
        As[k * TS + m] = v;
    }
    for (int ch = 0; ch < 2; ch++) {
        __syncthreads();
#pragma unroll
        for (int i = 0; i < 32; i++) {
            int idx = t + 256 * i;
            int k = idx >> 6, c = idx & 63;
            Ws[k * TS + c] = W_f[k * HH + ch * 64 + c];
        }
        __syncthreads();
        float acc[4][4] = {};
#pragma unroll 8
        for (int k = 0; k < 128; k++) {
            float4 a = *(const float4*)(As + k * TS + m0);
            float4 b = *(const float4*)(Ws + k * TS + c0);
            acc[0][0] += a.x*b.x; acc[0][1] += a.x*b.y; acc[0][2] += a.x*b.z; acc[0][3] += a.x*b.w;
            acc[1][0] += a.y*b.x; acc[1][1] += a.y*b.y; acc[1][2] += a.y*b.z; acc[1][3] += a.y*b.w;
            acc[2][0] += a.z*b.x; acc[2][1] += a.z*b.y; acc[2][2] += a.z*b.z; acc[2][3] += a.z*b.w;
            acc[3][0] += a.w*b.x; acc[3][1] += a.w*b.y; acc[3][2] += a.w*b.z; acc[3][3] += a.w*b.w;
        }
#pragma unroll
        for (int i = 0; i < 4; i++)
#pragma unroll
            for (int j = 0; j < 4; j++) {
                int m = m0 + i, cc = ch * 64 + c0 + j;
                if (m < n_rows)
                    g_xf[(size_t)(base + m) * HH + cc] = acc[i][j] + b_f[cc];
            }
    }
}

// ---------------------------------------------------------------------------
extern "C" void kernel_launch(void* const* d_in, const int* in_sizes, int n_in,
                              void* d_out, int out_size) {
    const float* x = (const float*)d_in[0];
    int wi = 3;
    if (n_in > 3 && in_sizes[3] <= 1) wi = 4;
    const float* W_iou = (const float*)d_in[wi + 0];
    const float* b_iou = (const float*)d_in[wi + 1];
    const float* U_iou = (const float*)d_in[wi + 2];
    const float* W_f   = (const float*)d_in[wi + 3];
    const float* b_f   = (const float*)d_in[wi + 4];
    const float* U_f   = (const float*)d_in[wi + 5];
    const float* W_out = (const float*)d_in[wi + 6];
    const float* b_out = (const float*)d_in[wi + 7];
    const float* gamma = (const float*)d_in[wi + 8];
    const float* beta  = (const float*)d_in[wi + 9];
    float* out = (float*)d_out;

    cudaFuncSetAttribute(level_mm, cudaFuncAttributeMaxDynamicSharedMemorySize, SM_LVL);
    cudaFuncSetAttribute(out_mm,   cudaFuncAttributeMaxDynamicSharedMemorySize, SM_OUT);
    cudaFuncSetAttribute(xf_kernel, cudaFuncAttributeMaxDynamicSharedMemorySize,
                         (2 * 128 * TS) * (int)sizeof(float));

    prep_all<<<576, 256>>>(W_iou, U_iou, U_f, W_out);
    xf_kernel<<<(NPAR + 63) / 64, 256, (2 * 128 * TS) * sizeof(float)>>>(x, W_f, b_f);

    const int off[8] = {0, 1, 9, 73, 585, 4681, 37449, 299593};
    for (int l = 6; l >= 0; l--) {
        int base = off[l], n = off[l + 1] - off[l];
        int blocks = (n + 127) / 128;
        level_mm<<<blocks, 256, SM_LVL>>>(x, b_iou, base, n,
                                          (l < 6) ? 1 : 0, (l > 0) ? 1 : 0);
    }
    out_mm<<<(NN + 63) / 64, 256, SM_OUT>>>(b_out, gamma, beta, out);
}

// round 15
// speedup vs baseline: 5.5482x; 1.0436x over previous
#include <cuda_runtime.h>
#include <cuda_fp16.h>
#include <math.h>
#include <stdint.h>

// ---------------------------------------------------------------------------
// Problem constants
// ---------------------------------------------------------------------------
#define NN    299593      // total nodes, complete 8-ary tree, 7 levels
#define HH    128         // D_ENC == D_EMB
#define NIOU  384         // 3*H
#define DDEC  256
#define NPAR  37449       // nodes at levels 0..5 (all parents)

#define CHUNK_BYTES 8192  // one pre-swizzled B chunk: 32 N-rows x 128 K x fp16
#define CHUNK_U4    (CHUNK_BYTES / 16)

// Scratch (device globals: allocation-free per harness rules)
__device__ float g_h [(size_t)NN  * HH];
__device__ float g_c [(size_t)NN  * HH];
__device__ float g_xf[(size_t)NPAR * HH];
__device__ float g_uh[(size_t)NPAR * NIOU];
__device__ float g_fc[(size_t)NPAR * HH];

// Pre-swizzled fp16 weight blobs (single-rounded), 32-row x 128-K chunks
__device__ uint4 g_Wiou_sw[12 * CHUNK_U4];
__device__ uint4 g_U_sw   [16 * CHUNK_U4];  // [U_iou(384) | U_f(128)] cols
__device__ uint4 g_Wout_sw[ 8 * CHUNK_U4];

// ---------------------------------------------------------------------------
// Helpers
// ---------------------------------------------------------------------------
__device__ __forceinline__ uint32_t smem_to_u32(const void* p) {
    uint32_t a;
    asm("{ .reg .u64 t; cvta.to.shared.u64 t, %1; cvt.u32.u64 %0, t; }" : "=r"(a) : "l"(p));
    return a;
}
__device__ __forceinline__ uint32_t swz(uint32_t o) { return o ^ ((o >> 3) & 0x70); }
__device__ __forceinline__ uint32_t offA(int row, int k) {   // 128-row tile: 16 atoms/kblk
    return swz((uint32_t)(((row >> 3) + (k >> 6) * 16) * 1024 + (row & 7) * 128 + (k & 63) * 2));
}
__device__ __forceinline__ uint32_t offA64(int row, int k) { // 64-row tile: 8 atoms/kblk
    return swz((uint32_t)(((row >> 3) + (k >> 6) * 8) * 1024 + (row & 7) * 128 + (k & 63) * 2));
}
__device__ __forceinline__ uint32_t offA16(int row, int k) { // 16-row tile: 2 atoms/kblk
    return swz((uint32_t)(((row >> 3) + (k >> 6) * 2) * 1024 + (row & 7) * 128 + (k & 63) * 2));
}
__device__ __forceinline__ uint32_t offB32(int row, int k) { // 32-row tile: 4 atoms/kblk
    return swz((uint32_t)(((row >> 3) + (k >> 6) * 4) * 1024 + (row & 7) * 128 + (k & 63) * 2));
}
__device__ __forceinline__ uint32_t packh2(float a, float b) {
    __half2 h = __floats2half2_rn(a, b);
    return *reinterpret_cast<uint32_t*>(&h);
}
__device__ __forceinline__ float sigf(float v) {
    return __fdividef(1.0f, 1.0f + __expf(-v));
}
__device__ __forceinline__ float tanh_fast(float x) {
    float t = __expf(2.0f * x);
    return 1.0f - __fdividef(2.0f, t + 1.0f);
}

#define LDSM4(R0, R1, R2, R3, ADDR) \
    asm volatile("ldmatrix.sync.aligned.m8n8.x4.shared.b16 {%0,%1,%2,%3}, [%4];" \
                 : "=r"(R0), "=r"(R1), "=r"(R2), "=r"(R3) : "r"(ADDR))
#define LDSM2(R0, R1, ADDR) \
    asm volatile("ldmatrix.sync.aligned.m8n8.x2.shared.b16 {%0,%1}, [%2];" \
                 : "=r"(R0), "=r"(R1) : "r"(ADDR))

__device__ __forceinline__ void mma_f16(float (&d)[4], const uint32_t (&a)[4],
                                        uint32_t b0, uint32_t b1) {
    asm volatile("mma.sync.aligned.m16n8k16.row.col.f32.f16.f16.f32 "
                 "{%0,%1,%2,%3}, {%4,%5,%6,%7}, {%8,%9}, {%0,%1,%2,%3};"
                 : "+f"(d[0]), "+f"(d[1]), "+f"(d[2]), "+f"(d[3])
                 : "r"(a[0]), "r"(a[1]), "r"(a[2]), "r"(a[3]), "r"(b0), "r"(b1));
}

__device__ __forceinline__ void zacc(float (&a)[2][2][4]) {
#pragma unroll
    for (int i = 0; i < 2; i++)
#pragma unroll
        for (int j = 0; j < 2; j++)
#pragma unroll
            for (int k = 0; k < 4; k++) a[i][j][k] = 0.f;
}

// Triple-fused pass: A fragments loaded ONCE per kstep feed 3 B chunks (I,O,U)
__device__ __forceinline__ void mma_trip32(uint32_t Abase, uint32_t B0, uint32_t B1,
                                           uint32_t B2,
                                           float (&aI)[2][2][4], float (&aO)[2][2][4],
                                           float (&aU)[2][2][4],
                                           int wm, int wn, int lane) {
    int rA = wm * 32 + (lane & 15);
    uint32_t PA = Abase + ((rA >> 3) << 10) + ((rA & 7) << 7);
    uint32_t CA = (rA & 7) << 4;
    int aK = (lane >> 4) << 3;
    int nB = wn * 16 + (((lane >> 4) & 1) << 3) + (lane & 7);
    uint32_t SB = ((uint32_t)(nB >> 3) << 10) + ((uint32_t)(nB & 7) << 7);
    uint32_t CB = (nB & 7) << 4;
    int bK = ((lane >> 3) & 1) << 3;
#pragma unroll
    for (int s = 0; s < 8; s++) {
        int kA = (s << 4) + aK;
        int kB = (s << 4) + bK;
        uint32_t aAh = PA + ((uint32_t)(kA >> 6) << 14) + ((uint32_t)((kA & 63) << 1) ^ CA);
        uint32_t ob  = SB + ((uint32_t)(kB >> 6) << 12) + ((uint32_t)((kB & 63) << 1) ^ CB);
        uint32_t ah0[4], ah1[4], bI[4], bO[4], bU[4];
        LDSM4(ah0[0], ah0[1], ah0[2], ah0[3], aAh);
        LDSM4(ah1[0], ah1[1], ah1[2], ah1[3], aAh + 2048);
        LDSM4(bI[0], bI[1], bI[2], bI[3], B0 + ob);
        LDSM4(bO[0], bO[1], bO[2], bO[3], B1 + ob);
        LDSM4(bU[0], bU[1], bU[2], bU[3], B2 + ob);
        mma_f16(aI[0][0], ah0, bI[0], bI[1]);
        mma_f16(aI[1][0], ah1, bI[0], bI[1]);
        mma_f16(aI[0][1], ah0, bI[2], bI[3]);
        mma_f16(aI[1][1], ah1, bI[2], bI[3]);
        mma_f16(aO[0][0], ah0, bO[0], bO[1]);
        mma_f16(aO[1][0], ah1, bO[0], bO[1]);
        mma_f16(aO[0][1], ah0, bO[2], bO[3]);
        mma_f16(aO[1][1], ah1, bO[2], bO[3]);
        mma_f16(aU[0][0], ah0, bU[0], bU[1]);
        mma_f16(aU[1][0], ah1, bU[0], bU[1]);
        mma_f16(aU[0][1], ah0, bU[2], bU[3]);
        mma_f16(aU[1][1], ah1, bU[2], bU[3]);
    }
}

// Pair-fused: A fragments feed 2 B chunks
__device__ __forceinline__ void mma_pair32(uint32_t Abase, uint32_t B0, uint32_t B1,
                                           float (&aX)[2][2][4], float (&aY)[2][2][4],
                                           int wm, int wn, int lane) {
    int rA = wm * 32 + (lane & 15);
    uint32_t PA = Abase + ((rA >> 3) << 10) + ((rA & 7) << 7);
    uint32_t CA = (rA & 7) << 4;
    int aK = (lane >> 4) << 3;
    int nB = wn * 16 + (((lane >> 4) & 1) << 3) + (lane & 7);
    uint32_t SB = ((uint32_t)(nB >> 3) << 10) + ((uint32_t)(nB & 7) << 7);
    uint32_t CB = (nB & 7) << 4;
    int bK = ((lane >> 3) & 1) << 3;
#pragma unroll
    for (int s = 0; s < 8; s++) {
        int kA = (s << 4) + aK;
        int kB = (s << 4) + bK;
        uint32_t aAh = PA + ((uint32_t)(kA >> 6) << 14) + ((uint32_t)((kA & 63) << 1) ^ CA);
        uint32_t ob  = SB + ((uint32_t)(kB >> 6) << 12) + ((uint32_t)((kB & 63) << 1) ^ CB);
        uint32_t ah0[4], ah1[4], bX[4], bY[4];
        LDSM4(ah0[0], ah0[1], ah0[2], ah0[3], aAh);
        LDSM4(ah1[0], ah1[1], ah1[2], ah1[3], aAh + 2048);
        LDSM4(bX[0], bX[1], bX[2], bX[3], B0 + ob);
        LDSM4(bY[0], bY[1], bY[2], bY[3], B1 + ob);
        mma_f16(aX[0][0], ah0, bX[0], bX[1]);
        mma_f16(aX[1][0], ah1, bX[0], bX[1]);
        mma_f16(aX[0][1], ah0, bX[2], bX[3]);
        mma_f16(aX[1][1], ah1, bX[2], bX[3]);
        mma_f16(aY[0][0], ah0, bY[0], bY[1]);
        mma_f16(aY[1][0], ah1, bY[0], bY[1]);
        mma_f16(aY[0][1], ah0, bY[2], bY[3]);
        mma_f16(aY[1][1], ah1, bY[2], bY[3]);
    }
}

// Out kernel: 64-row tile, 4 B chunks share A fragments; per-warp n8 per chunk
__device__ __forceinline__ void mma_quad64(uint32_t Abase, uint32_t Bbase,
                                           float (*acc)[2][4],   // [4][2][4]
                                           int wm, int wn, int lane) {
    int rA = wm * 32 + (lane & 15);
    uint32_t PA = Abase + ((rA >> 3) << 10) + ((rA & 7) << 7);
    uint32_t CA = (rA & 7) << 4;
    int aK = (lane >> 4) << 3;
    int nB = wn * 8 + (lane & 7);
    uint32_t SB = ((uint32_t)(nB >> 3) << 10) + ((uint32_t)(nB & 7) << 7);
    uint32_t CB = (nB & 7) << 4;
    int bK = ((lane >> 3) & 1) << 3;
#pragma unroll
    for (int s = 0; s < 8; s++) {
        int kA = (s << 4) + aK;
        int kB = (s << 4) + bK;
        uint32_t aAh = PA + ((uint32_t)(kA >> 6) << 13) + ((uint32_t)((kA & 63) << 1) ^ CA);
        uint32_t ob  = SB + ((uint32_t)(kB >> 6) << 12) + ((uint32_t)((kB & 63) << 1) ^ CB);
        uint32_t ah0[4], ah1[4];
        LDSM4(ah0[0], ah0[1], ah0[2], ah0[3], aAh);
        LDSM4(ah1[0], ah1[1], ah1[2], ah1[3], aAh + 2048);
#pragma unroll
        for (int j = 0; j < 4; j++) {
            uint32_t b0, b1;
            LDSM2(b0, b1, Bbase + (uint32_t)j * CHUNK_BYTES + ob);
            mma_f16(acc[j][0], ah0, b0, b1);
            mma_f16(acc[j][1], ah1, b0, b1);
        }
    }
}

// ---------------------------------------------------------------------------
// cp.async: one 8KB chunk, 256 threads x 2 x 16B, one commit group
// ---------------------------------------------------------------------------
__device__ __forceinline__ void cp_chunk(uint32_t dst, const uint4* src, int t) {
    const char* s = (const char*)src;
#pragma unroll
    for (int i = 0; i < 2; i++)
        asm volatile("cp.async.cg.shared.global [%0], [%1], 16;"
                     :: "r"(dst + (uint32_t)(t * 16 + i * 4096)),
                        "l"(s + t * 16 + i * 4096) : "memory");
    asm volatile("cp.async.commit_group;" ::: "memory");
}
#define CP_WAIT0() asm volatile("cp.async.wait_group 0;" ::: "memory")

// ---------------------------------------------------------------------------
// Weight prep (single launch): fp16 round + swizzle all four blobs
// ---------------------------------------------------------------------------
__global__ void prep_all(const float* __restrict__ W_iou, const float* __restrict__ U_iou,
                         const float* __restrict__ U_f, const float* __restrict__ W_out) {
    int b = blockIdx.x;
    const float* src; int ncols, dst_id, chunkoff, rel;
    if (b < 192)      { src = W_iou; ncols = 384; dst_id = 0; chunkoff = 0;  rel = b; }
    else if (b < 384) { src = U_iou; ncols = 384; dst_id = 1; chunkoff = 0;  rel = b - 192; }
    else if (b < 448) { src = U_f;   ncols = 128; dst_id = 1; chunkoff = 12; rel = b - 384; }
    else              { src = W_out; ncols = 256; dst_id = 2; chunkoff = 0;  rel = b - 448; }
    int idx = rel * 256 + threadIdx.x;
    if (idx >= 128 * ncols) return;
    int k = idx / ncols, n = idx - k * ncols;
    float v = src[k * ncols + n];
    unsigned short hu = __half_as_ushort(__float2half_rn(v));
    unsigned char* bb = (dst_id == 0) ? (unsigned char*)g_Wiou_sw
                      : (dst_id == 1) ? (unsigned char*)g_U_sw
                                      : (unsigned char*)g_Wout_sw;
    unsigned char* blob = bb + (size_t)(chunkoff + (n >> 5)) * CHUNK_BYTES;
    int row = n & 31;
    *(unsigned short*)(blob + offB32(row, k)) = hu;
}

// ---------------------------------------------------------------------------
// Level SMEM (occ 2): A [0,32768) | A2 [32768,36864) | ring 8x8KB [36864,102400)
// Out SMEM: A64 [0,16384) | ring 8x8KB [16384,81920) | part [81920,83968)
// ---------------------------------------------------------------------------
#define SM_A2    32768
#define SM_B     36864
#define SM_LVL   102400
#define SM_OB    16384
#define SM_OPART 81920
#define SM_OUT   83968

// build a 128x128 fp16 tile from fp32 rows (src row-major, HH cols)
__device__ __forceinline__ void build_tile(char* Ac, const float* src, size_t base,
                                           int n_rows, int t) {
    int row = t >> 1, kh = (t & 1) << 6;
    bool val = row < n_rows;
    const float4* xr = (const float4*)(src + (base + row) * HH + kh);
#pragma unroll
    for (int gg = 0; gg < 8; gg++) {
        float v[8];
        if (val) {
            float4 a = xr[gg * 2], b = xr[gg * 2 + 1];
            v[0]=a.x; v[1]=a.y; v[2]=a.z; v[3]=a.w; v[4]=b.x; v[5]=b.y; v[6]=b.z; v[7]=b.w;
        } else {
#pragma unroll
            for (int q = 0; q < 8; q++) v[q] = 0.f;
        }
        *(uint4*)(Ac + offA(row, kh + gg * 8)) =
            make_uint4(packh2(v[0], v[1]), packh2(v[2], v[3]),
                       packh2(v[4], v[5]), packh2(v[6], v[7]));
    }
}

// 64-row variant (4 threads per row, 32 K each)
__device__ __forceinline__ void build_tile64(char* Ac, const float* src, size_t base,
                                             int n_rows, int t) {
    int row = t >> 2, kh = (t & 3) << 5;
    bool val = row < n_rows;
    const float4* xr = (const float4*)(src + (base + row) * HH + kh);
#pragma unroll
    for (int gg = 0; gg < 4; gg++) {
        float v[8];
        if (val) {
            float4 a = xr[gg * 2], b = xr[gg * 2 + 1];
            v[0]=a.x; v[1]=a.y; v[2]=a.z; v[3]=a.w; v[4]=b.x; v[5]=b.y; v[6]=b.z; v[7]=b.w;
        } else {
#pragma unroll
            for (int q = 0; q < 8; q++) v[q] = 0.f;
        }
        *(uint4*)(Ac + offA64(row, kh + gg * 8)) =
            make_uint4(packh2(v[0], v[1]), packh2(v[2], v[3]),
                       packh2(v[4], v[5]), packh2(v[6], v[7]));
    }
}

// chunk c -> blob source (0..11 GEMM1 as (I_p,O_p,U_p) triples, 12..27 GEMM2)
__device__ __forceinline__ const uint4* lvl_src(int c) {
    if (c < 12) {
        int p = c / 3, sub = c - p * 3;              // blob chunk = sub*4 + p
        return g_Wiou_sw + (size_t)(sub * 4 + p) * CHUNK_U4;
    }
    return g_U_sw + (size_t)(c - 12) * CHUNK_U4;
}
// step s: s<4 -> GEMM1 pass s (3 chunks); s=4..6 -> GEMM2a (4 tiny); s=7 -> GEMM2b (4)
__device__ __forceinline__ int st_start(int s) { return (s < 4) ? 3 * s : 12 + 4 * (s - 4); }
__device__ __forceinline__ int st_cnt(int s)   { return (s < 4) ? 3 : 4; }
__device__ __forceinline__ void issue_group(uint32_t sb, int s, int t) {
    int st = st_start(s), cn = st_cnt(s);
    uint32_t slot = (uint32_t)((s & 1) * 4);
    for (int j = 0; j < cn; j++)
        cp_chunk(sb + SM_B + (slot + j) * CHUNK_BYTES, lvl_src(st + j), t);
}

// ---------------------------------------------------------------------------
// Fused per-level kernel: one CTA per 128-row tile, 256 threads, 2 CTAs/SM
// 8 steps: 4 GEMM1 passes (triple-fused + epilogue), 3 GEMM2a, 1 GEMM2b
// ---------------------------------------------------------------------------
__global__ __launch_bounds__(256, 2)
void level_mm(const float* __restrict__ x, const float* __restrict__ b_iou,
              int base0, int n_total, int read_sums, int has_parent) {
    extern __shared__ __align__(1024) char smem[];
    uint32_t sb = smem_to_u32(smem);
    int t = threadIdx.x, lane = t & 31, w = t >> 5;
    int wm = w & 3, wn = w >> 2;
    int q = lane & 3, g = lane >> 2;
    int base = base0 + ((int)blockIdx.x << 7);
    int n_rows = n_total - ((int)blockIdx.x << 7); if (n_rows > 128) n_rows = 128;
    int pbase = (base - 1) >> 3;
    const int n_steps = has_parent ? 8 : 4;

    issue_group(sb, 0, t);
    build_tile(smem, x, (size_t)base, n_rows, t);

    float accI[2][2][4], accO[2][2][4], accU[2][2][4];
    zacc(accI); zacc(accO); zacc(accU);

    for (int s = 0; s < n_steps; s++) {
        CP_WAIT0();
        __syncthreads();               // group s landed; prior step's reads done
        if (s + 1 < n_steps) issue_group(sb, s + 1, t);
        uint32_t B0 = sb + SM_B + (uint32_t)((s & 1) * 4) * CHUNK_BYTES;

        if (s < 4) {
            int p = s;
            mma_trip32(sb, B0, B0 + CHUNK_BYTES, B0 + 2 * CHUNK_BYTES,
                       accI, accO, accU, wm, wn, lane);
            // epilogue for pass p: gates -> c,h (global) + A2 sibling sums
#pragma unroll
            for (int mi = 0; mi < 2; mi++)
#pragma unroll
            for (int nn = 0; nn < 2; nn++) {
                int cp = p * 32 + wn * 16 + nn * 8 + 2 * q;
                float bi0 = __ldg(b_iou + cp),       bi1 = __ldg(b_iou + cp + 1);
                float bo0 = __ldg(b_iou + 128 + cp), bo1 = __ldg(b_iou + 129 + cp);
                float bu0 = __ldg(b_iou + 256 + cp), bu1 = __ldg(b_iou + 257 + cp);
#pragma unroll
                for (int rh = 0; rh < 2; rh++) {
                    int lr = wm * 32 + mi * 16 + g + rh * 8;
                    int rg = base + lr;
                    bool val = lr < n_rows;
                    float2 ui = make_float2(0.f, 0.f), uo = ui, uu = ui, fc = ui;
                    if (val && read_sums) {
                        const float* uh = g_uh + (size_t)rg * NIOU + cp;
                        ui = *(const float2*)(uh);
                        uo = *(const float2*)(uh + 128);
                        uu = *(const float2*)(uh + 256);
                        fc = *(const float2*)(g_fc + (size_t)rg * HH + cp);
                    }
                    float c0 = sigf(accI[mi][nn][rh*2]   + bi0 + ui.x) *
                               tanh_fast(accU[mi][nn][rh*2]   + bu0 + uu.x) + fc.x;
                    float c1 = sigf(accI[mi][nn][rh*2+1] + bi1 + ui.y) *
                               tanh_fast(accU[mi][nn][rh*2+1] + bu1 + uu.y) + fc.y;
                    float h0 = sigf(accO[mi][nn][rh*2]   + bo0 + uo.x) * tanh_fast(c0);
                    float h1 = sigf(accO[mi][nn][rh*2+1] + bo1 + uo.y) * tanh_fast(c1);
                    if (val) {
                        *(float2*)(g_c + (size_t)rg * HH + cp) = make_float2(c0, c1);
                        *(float2*)(g_h + (size_t)rg * HH + cp) = make_float2(h0, h1);
                    }
                    if (has_parent) {
                        float hs0 = val ? h0 : 0.f, hs1 = val ? h1 : 0.f;
                        hs0 += __shfl_xor_sync(0xffffffffu, hs0, 4);
                        hs0 += __shfl_xor_sync(0xffffffffu, hs0, 8);
                        hs0 += __shfl_xor_sync(0xffffffffu, hs0, 16);
                        hs1 += __shfl_xor_sync(0xffffffffu, hs1, 4);
                        hs1 += __shfl_xor_sync(0xffffffffu, hs1, 8);
                        hs1 += __shfl_xor_sync(0xffffffffu, hs1, 16);
                        if (lane < 4) {
                            int row2 = 4 * wm + 2 * mi + rh;
                            *(uint32_t*)(smem + SM_A2 + offA16(row2, cp)) =
                                packh2(hs0, hs1);
                        }
                    }
                }
            }
            zacc(accI); zacc(accO); zacc(accU);
            if (s == 3 && has_parent) {
                __syncthreads();               // all warps done reading A (GEMM1)
                build_tile(smem, g_h, (size_t)base, n_rows, t);
            }
        } else if (s < 7) {
            // four tiny GEMM2a chunks: Uh_sum[16 rows] = hsum @ U_iou
            int ch0 = st_start(s) - 12;
            if (w < 4) {
#pragma unroll
                for (int jj = 0; jj < 4; jj++) {
                    int ch = ch0 + jj;
                    uint32_t Bb = B0 + (uint32_t)jj * CHUNK_BYTES;
                    float acc2[4] = {0.f, 0.f, 0.f, 0.f};
                    int rA2 = lane & 15;
                    uint32_t PA2 = (sb + SM_A2) + ((uint32_t)(rA2 >> 3) << 10)
                                                + ((uint32_t)(rA2 & 7) << 7);
                    uint32_t CA2 = (rA2 & 7) << 4;
                    int aK = (lane >> 4) << 3;
                    int nB2 = w * 8 + (lane & 7);
                    uint32_t PB2 = Bb + ((uint32_t)(nB2 >> 3) << 10)
                                      + ((uint32_t)(nB2 & 7) << 7);
                    uint32_t CB2 = (nB2 & 7) << 4;
                    int kB2 = ((lane >> 3) & 1) << 3;
#pragma unroll
                    for (int ks = 0; ks < 8; ks++) {
                        int kA = (ks << 4) + aK;
                        int kB = (ks << 4) + kB2;
                        uint32_t aAh = PA2 + ((uint32_t)(kA >> 6) << 11)
                                           + (((uint32_t)(kA & 63) << 1) ^ CA2);
                        uint32_t aB  = PB2 + ((uint32_t)(kB >> 6) << 12)
                                           + (((uint32_t)(kB & 63) << 1) ^ CB2);
                        uint32_t a2h[4], b0, b1;
                        LDSM4(a2h[0], a2h[1], a2h[2], a2h[3], aAh);
                        LDSM2(b0, b1, aB);
                        mma_f16(acc2, a2h, b0, b1);
                    }
                    int cb2 = ch * 32 + w * 8 + 2 * (lane & 3);
                    int gr0 = lane >> 2;
                    if (gr0 * 8 < n_rows)
                        *(float2*)(g_uh + (size_t)(pbase + gr0) * NIOU + cb2) =
                            make_float2(acc2[0], acc2[1]);
                    if ((gr0 + 8) * 8 < n_rows)
                        *(float2*)(g_uh + (size_t)(pbase + gr0 + 8) * NIOU + cb2) =
                            make_float2(acc2[2], acc2[3]);
                }
            }
        } else {
            // GEMM2b: all 4 U_f chunks in this step, two pair-fused rounds
#pragma unroll
            for (int r = 0; r < 2; r++) {
                int cf0 = 2 * r;
                mma_pair32(sb, B0 + (uint32_t)(2 * r) * CHUNK_BYTES,
                           B0 + (uint32_t)(2 * r + 1) * CHUNK_BYTES,
                           accI, accO, wm, wn, lane);
#pragma unroll
                for (int jj = 0; jj < 2; jj++) {
#pragma unroll
                    for (int mi = 0; mi < 2; mi++)
#pragma unroll
                    for (int nn = 0; nn < 2; nn++) {
                        int cfl = (cf0 + jj) * 32 + wn * 16 + nn * 8 + 2 * q;
                        float v[4];
#pragma unroll
                        for (int rh = 0; rh < 2; rh++) {
                            int lr = wm * 32 + mi * 16 + g + rh * 8;
                            int rg = base + lr;
                            float a0 = jj ? accO[mi][nn][rh*2]   : accI[mi][nn][rh*2];
                            float a1 = jj ? accO[mi][nn][rh*2+1] : accI[mi][nn][rh*2+1];
                            if (lr < n_rows) {
                                int pr = (rg - 1) >> 3;
                                float2 xf2 = *(const float2*)(g_xf + (size_t)pr * HH + cfl);
                                float2 c2  = *(const float2*)(g_c  + (size_t)rg * HH + cfl);
                                v[rh*2]   = sigf(a0 + xf2.x) * c2.x;
                                v[rh*2+1] = sigf(a1 + xf2.y) * c2.y;
                            } else { v[rh*2] = 0.f; v[rh*2+1] = 0.f; }
                        }
#pragma unroll
                        for (int rr = 0; rr < 4; rr++) {
                            float sv = v[rr];
                            sv += __shfl_xor_sync(0xffffffffu, sv, 4);
                            sv += __shfl_xor_sync(0xffffffffu, sv, 8);
                            sv += __shfl_xor_sync(0xffffffffu, sv, 16);
                            v[rr] = sv;
                        }
                        if (lane < 4) {
#pragma unroll
                            for (int rh = 0; rh < 2; rh++) {
                                int lr0 = wm * 32 + mi * 16 + rh * 8;
                                if (lr0 < n_rows) {
                                    int pr = (base + lr0 - 1) >> 3;
                                    *(float2*)(g_fc + (size_t)pr * HH + cfl) =
                                        make_float2(v[rh*2], v[rh*2+1]);
                                }
                            }
                        }
                    }
                }
                zacc(accI); zacc(accO);
            }
        }
    }
}

// ---------------------------------------------------------------------------
// Output kernel: 64-row tiles, occupancy 2, 2 quad-fused steps
// ---------------------------------------------------------------------------
__global__ __launch_bounds__(256, 2)
void out_mm(const float* __restrict__ b_out, const float* __restrict__ gamma,
            const float* __restrict__ beta, float* __restrict__ out) {
    extern __shared__ __align__(1024) char smem[];
    uint32_t sb = smem_to_u32(smem);
    int t = threadIdx.x, lane = t & 31, w = t >> 5;
    int wm = w & 1, wn = w >> 1;           // 2 x 4 warp grid
    int q = lane & 3, g = lane >> 2;
    int base = (int)blockIdx.x << 6;
    int n_rows = NN - base; if (n_rows > 64) n_rows = 64;

    // step 0 group: chunks 0..3 -> slots 0..3
#pragma unroll
    for (int j = 0; j < 4; j++)
        cp_chunk(sb + SM_OB + (uint32_t)j * CHUNK_BYTES, g_Wout_sw + (size_t)j * CHUNK_U4, t);

    build_tile64(smem, g_h, (size_t)base, n_rows, t);

    float acc8[8][2][4];
#pragma unroll
    for (int c = 0; c < 8; c++)
#pragma unroll
        for (int i = 0; i < 2; i++)
#pragma unroll
            for (int k = 0; k < 4; k++) acc8[c][i][k] = 0.f;

    for (int s = 0; s < 2; s++) {
        CP_WAIT0();
        __syncthreads();
        if (s == 0) {
#pragma unroll
            for (int j = 0; j < 4; j++)
                cp_chunk(sb + SM_OB + (uint32_t)(4 + j) * CHUNK_BYTES,
                         g_Wout_sw + (size_t)(4 + j) * CHUNK_U4, t);
        }
        mma_quad64(sb, sb + SM_OB + (uint32_t)(s * 4) * CHUNK_BYTES,
                   &acc8[4 * s], wm, wn, lane);
    }

    // bias + per-row partial sums
    float s2[2][2] = {{0.f,0.f},{0.f,0.f}}, sq[2][2] = {{0.f,0.f},{0.f,0.f}};
#pragma unroll
    for (int ch = 0; ch < 8; ch++) {
        int cb = ch * 32 + wn * 8 + 2 * q;
        float b0 = __ldg(b_out + cb), b1 = __ldg(b_out + cb + 1);
#pragma unroll
        for (int mi = 0; mi < 2; mi++)
#pragma unroll
        for (int rh = 0; rh < 2; rh++) {
            float y0 = (acc8[ch][mi][rh*2]   += b0);
            float y1 = (acc8[ch][mi][rh*2+1] += b1);
            s2[mi][rh] += y0 + y1;
            sq[mi][rh] += y0 * y0 + y1 * y1;
        }
    }
#pragma unroll
    for (int mi = 0; mi < 2; mi++)
#pragma unroll
    for (int rh = 0; rh < 2; rh++) {
        s2[mi][rh] += __shfl_xor_sync(0xffffffffu, s2[mi][rh], 1);
        s2[mi][rh] += __shfl_xor_sync(0xffffffffu, s2[mi][rh], 2);
        sq[mi][rh] += __shfl_xor_sync(0xffffffffu, sq[mi][rh], 1);
        sq[mi][rh] += __shfl_xor_sync(0xffffffffu, sq[mi][rh], 2);
    }
    float2* part = (float2*)(smem + SM_OPART);   // [64][4]
    __syncthreads();
    if (q == 0) {
#pragma unroll
        for (int mi = 0; mi < 2; mi++)
#pragma unroll
        for (int rh = 0; rh < 2; rh++) {
            int lr = wm * 32 + mi * 16 + g + rh * 8;
            part[lr * 4 + wn] = make_float2(s2[mi][rh], sq[mi][rh]);
        }
    }
    __syncthreads();
    float mu[2][2], rs[2][2];
#pragma unroll
    for (int mi = 0; mi < 2; mi++)
#pragma unroll
    for (int rh = 0; rh < 2; rh++) {
        int lr = wm * 32 + mi * 16 + g + rh * 8;
        float ssum = 0.f, qsum = 0.f;
#pragma unroll
        for (int j = 0; j < 4; j++) {
            float2 p = part[lr * 4 + j];
            ssum += p.x; qsum += p.y;
        }
        float m = ssum * (1.f / 256.f);
        float var = qsum * (1.f / 256.f) - m * m;
        mu[mi][rh] = m;
        rs[mi][rh] = rsqrtf(var + 1e-5f);
    }
#pragma unroll
    for (int ch = 0; ch < 8; ch++) {
        int cb = ch * 32 + wn * 8 + 2 * q;
        float g0 = __ldg(gamma + cb), g1 = __ldg(gamma + cb + 1);
        float e0 = __ldg(beta + cb),  e1 = __ldg(beta + cb + 1);
#pragma unroll
        for (int mi = 0; mi < 2; mi++)
#pragma unroll
        for (int rh = 0; rh < 2; rh++) {
            int lr = wm * 32 + mi * 16 + g + rh * 8;
            if (lr < n_rows) {
                float y0 = (acc8[ch][mi][rh*2]   - mu[mi][rh]) * rs[mi][rh] * g0 + e0;
                float y1 = (acc8[ch][mi][rh*2+1] - mu[mi][rh]) * rs[mi][rh] * g1 + e1;
                *(float2*)(out + (size_t)(base + lr) * DDEC + cb) =
                    make_float2(tanh_fast(y0), tanh_fast(y1));
            }
        }
    }
}

// ---------------------------------------------------------------------------
// x_f precompute (FFMA, small): g_xf[r] = x[r] @ W_f + b_f  for r < NPAR
// ---------------------------------------------------------------------------
#define TS 68
__global__ void xf_kernel(const float* __restrict__ x, const float* __restrict__ W_f,
                          const float* __restrict__ b_f) {
    extern __shared__ float sm[];
    float* As = sm;
    float* Ws = sm + 128 * TS;
    int t = threadIdx.x;
    int base = blockIdx.x << 6;
    int n_rows = NPAR - base; if (n_rows > 64) n_rows = 64;
    int m0 = (t & 15) * 4, c0 = (t >> 4) * 4;

#pragma unroll
    for (int i = 0; i < 32; i++) {
        int idx = t + 256 * i;
        int m = idx >> 7, k = idx & 127;
        float v = 0.f;
        if (m < n_rows) v = x[(size_t)(base + m) * HH + k];
        As[k * TS + m] = v;
    }
    for (int ch = 0; ch < 2; ch++) {
        __syncthreads();
#pragma unroll
        for (int i = 0; i < 32; i++) {
            int idx = t + 256 * i;
            int k = idx >> 6, c = idx & 63;
            Ws[k * TS + c] = W_f[k * HH + ch * 64 + c];
        }
        __syncthreads();
        float acc[4][4] = {};
#pragma unroll 8
        for (int k = 0; k < 128; k++) {
            float4 a = *(const float4*)(As + k * TS + m0);
            float4 b = *(const float4*)(Ws + k * TS + c0);
            acc[0][0] += a.x*b.x; acc[0][1] += a.x*b.y; acc[0][2] += a.x*b.z; acc[0][3] += a.x*b.w;
            acc[1][0] += a.y*b.x; acc[1][1] += a.y*b.y; acc[1][2] += a.y*b.z; acc[1][3] += a.y*b.w;
            acc[2][0] += a.z*b.x; acc[2][1] += a.z*b.y; acc[2][2] += a.z*b.z; acc[2][3] += a.z*b.w;
            acc[3][0] += a.w*b.x; acc[3][1] += a.w*b.y; acc[3][2] += a.w*b.z; acc[3][3] += a.w*b.w;
        }
#pragma unroll
        for (int i = 0; i < 4; i++)
#pragma unroll
            for (int j = 0; j < 4; j++) {
                int m = m0 + i, cc = ch * 64 + c0 + j;
                if (m < n_rows)
                    g_xf[(size_t)(base + m) * HH + cc] = acc[i][j] + b_f[cc];
            }
    }
}

// ---------------------------------------------------------------------------
extern "C" void kernel_launch(void* const* d_in, const int* in_sizes, int n_in,
                              void* d_out, int out_size) {
    const float* x = (const float*)d_in[0];
    int wi = 3;
    if (n_in > 3 && in_sizes[3] <= 1) wi = 4;
    const float* W_iou = (const float*)d_in[wi + 0];
    const float* b_iou = (const float*)d_in[wi + 1];
    const float* U_iou = (const float*)d_in[wi + 2];
    const float* W_f   = (const float*)d_in[wi + 3];
    const float* b_f   = (const float*)d_in[wi + 4];
    const float* U_f   = (const float*)d_in[wi + 5];
    const float* W_out = (const float*)d_in[wi + 6];
    const float* b_out = (const float*)d_in[wi + 7];
    const float* gamma = (const float*)d_in[wi + 8];
    const float* beta  = (const float*)d_in[wi + 9];
    float* out = (float*)d_out;

    cudaFuncSetAttribute(level_mm, cudaFuncAttributeMaxDynamicSharedMemorySize, SM_LVL);
    cudaFuncSetAttribute(out_mm,   cudaFuncAttributeMaxDynamicSharedMemorySize, SM_OUT);
    cudaFuncSetAttribute(xf_kernel, cudaFuncAttributeMaxDynamicSharedMemorySize,
                         (2 * 128 * TS) * (int)sizeof(float));

    prep_all<<<576, 256>>>(W_iou, U_iou, U_f, W_out);
    xf_kernel<<<(NPAR + 63) / 64, 256, (2 * 128 * TS) * sizeof(float)>>>(x, W_f, b_f);

    const int off[8] = {0, 1, 9, 73, 585, 4681, 37449, 299593};
    for (int l = 6; l >= 0; l--) {
        int base = off[l], n = off[l + 1] - off[l];
        int blocks = (n + 127) / 128;
        level_mm<<<blocks, 256, SM_LVL>>>(x, b_iou, base, n,
                                          (l < 6) ? 1 : 0, (l > 0) ? 1 : 0);
    }
    out_mm<<<(NN + 63) / 64, 256, SM_OUT>>>(b_out, gamma, beta, out);
}